// round 4
// baseline (speedup 1.0000x reference)
#include <cuda_runtime.h>
#include <math.h>

// ---------------- problem constants ----------------
#define D_MODEL 512
#define D_FF    2048
#define NHEAD   8
#define DK      64
#define NLAYER  4
#define VOCAB   512
#define BATCH   16
#define LFULL   513
#define LT      512          // target length (L-1)
#define SRC_S   256
#define MT      (BATCH*LT)   // 8192 token rows
#define MS      (BATCH*SRC_S)// 4096 src rows

// ---------------- device scratch (static, no allocation) ----------------
__device__ float g_x  [MT*D_MODEL];
__device__ float g_h  [MT*D_MODEL];
__device__ float g_q  [MT*D_MODEL];
__device__ float g_k  [MT*D_MODEL];   // also holds cross-K (first MS rows)
__device__ float g_v  [MT*D_MODEL];   // also holds cross-V (first MS rows)
__device__ float g_att[MT*D_MODEL];
__device__ float g_sc [BATCH*NHEAD*LT*LT];  // 134 MB score scratch
__device__ float g_ffn[MT*D_FF];
__device__ float g_pe [LT*D_MODEL];
__device__ float g_lg [MT*VOCAB];

// ---------------- positional encoding (fp64 to match numpy) ----------------
__global__ void pe_kernel() {
    int i = blockIdx.x * blockDim.x + threadIdx.x;
    if (i >= LT * D_MODEL) return;
    int t = i / D_MODEL, d = i % D_MODEL;
    int e = d & ~1;
    double div = exp(-(double)e * (log(10000.0) / (double)D_MODEL));
    double ang = (double)t * div;
    g_pe[i] = (float)((d & 1) ? cos(ang) : sin(ang));
}

// ---------------- embedding + PE ----------------
__global__ void embed_kernel(const int* __restrict__ ids, const float* __restrict__ emb) {
    int i = blockIdx.x * blockDim.x + threadIdx.x;
    if (i >= MT * D_MODEL) return;
    int row = i / D_MODEL, d = i % D_MODEL;
    int b = row / LT, t = row % LT;
    int tok = ids[b * LFULL + t];
    g_x[i] = emb[tok * D_MODEL + d] * 22.62741699796952f + g_pe[t * D_MODEL + d];
}

// ---------------- layernorm (ddof=1, denom = std + eps) ----------------
__global__ void ln_kernel(const float* __restrict__ x, float* __restrict__ y,
                          const float* __restrict__ ga, const float* __restrict__ gb) {
    int row = blockIdx.x;
    const float* xr = x + (size_t)row * D_MODEL;
    float*       yr = y + (size_t)row * D_MODEL;
    int t = threadIdx.x;  // 128 threads
    float v[4], s = 0.f, s2 = 0.f;
#pragma unroll
    for (int j = 0; j < 4; j++) {
        v[j] = xr[t + j * 128];
        s += v[j]; s2 += v[j] * v[j];
    }
    __shared__ float red[2][4];
#pragma unroll
    for (int o = 16; o > 0; o >>= 1) {
        s  += __shfl_down_sync(0xffffffffu, s,  o);
        s2 += __shfl_down_sync(0xffffffffu, s2, o);
    }
    if ((t & 31) == 0) { red[0][t >> 5] = s; red[1][t >> 5] = s2; }
    __syncthreads();
    if (t == 0) {
        float S1 = red[0][0] + red[0][1] + red[0][2] + red[0][3];
        float S2 = red[1][0] + red[1][1] + red[1][2] + red[1][3];
        float mean = S1 / 512.0f;
        float var  = fmaxf(0.f, S2 - 512.0f * mean * mean) / 511.0f;
        red[0][0] = mean;
        red[1][0] = 1.0f / (sqrtf(var) + 1e-6f);
    }
    __syncthreads();
    float mean = red[0][0], inv = red[1][0];
#pragma unroll
    for (int j = 0; j < 4; j++) {
        int c = t + j * 128;
        yr[c] = ga[c] * (v[j] - mean) * inv + gb[c];
    }
}

// ---------------- generic GEMM: C = A(MxK) @ W(KxN) + bias [+res] [relu] ----------------
// 64x64 tile, BK=16, 256 threads, 4x4 micro-tile. M%64==0, N%64==0, K%16==0.
__global__ void gemm_kernel(const float* __restrict__ A, const float* __restrict__ W,
                            const float* __restrict__ bias, const float* __restrict__ res,
                            float* __restrict__ C, int M, int N, int K, int relu) {
    __shared__ float As[16][64];
    __shared__ float Bs[16][64];
    int row0 = blockIdx.y * 64, col0 = blockIdx.x * 64;
    int tid = threadIdx.x;
    int tx = tid & 15, ty = tid >> 4;
    int am = tid >> 2, ak = (tid & 3) * 4;
    int bk = tid >> 4, bn = (tid & 15) * 4;
    float acc[4][4] = {};
    for (int k0 = 0; k0 < K; k0 += 16) {
        float4 a4 = *(const float4*)(A + (size_t)(row0 + am) * K + k0 + ak);
        float4 b4 = *(const float4*)(W + (size_t)(k0 + bk) * N + col0 + bn);
        As[ak + 0][am] = a4.x; As[ak + 1][am] = a4.y;
        As[ak + 2][am] = a4.z; As[ak + 3][am] = a4.w;
        *(float4*)&Bs[bk][bn] = b4;
        __syncthreads();
#pragma unroll
        for (int k = 0; k < 16; k++) {
            float ar[4], br[4];
#pragma unroll
            for (int i = 0; i < 4; i++) ar[i] = As[k][ty * 4 + i];
            float4 bb = *(float4*)&Bs[k][tx * 4];
            br[0] = bb.x; br[1] = bb.y; br[2] = bb.z; br[3] = bb.w;
#pragma unroll
            for (int i = 0; i < 4; i++)
#pragma unroll
                for (int j = 0; j < 4; j++) acc[i][j] += ar[i] * br[j];
        }
        __syncthreads();
    }
#pragma unroll
    for (int i = 0; i < 4; i++) {
        int r = row0 + ty * 4 + i;
#pragma unroll
        for (int j = 0; j < 4; j++) {
            int c = col0 + tx * 4 + j;
            float v = acc[i][j] + bias[c];
            if (res) v += res[(size_t)r * N + c];
            if (relu) v = fmaxf(v, 0.f);
            C[(size_t)r * N + c] = v;
        }
    }
}

// ---------------- batched QK^T: S[z,m,n] = scale * sum_d Q[b,m,h*64+d]*K[b,n,h*64+d] ----------------
__global__ void qk_kernel(const float* __restrict__ Q, const float* __restrict__ Kc,
                          float* __restrict__ Sc, int Lq, int Lk, float scale) {
    int z = blockIdx.z, b = z / NHEAD, h = z % NHEAD;
    const float* Qb = Q + (size_t)b * Lq * D_MODEL + h * DK;
    const float* Kb = Kc + (size_t)b * Lk * D_MODEL + h * DK;
    float* Sb = Sc + (size_t)z * Lq * Lk;
    __shared__ float Qs[16][64];
    __shared__ float Ks[16][64];
    int m0 = blockIdx.y * 64, n0 = blockIdx.x * 64;
    int tid = threadIdx.x;
    int tx = tid & 15, ty = tid >> 4;
    int am = tid >> 2, ak = (tid & 3) * 4;
    float acc[4][4] = {};
    for (int k0 = 0; k0 < DK; k0 += 16) {
        float4 a4 = *(const float4*)(Qb + (size_t)(m0 + am) * D_MODEL + k0 + ak);
        float4 b4 = *(const float4*)(Kb + (size_t)(n0 + am) * D_MODEL + k0 + ak);
        Qs[ak + 0][am] = a4.x; Qs[ak + 1][am] = a4.y;
        Qs[ak + 2][am] = a4.z; Qs[ak + 3][am] = a4.w;
        Ks[ak + 0][am] = b4.x; Ks[ak + 1][am] = b4.y;
        Ks[ak + 2][am] = b4.z; Ks[ak + 3][am] = b4.w;
        __syncthreads();
#pragma unroll
        for (int k = 0; k < 16; k++) {
            float ar[4], br[4];
#pragma unroll
            for (int i = 0; i < 4; i++) { ar[i] = Qs[k][ty * 4 + i]; br[i] = Ks[k][tx * 4 + i]; }
#pragma unroll
            for (int i = 0; i < 4; i++)
#pragma unroll
                for (int j = 0; j < 4; j++) acc[i][j] += ar[i] * br[j];
        }
        __syncthreads();
    }
#pragma unroll
    for (int i = 0; i < 4; i++)
#pragma unroll
        for (int j = 0; j < 4; j++)
            Sb[(size_t)(m0 + ty * 4 + i) * Lk + n0 + tx * 4 + j] = acc[i][j] * scale;
}

// ---------------- masked softmax over last dim, in place. warp per row ----------------
template <int LK>
__global__ void softmax_kernel(float* __restrict__ Sc, const int* __restrict__ amask,
                               int Lq, int maskStride, int causal) {
    int warp = (blockIdx.x * blockDim.x + threadIdx.x) >> 5;
    int lane = threadIdx.x & 31;
    int total = BATCH * NHEAD * Lq;
    if (warp >= total) return;
    int qi = warp % Lq;
    int b  = warp / (NHEAD * Lq);
    float* row = Sc + (size_t)warp * LK;
    const int* mrow = amask + (size_t)b * maskStride;
    const int NPER = LK / 32;
    float vals[NPER];
    float mx = -1e30f;
#pragma unroll
    for (int j = 0; j < NPER; j++) {
        int ki = lane + j * 32;
        bool ok = (mrow[ki] != 0) && (!causal || ki <= qi);
        float v = ok ? row[ki] : -10000.0f;
        vals[j] = v; mx = fmaxf(mx, v);
    }
#pragma unroll
    for (int o = 16; o > 0; o >>= 1) mx = fmaxf(mx, __shfl_xor_sync(0xffffffffu, mx, o));
    float sum = 0.f;
#pragma unroll
    for (int j = 0; j < NPER; j++) { vals[j] = expf(vals[j] - mx); sum += vals[j]; }
#pragma unroll
    for (int o = 16; o > 0; o >>= 1) sum += __shfl_xor_sync(0xffffffffu, sum, o);
    float inv = 1.0f / sum;
#pragma unroll
    for (int j = 0; j < NPER; j++) row[lane + j * 32] = vals[j] * inv;
}

// ---------------- batched P@V: O[b,m,h*64+n] = sum_k P[z,m,k]*V[b,k,h*64+n] ----------------
__global__ void pv_kernel(const float* __restrict__ P, const float* __restrict__ V,
                          float* __restrict__ O, int Lq, int Lk) {
    int z = blockIdx.z, b = z / NHEAD, h = z % NHEAD;
    const float* Pb = P + (size_t)z * Lq * Lk;
    const float* Vb = V + (size_t)b * Lk * D_MODEL + h * DK;
    float*       Ob = O + (size_t)b * Lq * D_MODEL + h * DK;
    int m0 = blockIdx.y * 64;  // N tile is the full 64-wide head dim
    __shared__ float Ps[16][64];
    __shared__ float Vs[16][64];
    int tid = threadIdx.x;
    int tx = tid & 15, ty = tid >> 4;
    int am = tid >> 2, ak = (tid & 3) * 4;
    int bk = tid >> 4, bn = (tid & 15) * 4;
    float acc[4][4] = {};
    for (int k0 = 0; k0 < Lk; k0 += 16) {
        float4 a4 = *(const float4*)(Pb + (size_t)(m0 + am) * Lk + k0 + ak);
        float4 b4 = *(const float4*)(Vb + (size_t)(k0 + bk) * D_MODEL + bn);
        Ps[ak + 0][am] = a4.x; Ps[ak + 1][am] = a4.y;
        Ps[ak + 2][am] = a4.z; Ps[ak + 3][am] = a4.w;
        *(float4*)&Vs[bk][bn] = b4;
        __syncthreads();
#pragma unroll
        for (int k = 0; k < 16; k++) {
            float ar[4], br[4];
#pragma unroll
            for (int i = 0; i < 4; i++) ar[i] = Ps[k][ty * 4 + i];
            float4 bb = *(float4*)&Vs[k][tx * 4];
            br[0] = bb.x; br[1] = bb.y; br[2] = bb.z; br[3] = bb.w;
#pragma unroll
            for (int i = 0; i < 4; i++)
#pragma unroll
                for (int j = 0; j < 4; j++) acc[i][j] += ar[i] * br[j];
        }
        __syncthreads();
    }
#pragma unroll
    for (int i = 0; i < 4; i++)
#pragma unroll
        for (int j = 0; j < 4; j++)
            Ob[(size_t)(m0 + ty * 4 + i) * D_MODEL + tx * 4 + j] = acc[i][j];
}

// ---------------- final log_softmax (warp per row, 512 cols) ----------------
__global__ void logsoftmax_kernel(const float* __restrict__ X, float* __restrict__ Out) {
    int warp = (blockIdx.x * blockDim.x + threadIdx.x) >> 5;
    int lane = threadIdx.x & 31;
    if (warp >= MT) return;
    const float* r = X + (size_t)warp * VOCAB;
    float v[16], mx = -1e30f;
#pragma unroll
    for (int j = 0; j < 16; j++) { v[j] = r[lane + j * 32]; mx = fmaxf(mx, v[j]); }
#pragma unroll
    for (int o = 16; o > 0; o >>= 1) mx = fmaxf(mx, __shfl_xor_sync(0xffffffffu, mx, o));
    float sum = 0.f;
#pragma unroll
    for (int j = 0; j < 16; j++) sum += expf(v[j] - mx);
#pragma unroll
    for (int o = 16; o > 0; o >>= 1) sum += __shfl_xor_sync(0xffffffffu, sum, o);
    float lse = mx + logf(sum);
    float* out = Out + (size_t)warp * VOCAB;
#pragma unroll
    for (int j = 0; j < 16; j++) out[lane + j * 32] = v[j] - lse;
}

// ---------------- host driver ----------------
static float* sym(const void* s) {
    void* p = nullptr;
    cudaGetSymbolAddress(&p, s);
    return (float*)p;
}

extern "C" void kernel_launch(void* const* d_in, const int* in_sizes, int n_in,
                              void* d_out, int out_size) {
    const int*   ids    = (const int*)d_in[0];
    const int*   attm   = (const int*)d_in[1];
    const float* src    = (const float*)d_in[2];
    const int*   srcm   = (const int*)d_in[3];
    const float* emb    = (const float*)d_in[4];
    const float* sa_W   = (const float*)d_in[5];
    const float* sa_b   = (const float*)d_in[6];
    const float* ca_W   = (const float*)d_in[7];
    const float* ca_b   = (const float*)d_in[8];
    const float* ln_a   = (const float*)d_in[9];
    const float* ln_b   = (const float*)d_in[10];
    const float* ffn_w1 = (const float*)d_in[11];
    const float* ffn_b1 = (const float*)d_in[12];
    const float* ffn_w2 = (const float*)d_in[13];
    const float* ffn_b2 = (const float*)d_in[14];
    const float* fin_a  = (const float*)d_in[15];
    const float* fin_b  = (const float*)d_in[16];
    const float* lm_W   = (const float*)d_in[17];
    const float* lm_b   = (const float*)d_in[18];
    float* out = (float*)d_out;

    float* x   = sym(g_x);
    float* h   = sym(g_h);
    float* q   = sym(g_q);
    float* kb  = sym(g_k);
    float* vb  = sym(g_v);
    float* att = sym(g_att);
    float* sc  = sym(g_sc);
    float* ffn = sym(g_ffn);
    float* lg  = sym(g_lg);

    const float scale = 1.0f / 8.0f;  // 1/sqrt(64)

    // PE table + embedding
    pe_kernel<<<(LT * D_MODEL + 255) / 256, 256>>>();
    embed_kernel<<<(MT * D_MODEL + 255) / 256, 256>>>(ids, emb);

    dim3 gProjT(D_MODEL / 64, MT / 64);   // 8192 x 512
    dim3 gProjS(D_MODEL / 64, MS / 64);   // 4096 x 512
    dim3 gFfn1(D_FF / 64, MT / 64);
    dim3 gFfn2(D_MODEL / 64, MT / 64);

    for (int i = 0; i < NLAYER; i++) {
        const float* saW = sa_W + (size_t)i * 4 * D_MODEL * D_MODEL;
        const float* sab = sa_b + (size_t)i * 4 * D_MODEL;
        const float* caW = ca_W + (size_t)i * 4 * D_MODEL * D_MODEL;
        const float* cab = ca_b + (size_t)i * 4 * D_MODEL;
        const float* lnA = ln_a + (size_t)i * 3 * D_MODEL;
        const float* lnB = ln_b + (size_t)i * 3 * D_MODEL;

        // ---- self-attention ----
        ln_kernel<<<MT, 128>>>(x, h, lnA + 0 * D_MODEL, lnB + 0 * D_MODEL);
        gemm_kernel<<<gProjT, 256>>>(h, saW + 0 * D_MODEL * D_MODEL, sab + 0 * D_MODEL, nullptr, q,  MT, D_MODEL, D_MODEL, 0);
        gemm_kernel<<<gProjT, 256>>>(h, saW + 1 * D_MODEL * D_MODEL, sab + 1 * D_MODEL, nullptr, kb, MT, D_MODEL, D_MODEL, 0);
        gemm_kernel<<<gProjT, 256>>>(h, saW + 2 * D_MODEL * D_MODEL, sab + 2 * D_MODEL, nullptr, vb, MT, D_MODEL, D_MODEL, 0);
        qk_kernel<<<dim3(LT / 64, LT / 64, BATCH * NHEAD), 256>>>(q, kb, sc, LT, LT, scale);
        softmax_kernel<LT><<<(BATCH * NHEAD * LT) / 8, 256>>>(sc, attm, LT, LFULL, 1);
        pv_kernel<<<dim3(1, LT / 64, BATCH * NHEAD), 256>>>(sc, vb, att, LT, LT);
        gemm_kernel<<<gProjT, 256>>>(att, saW + 3 * D_MODEL * D_MODEL, sab + 3 * D_MODEL, x, x, MT, D_MODEL, D_MODEL, 0);

        // ---- cross-attention ----
        ln_kernel<<<MT, 128>>>(x, h, lnA + 1 * D_MODEL, lnB + 1 * D_MODEL);
        gemm_kernel<<<gProjT, 256>>>(h,   caW + 0 * D_MODEL * D_MODEL, cab + 0 * D_MODEL, nullptr, q,  MT, D_MODEL, D_MODEL, 0);
        gemm_kernel<<<gProjS, 256>>>(src, caW + 1 * D_MODEL * D_MODEL, cab + 1 * D_MODEL, nullptr, kb, MS, D_MODEL, D_MODEL, 0);
        gemm_kernel<<<gProjS, 256>>>(src, caW + 2 * D_MODEL * D_MODEL, cab + 2 * D_MODEL, nullptr, vb, MS, D_MODEL, D_MODEL, 0);
        qk_kernel<<<dim3(SRC_S / 64, LT / 64, BATCH * NHEAD), 256>>>(q, kb, sc, LT, SRC_S, scale);
        softmax_kernel<SRC_S><<<(BATCH * NHEAD * LT) / 8, 256>>>(sc, srcm, LT, SRC_S, 0);
        pv_kernel<<<dim3(1, LT / 64, BATCH * NHEAD), 256>>>(sc, vb, att, LT, SRC_S);
        gemm_kernel<<<gProjT, 256>>>(att, caW + 3 * D_MODEL * D_MODEL, cab + 3 * D_MODEL, x, x, MT, D_MODEL, D_MODEL, 0);

        // ---- FFN ----
        ln_kernel<<<MT, 128>>>(x, h, lnA + 2 * D_MODEL, lnB + 2 * D_MODEL);
        gemm_kernel<<<gFfn1, 256>>>(h, ffn_w1 + (size_t)i * D_MODEL * D_FF, ffn_b1 + (size_t)i * D_FF, nullptr, ffn, MT, D_FF, D_MODEL, 1);
        gemm_kernel<<<gFfn2, 256>>>(ffn, ffn_w2 + (size_t)i * D_FF * D_MODEL, ffn_b2 + (size_t)i * D_MODEL, x, x, MT, D_MODEL, D_FF, 0);
    }

    // final LN + LM head + log_softmax
    ln_kernel<<<MT, 128>>>(x, h, fin_a, fin_b);
    gemm_kernel<<<dim3(VOCAB / 64, MT / 64), 256>>>(h, lm_W, lm_b, nullptr, lg, MT, VOCAB, D_MODEL, 0);
    logsoftmax_kernel<<<(MT * 32 + 255) / 256, 256>>>(lg, out);
}

// round 5
// speedup vs baseline: 2.9493x; 2.9493x over previous
#include <cuda_runtime.h>
#include <math.h>

// ---------------- problem constants ----------------
#define D_MODEL 512
#define D_FF    2048
#define NHEAD   8
#define DK      64
#define NLAYER  4
#define VOCAB   512
#define BATCH   16
#define LFULL   513
#define LT      512          // target length (L-1)
#define SRC_S   256
#define MT      (BATCH*LT)   // 8192 token rows
#define MS      (BATCH*SRC_S)// 4096 src rows

// ---------------- device scratch (static, no allocation) ----------------
__device__ float g_x  [MT*D_MODEL];
__device__ float g_h  [MT*D_MODEL];
__device__ float g_q  [MT*D_MODEL];
__device__ float g_k  [MT*D_MODEL];
__device__ float g_v  [MT*D_MODEL];
__device__ float g_att[MT*D_MODEL];
__device__ float g_sc [BATCH*NHEAD*LT*LT];
__device__ float g_ffn[MT*D_FF];
__device__ float g_pe [LT*D_MODEL];
__device__ float g_lg [MT*VOCAB];

// ---------------- small PTX helpers ----------------
__device__ __forceinline__ void cpa16(void* s, const void* g) {
    unsigned a = (unsigned)__cvta_generic_to_shared(s);
    asm volatile("cp.async.ca.shared.global [%0], [%1], 16;" :: "r"(a), "l"(g));
}
__device__ __forceinline__ void cp_commit() { asm volatile("cp.async.commit_group;"); }
__device__ __forceinline__ void cp_wait0()  { asm volatile("cp.async.wait_group 0;"); }
__device__ __forceinline__ void cp_wait1()  { asm volatile("cp.async.wait_group 1;"); }
__device__ __forceinline__ unsigned f2tf(float f) {
    unsigned u; asm("cvt.rna.tf32.f32 %0, %1;" : "=r"(u) : "f"(f)); return u;
}
__device__ __forceinline__ void mma8(float* c, const unsigned* a, const unsigned* b) {
    asm volatile(
        "mma.sync.aligned.m16n8k8.row.col.f32.tf32.tf32.f32 "
        "{%0,%1,%2,%3}, {%4,%5,%6,%7}, {%8,%9}, {%0,%1,%2,%3};"
        : "+f"(c[0]), "+f"(c[1]), "+f"(c[2]), "+f"(c[3])
        : "r"(a[0]), "r"(a[1]), "r"(a[2]), "r"(a[3]), "r"(b[0]), "r"(b[1]));
}

// ---------------- positional encoding (fp64 to match numpy) ----------------
__global__ void pe_kernel() {
    int i = blockIdx.x * blockDim.x + threadIdx.x;
    if (i >= LT * D_MODEL) return;
    int t = i / D_MODEL, d = i % D_MODEL;
    int e = d & ~1;
    double div = exp(-(double)e * (log(10000.0) / (double)D_MODEL));
    double ang = (double)t * div;
    g_pe[i] = (float)((d & 1) ? cos(ang) : sin(ang));
}

// ---------------- embedding + PE ----------------
__global__ void embed_kernel(const int* __restrict__ ids, const float* __restrict__ emb) {
    int i = blockIdx.x * blockDim.x + threadIdx.x;
    if (i >= MT * D_MODEL) return;
    int row = i / D_MODEL, d = i % D_MODEL;
    int b = row / LT, t = row % LT;
    int tok = ids[b * LFULL + t];
    g_x[i] = emb[tok * D_MODEL + d] * 22.62741699796952f + g_pe[t * D_MODEL + d];
}

// ---------------- layernorm (ddof=1, denom = std + eps) ----------------
__global__ void ln_kernel(const float* __restrict__ x, float* __restrict__ y,
                          const float* __restrict__ ga, const float* __restrict__ gb) {
    int row = blockIdx.x;
    const float* xr = x + (size_t)row * D_MODEL;
    float*       yr = y + (size_t)row * D_MODEL;
    int t = threadIdx.x;  // 128 threads
    float v[4], s = 0.f, s2 = 0.f;
#pragma unroll
    for (int j = 0; j < 4; j++) {
        v[j] = xr[t + j * 128];
        s += v[j]; s2 += v[j] * v[j];
    }
    __shared__ float red[2][4];
#pragma unroll
    for (int o = 16; o > 0; o >>= 1) {
        s  += __shfl_down_sync(0xffffffffu, s,  o);
        s2 += __shfl_down_sync(0xffffffffu, s2, o);
    }
    if ((t & 31) == 0) { red[0][t >> 5] = s; red[1][t >> 5] = s2; }
    __syncthreads();
    if (t == 0) {
        float S1 = red[0][0] + red[0][1] + red[0][2] + red[0][3];
        float S2 = red[1][0] + red[1][1] + red[1][2] + red[1][3];
        float mean = S1 / 512.0f;
        float var  = fmaxf(0.f, S2 - 512.0f * mean * mean) / 511.0f;
        red[0][0] = mean;
        red[1][0] = 1.0f / (sqrtf(var) + 1e-6f);
    }
    __syncthreads();
    float mean = red[0][0], inv = red[1][0];
#pragma unroll
    for (int j = 0; j < 4; j++) {
        int c = t + j * 128;
        yr[c] = ga[c] * (v[j] - mean) * inv + gb[c];
    }
}

// =====================================================================
// Tensor-core TF32 GEMM: C = A(MxK,row) @ W(KxN,row) + bias [+res][relu]
// BM=128 BN=128 BK=16, 256 threads, 8 warps (2m x 4n), warp tile 64x32.
// =====================================================================
__global__ void __launch_bounds__(256) gemm_tc(
        const float* __restrict__ A, const float* __restrict__ W,
        const float* __restrict__ bias, const float* __restrict__ res,
        float* __restrict__ C, int M, int N, int K, int relu) {
    __shared__ float As[2][128][20];   // [m][k], stride 20 -> conflict-free frags
    __shared__ float Bs[2][16][136];   // [k][n], stride 136 -> conflict-free frags
    int row0 = blockIdx.y * 128, col0 = blockIdx.x * 128;
    int tid = threadIdx.x;
    int wid = tid >> 5, lane = tid & 31;
    int g = lane >> 2, t = lane & 3;
    int wm = wid & 1, wn = wid >> 1;   // warp tile origin: (wm*64, wn*32)

    float c[4][4][4];
#pragma unroll
    for (int i = 0; i < 4; i++)
#pragma unroll
        for (int j = 0; j < 4; j++)
#pragma unroll
            for (int r = 0; r < 4; r++) c[i][j][r] = 0.f;

    int nIter = K >> 4;
    // ---- prologue prefetch stage 0 ----
    {
#pragma unroll
        for (int i = 0; i < 2; i++) {
            int idx = tid + i * 256;
            int m = idx >> 2, kq = (idx & 3) * 4;
            cpa16(&As[0][m][kq], A + (size_t)(row0 + m) * K + kq);
        }
#pragma unroll
        for (int i = 0; i < 2; i++) {
            int idx = tid + i * 256;
            int k = idx >> 5, nq = (idx & 31) * 4;
            cpa16(&Bs[0][k][nq], W + (size_t)k * N + col0 + nq);
        }
        cp_commit();
    }
    int s = 0;
    for (int it = 0; it < nIter; ++it) {
        if (it + 1 < nIter) {
            int k0g = (it + 1) << 4;
#pragma unroll
            for (int i = 0; i < 2; i++) {
                int idx = tid + i * 256;
                int m = idx >> 2, kq = (idx & 3) * 4;
                cpa16(&As[s ^ 1][m][kq], A + (size_t)(row0 + m) * K + k0g + kq);
            }
#pragma unroll
            for (int i = 0; i < 2; i++) {
                int idx = tid + i * 256;
                int k = idx >> 5, nq = (idx & 31) * 4;
                cpa16(&Bs[s ^ 1][k][nq], W + (size_t)(k0g + k) * N + col0 + nq);
            }
            cp_commit();
            cp_wait1();
        } else {
            cp_wait0();
        }
        __syncthreads();
#pragma unroll
        for (int ks = 0; ks < 2; ks++) {
            int k0 = ks * 8;
            unsigned af[4][4];
#pragma unroll
            for (int mt = 0; mt < 4; mt++) {
                int mr = wm * 64 + mt * 16 + g;
                af[mt][0] = f2tf(As[s][mr][k0 + t]);
                af[mt][1] = f2tf(As[s][mr + 8][k0 + t]);
                af[mt][2] = f2tf(As[s][mr][k0 + t + 4]);
                af[mt][3] = f2tf(As[s][mr + 8][k0 + t + 4]);
            }
            unsigned bf[4][2];
#pragma unroll
            for (int nt = 0; nt < 4; nt++) {
                int nc = wn * 32 + nt * 8 + g;
                bf[nt][0] = f2tf(Bs[s][k0 + t][nc]);
                bf[nt][1] = f2tf(Bs[s][k0 + t + 4][nc]);
            }
#pragma unroll
            for (int mt = 0; mt < 4; mt++)
#pragma unroll
                for (int nt = 0; nt < 4; nt++) mma8(c[mt][nt], af[mt], bf[nt]);
        }
        __syncthreads();
        s ^= 1;
    }
    // ---- epilogue ----
#pragma unroll
    for (int mt = 0; mt < 4; mt++) {
        int r = row0 + wm * 64 + mt * 16 + g;
#pragma unroll
        for (int nt = 0; nt < 4; nt++) {
            int cc = col0 + wn * 32 + nt * 8 + 2 * t;
            float b0 = bias[cc], b1 = bias[cc + 1];
            float v0 = c[mt][nt][0] + b0, v1 = c[mt][nt][1] + b1;
            float v2 = c[mt][nt][2] + b0, v3 = c[mt][nt][3] + b1;
            if (res) {
                v0 += res[(size_t)r * N + cc];       v1 += res[(size_t)r * N + cc + 1];
                v2 += res[(size_t)(r + 8) * N + cc]; v3 += res[(size_t)(r + 8) * N + cc + 1];
            }
            if (relu) {
                v0 = fmaxf(v0, 0.f); v1 = fmaxf(v1, 0.f);
                v2 = fmaxf(v2, 0.f); v3 = fmaxf(v3, 0.f);
            }
            *(float2*)(C + (size_t)r * N + cc)       = make_float2(v0, v1);
            *(float2*)(C + (size_t)(r + 8) * N + cc) = make_float2(v2, v3);
        }
    }
}

// =====================================================================
// Tensor-core QK^T: S[z,m,n] = scale * Q[b,m,h*64+k] . K[b,n,h*64+k]
// NT gemm: both operands row-major with contiguous k. BM=BN=128, K=64.
// =====================================================================
__global__ void __launch_bounds__(256) qk_tc(
        const float* __restrict__ Q, const float* __restrict__ Kc,
        float* __restrict__ Sc, int Lq, int Lk, float scale) {
    __shared__ float As[2][128][20];
    __shared__ float Ns[2][128][20];
    int z = blockIdx.z, b = z / NHEAD, h = z % NHEAD;
    const float* Qb = Q  + (size_t)b * Lq * D_MODEL + h * DK;
    const float* Kb = Kc + (size_t)b * Lk * D_MODEL + h * DK;
    float* Sb = Sc + (size_t)z * Lq * Lk;
    int m0 = blockIdx.y * 128, n0b = blockIdx.x * 128;
    int tid = threadIdx.x;
    int wid = tid >> 5, lane = tid & 31;
    int g = lane >> 2, t = lane & 3;
    int wm = wid & 1, wn = wid >> 1;

    float c[4][4][4];
#pragma unroll
    for (int i = 0; i < 4; i++)
#pragma unroll
        for (int j = 0; j < 4; j++)
#pragma unroll
            for (int r = 0; r < 4; r++) c[i][j][r] = 0.f;

    const int nIter = DK >> 4;  // 4
    {
#pragma unroll
        for (int i = 0; i < 2; i++) {
            int idx = tid + i * 256;
            int m = idx >> 2, kq = (idx & 3) * 4;
            cpa16(&As[0][m][kq], Qb + (size_t)(m0 + m) * D_MODEL + kq);
            cpa16(&Ns[0][m][kq], Kb + (size_t)(n0b + m) * D_MODEL + kq);
        }
        cp_commit();
    }
    int s = 0;
    for (int it = 0; it < nIter; ++it) {
        if (it + 1 < nIter) {
            int k0g = (it + 1) << 4;
#pragma unroll
            for (int i = 0; i < 2; i++) {
                int idx = tid + i * 256;
                int m = idx >> 2, kq = (idx & 3) * 4;
                cpa16(&As[s ^ 1][m][kq], Qb + (size_t)(m0 + m) * D_MODEL + k0g + kq);
                cpa16(&Ns[s ^ 1][m][kq], Kb + (size_t)(n0b + m) * D_MODEL + k0g + kq);
            }
            cp_commit();
            cp_wait1();
        } else {
            cp_wait0();
        }
        __syncthreads();
#pragma unroll
        for (int ks = 0; ks < 2; ks++) {
            int k0 = ks * 8;
            unsigned af[4][4];
#pragma unroll
            for (int mt = 0; mt < 4; mt++) {
                int mr = wm * 64 + mt * 16 + g;
                af[mt][0] = f2tf(As[s][mr][k0 + t]);
                af[mt][1] = f2tf(As[s][mr + 8][k0 + t]);
                af[mt][2] = f2tf(As[s][mr][k0 + t + 4]);
                af[mt][3] = f2tf(As[s][mr + 8][k0 + t + 4]);
            }
            unsigned bf[4][2];
#pragma unroll
            for (int nt = 0; nt < 4; nt++) {
                int nc = wn * 32 + nt * 8 + g;
                bf[nt][0] = f2tf(Ns[s][nc][k0 + t]);
                bf[nt][1] = f2tf(Ns[s][nc][k0 + t + 4]);
            }
#pragma unroll
            for (int mt = 0; mt < 4; mt++)
#pragma unroll
                for (int nt = 0; nt < 4; nt++) mma8(c[mt][nt], af[mt], bf[nt]);
        }
        __syncthreads();
        s ^= 1;
    }
#pragma unroll
    for (int mt = 0; mt < 4; mt++) {
        int r = m0 + wm * 64 + mt * 16 + g;
#pragma unroll
        for (int nt = 0; nt < 4; nt++) {
            int cc = n0b + wn * 32 + nt * 8 + 2 * t;
            *(float2*)(Sb + (size_t)r * Lk + cc) =
                make_float2(c[mt][nt][0] * scale, c[mt][nt][1] * scale);
            *(float2*)(Sb + (size_t)(r + 8) * Lk + cc) =
                make_float2(c[mt][nt][2] * scale, c[mt][nt][3] * scale);
        }
    }
}

// =====================================================================
// Tensor-core P@V: O[b,m,h*64+n] = P[z,m,k] . V[b,k,h*64+n]
// BM=128, BN=64, BK=16. 8 warps (4m x 2n), warp tile 32x32.
// =====================================================================
__global__ void __launch_bounds__(256) pv_tc(
        const float* __restrict__ P, const float* __restrict__ V,
        float* __restrict__ O, int Lq, int Lk) {
    __shared__ float As[2][128][20];
    __shared__ float Bs[2][16][72];
    int z = blockIdx.z, b = z / NHEAD, h = z % NHEAD;
    const float* Pb = P + (size_t)z * Lq * Lk;
    const float* Vb = V + (size_t)b * Lk * D_MODEL + h * DK;
    float*       Ob = O + (size_t)b * Lq * D_MODEL + h * DK;
    int m0 = blockIdx.y * 128;
    int tid = threadIdx.x;
    int wid = tid >> 5, lane = tid & 31;
    int g = lane >> 2, t = lane & 3;
    int wm = wid >> 1, wn = wid & 1;   // (wm*32, wn*32)

    float c[2][4][4];
#pragma unroll
    for (int i = 0; i < 2; i++)
#pragma unroll
        for (int j = 0; j < 4; j++)
#pragma unroll
            for (int r = 0; r < 4; r++) c[i][j][r] = 0.f;

    int nIter = Lk >> 4;
    {
#pragma unroll
        for (int i = 0; i < 2; i++) {
            int idx = tid + i * 256;
            int m = idx >> 2, kq = (idx & 3) * 4;
            cpa16(&As[0][m][kq], Pb + (size_t)(m0 + m) * Lk + kq);
        }
        { int k = tid >> 4, nq = (tid & 15) * 4;
          cpa16(&Bs[0][k][nq], Vb + (size_t)k * D_MODEL + nq); }
        cp_commit();
    }
    int s = 0;
    for (int it = 0; it < nIter; ++it) {
        if (it + 1 < nIter) {
            int k0g = (it + 1) << 4;
#pragma unroll
            for (int i = 0; i < 2; i++) {
                int idx = tid + i * 256;
                int m = idx >> 2, kq = (idx & 3) * 4;
                cpa16(&As[s ^ 1][m][kq], Pb + (size_t)(m0 + m) * Lk + k0g + kq);
            }
            { int k = tid >> 4, nq = (tid & 15) * 4;
              cpa16(&Bs[s ^ 1][k][nq], Vb + (size_t)(k0g + k) * D_MODEL + nq); }
            cp_commit();
            cp_wait1();
        } else {
            cp_wait0();
        }
        __syncthreads();
#pragma unroll
        for (int ks = 0; ks < 2; ks++) {
            int k0 = ks * 8;
            unsigned af[2][4];
#pragma unroll
            for (int mt = 0; mt < 2; mt++) {
                int mr = wm * 32 + mt * 16 + g;
                af[mt][0] = f2tf(As[s][mr][k0 + t]);
                af[mt][1] = f2tf(As[s][mr + 8][k0 + t]);
                af[mt][2] = f2tf(As[s][mr][k0 + t + 4]);
                af[mt][3] = f2tf(As[s][mr + 8][k0 + t + 4]);
            }
            unsigned bf[4][2];
#pragma unroll
            for (int nt = 0; nt < 4; nt++) {
                int nc = wn * 32 + nt * 8 + g;
                bf[nt][0] = f2tf(Bs[s][k0 + t][nc]);
                bf[nt][1] = f2tf(Bs[s][k0 + t + 4][nc]);
            }
#pragma unroll
            for (int mt = 0; mt < 2; mt++)
#pragma unroll
                for (int nt = 0; nt < 4; nt++) mma8(c[mt][nt], af[mt], bf[nt]);
        }
        __syncthreads();
        s ^= 1;
    }
#pragma unroll
    for (int mt = 0; mt < 2; mt++) {
        int r = m0 + wm * 32 + mt * 16 + g;
#pragma unroll
        for (int nt = 0; nt < 4; nt++) {
            int cc = wn * 32 + nt * 8 + 2 * t;
            *(float2*)(Ob + (size_t)r * D_MODEL + cc) =
                make_float2(c[mt][nt][0], c[mt][nt][1]);
            *(float2*)(Ob + (size_t)(r + 8) * D_MODEL + cc) =
                make_float2(c[mt][nt][2], c[mt][nt][3]);
        }
    }
}

// ---------------- masked softmax over last dim, in place. warp per row ----------------
template <int LK>
__global__ void softmax_kernel(float* __restrict__ Sc, const int* __restrict__ amask,
                               int Lq, int maskStride, int causal) {
    int warp = (blockIdx.x * blockDim.x + threadIdx.x) >> 5;
    int lane = threadIdx.x & 31;
    int total = BATCH * NHEAD * Lq;
    if (warp >= total) return;
    int qi = warp % Lq;
    int b  = warp / (NHEAD * Lq);
    float* row = Sc + (size_t)warp * LK;
    const int* mrow = amask + (size_t)b * maskStride;
    const int NPER = LK / 32;
    float vals[NPER];
    float mx = -1e30f;
#pragma unroll
    for (int j = 0; j < NPER; j++) {
        int ki = lane + j * 32;
        bool ok = (mrow[ki] != 0) && (!causal || ki <= qi);
        float v = ok ? row[ki] : -10000.0f;
        vals[j] = v; mx = fmaxf(mx, v);
    }
#pragma unroll
    for (int o = 16; o > 0; o >>= 1) mx = fmaxf(mx, __shfl_xor_sync(0xffffffffu, mx, o));
    float sum = 0.f;
#pragma unroll
    for (int j = 0; j < NPER; j++) { vals[j] = expf(vals[j] - mx); sum += vals[j]; }
#pragma unroll
    for (int o = 16; o > 0; o >>= 1) sum += __shfl_xor_sync(0xffffffffu, sum, o);
    float inv = 1.0f / sum;
#pragma unroll
    for (int j = 0; j < NPER; j++) row[lane + j * 32] = vals[j] * inv;
}

// ---------------- final log_softmax (warp per row, 512 cols) ----------------
__global__ void logsoftmax_kernel(const float* __restrict__ X, float* __restrict__ Out) {
    int warp = (blockIdx.x * blockDim.x + threadIdx.x) >> 5;
    int lane = threadIdx.x & 31;
    if (warp >= MT) return;
    const float* r = X + (size_t)warp * VOCAB;
    float v[16], mx = -1e30f;
#pragma unroll
    for (int j = 0; j < 16; j++) { v[j] = r[lane + j * 32]; mx = fmaxf(mx, v[j]); }
#pragma unroll
    for (int o = 16; o > 0; o >>= 1) mx = fmaxf(mx, __shfl_xor_sync(0xffffffffu, mx, o));
    float sum = 0.f;
#pragma unroll
    for (int j = 0; j < 16; j++) sum += expf(v[j] - mx);
#pragma unroll
    for (int o = 16; o > 0; o >>= 1) sum += __shfl_xor_sync(0xffffffffu, sum, o);
    float lse = mx + logf(sum);
    float* out = Out + (size_t)warp * VOCAB;
#pragma unroll
    for (int j = 0; j < 16; j++) out[lane + j * 32] = v[j] - lse;
}

// ---------------- host driver ----------------
static float* sym(const void* s) {
    void* p = nullptr;
    cudaGetSymbolAddress(&p, s);
    return (float*)p;
}

extern "C" void kernel_launch(void* const* d_in, const int* in_sizes, int n_in,
                              void* d_out, int out_size) {
    const int*   ids    = (const int*)d_in[0];
    const int*   attm   = (const int*)d_in[1];
    const float* src    = (const float*)d_in[2];
    const int*   srcm   = (const int*)d_in[3];
    const float* emb    = (const float*)d_in[4];
    const float* sa_W   = (const float*)d_in[5];
    const float* sa_b   = (const float*)d_in[6];
    const float* ca_W   = (const float*)d_in[7];
    const float* ca_b   = (const float*)d_in[8];
    const float* ln_a   = (const float*)d_in[9];
    const float* ln_b   = (const float*)d_in[10];
    const float* ffn_w1 = (const float*)d_in[11];
    const float* ffn_b1 = (const float*)d_in[12];
    const float* ffn_w2 = (const float*)d_in[13];
    const float* ffn_b2 = (const float*)d_in[14];
    const float* fin_a  = (const float*)d_in[15];
    const float* fin_b  = (const float*)d_in[16];
    const float* lm_W   = (const float*)d_in[17];
    const float* lm_b   = (const float*)d_in[18];
    float* out = (float*)d_out;

    float* x   = sym(g_x);
    float* h   = sym(g_h);
    float* q   = sym(g_q);
    float* kb  = sym(g_k);
    float* vb  = sym(g_v);
    float* att = sym(g_att);
    float* sc  = sym(g_sc);
    float* ffn = sym(g_ffn);
    float* lg  = sym(g_lg);

    const float scale = 1.0f / 8.0f;  // 1/sqrt(64)

    pe_kernel<<<(LT * D_MODEL + 255) / 256, 256>>>();
    embed_kernel<<<(MT * D_MODEL + 255) / 256, 256>>>(ids, emb);

    dim3 gProjT(D_MODEL / 128, MT / 128);   // (4, 64)
    dim3 gProjS(D_MODEL / 128, MS / 128);   // (4, 32)
    dim3 gFfn1(D_FF / 128, MT / 128);       // (16, 64)
    dim3 gFfn2(D_MODEL / 128, MT / 128);    // (4, 64)

    for (int i = 0; i < NLAYER; i++) {
        const float* saW = sa_W + (size_t)i * 4 * D_MODEL * D_MODEL;
        const float* sab = sa_b + (size_t)i * 4 * D_MODEL;
        const float* caW = ca_W + (size_t)i * 4 * D_MODEL * D_MODEL;
        const float* cab = ca_b + (size_t)i * 4 * D_MODEL;
        const float* lnA = ln_a + (size_t)i * 3 * D_MODEL;
        const float* lnB = ln_b + (size_t)i * 3 * D_MODEL;

        // ---- self-attention ----
        ln_kernel<<<MT, 128>>>(x, h, lnA + 0 * D_MODEL, lnB + 0 * D_MODEL);
        gemm_tc<<<gProjT, 256>>>(h, saW + 0 * D_MODEL * D_MODEL, sab + 0 * D_MODEL, nullptr, q,  MT, D_MODEL, D_MODEL, 0);
        gemm_tc<<<gProjT, 256>>>(h, saW + 1 * D_MODEL * D_MODEL, sab + 1 * D_MODEL, nullptr, kb, MT, D_MODEL, D_MODEL, 0);
        gemm_tc<<<gProjT, 256>>>(h, saW + 2 * D_MODEL * D_MODEL, sab + 2 * D_MODEL, nullptr, vb, MT, D_MODEL, D_MODEL, 0);
        qk_tc<<<dim3(LT / 128, LT / 128, BATCH * NHEAD), 256>>>(q, kb, sc, LT, LT, scale);
        softmax_kernel<LT><<<(BATCH * NHEAD * LT) / 8, 256>>>(sc, attm, LT, LFULL, 1);
        pv_tc<<<dim3(1, LT / 128, BATCH * NHEAD), 256>>>(sc, vb, att, LT, LT);
        gemm_tc<<<gProjT, 256>>>(att, saW + 3 * D_MODEL * D_MODEL, sab + 3 * D_MODEL, x, x, MT, D_MODEL, D_MODEL, 0);

        // ---- cross-attention ----
        ln_kernel<<<MT, 128>>>(x, h, lnA + 1 * D_MODEL, lnB + 1 * D_MODEL);
        gemm_tc<<<gProjT, 256>>>(h,   caW + 0 * D_MODEL * D_MODEL, cab + 0 * D_MODEL, nullptr, q,  MT, D_MODEL, D_MODEL, 0);
        gemm_tc<<<gProjS, 256>>>(src, caW + 1 * D_MODEL * D_MODEL, cab + 1 * D_MODEL, nullptr, kb, MS, D_MODEL, D_MODEL, 0);
        gemm_tc<<<gProjS, 256>>>(src, caW + 2 * D_MODEL * D_MODEL, cab + 2 * D_MODEL, nullptr, vb, MS, D_MODEL, D_MODEL, 0);
        qk_tc<<<dim3(SRC_S / 128, LT / 128, BATCH * NHEAD), 256>>>(q, kb, sc, LT, SRC_S, scale);
        softmax_kernel<SRC_S><<<(BATCH * NHEAD * LT) / 8, 256>>>(sc, srcm, LT, SRC_S, 0);
        pv_tc<<<dim3(1, LT / 128, BATCH * NHEAD), 256>>>(sc, vb, att, LT, SRC_S);
        gemm_tc<<<gProjT, 256>>>(att, caW + 3 * D_MODEL * D_MODEL, cab + 3 * D_MODEL, x, x, MT, D_MODEL, D_MODEL, 0);

        // ---- FFN ----
        ln_kernel<<<MT, 128>>>(x, h, lnA + 2 * D_MODEL, lnB + 2 * D_MODEL);
        gemm_tc<<<gFfn1, 256>>>(h, ffn_w1 + (size_t)i * D_MODEL * D_FF, ffn_b1 + (size_t)i * D_FF, nullptr, ffn, MT, D_FF, D_MODEL, 1);
        gemm_tc<<<gFfn2, 256>>>(ffn, ffn_w2 + (size_t)i * D_FF * D_MODEL, ffn_b2 + (size_t)i * D_MODEL, x, x, MT, D_MODEL, D_FF, 0);
    }

    ln_kernel<<<MT, 128>>>(x, h, fin_a, fin_b);
    gemm_tc<<<dim3(VOCAB / 128, MT / 128), 256>>>(h, lm_W, lm_b, nullptr, lg, MT, VOCAB, D_MODEL, 0);
    logsoftmax_kernel<<<(MT * 32 + 255) / 256, 256>>>(lg, out);
}

// round 6
// speedup vs baseline: 4.6291x; 1.5696x over previous
#include <cuda_runtime.h>
#include <cuda_bf16.h>
#include <math.h>

// ---------------- problem constants ----------------
#define D_MODEL 512
#define D_FF    2048
#define NHEAD   8
#define DK      64
#define NLAYER  4
#define VOCAB   512
#define BATCH   16
#define LFULL   513
#define LT      512
#define SRC_S   256
#define MT      (BATCH*LT)
#define MS      (BATCH*SRC_S)

typedef __nv_bfloat16 bf16;
typedef __nv_bfloat162 bf162;

// ---------------- device scratch (static, no allocation) ----------------
__device__ float g_x  [MT*D_MODEL];                  // residual stream (fp32)
__device__ float g_sc [BATCH*NHEAD*LT*LT];           // scores (fp32)
__device__ float g_pe [LT*D_MODEL];
__device__ float g_lg [MT*VOCAB];

__device__ bf16 g_hb [MT*D_MODEL];                   // ln output
__device__ bf16 g_qb [MT*D_MODEL];
__device__ bf16 g_kb [MT*D_MODEL];
__device__ bf16 g_vb [MT*D_MODEL];
__device__ bf16 g_ab [MT*D_MODEL];                   // attention output
__device__ bf16 g_fb [MT*D_FF];                      // ffn intermediate
__device__ bf16 g_pb [BATCH*NHEAD*LT*LT];            // softmax probs
__device__ bf16 g_wsa[NLAYER*4*D_MODEL*D_MODEL];
__device__ bf16 g_wca[NLAYER*4*D_MODEL*D_MODEL];
__device__ bf16 g_w1 [NLAYER*D_MODEL*D_FF];
__device__ bf16 g_w2 [NLAYER*D_FF*D_MODEL];
__device__ bf16 g_wlm[D_MODEL*VOCAB];
__device__ bf16 g_srcb[MS*D_MODEL];

// ---------------- PTX helpers ----------------
__device__ __forceinline__ void cpa16(void* s, const void* g) {
    unsigned a = (unsigned)__cvta_generic_to_shared(s);
    asm volatile("cp.async.ca.shared.global [%0], [%1], 16;" :: "r"(a), "l"(g));
}
__device__ __forceinline__ void cp_commit() { asm volatile("cp.async.commit_group;"); }
__device__ __forceinline__ void cp_wait0()  { asm volatile("cp.async.wait_group 0;"); }
__device__ __forceinline__ void cp_wait1()  { asm volatile("cp.async.wait_group 1;"); }
__device__ __forceinline__ void ldm_x4_t(unsigned* r, const void* p) {
    unsigned a = (unsigned)__cvta_generic_to_shared(p);
    asm volatile("ldmatrix.sync.aligned.m8n8.x4.trans.shared.b16 {%0,%1,%2,%3}, [%4];"
        : "=r"(r[0]), "=r"(r[1]), "=r"(r[2]), "=r"(r[3]) : "r"(a));
}
__device__ __forceinline__ void mmabf(float* c, const unsigned* a, const unsigned* b) {
    asm volatile(
        "mma.sync.aligned.m16n8k16.row.col.f32.bf16.bf16.f32 "
        "{%0,%1,%2,%3}, {%4,%5,%6,%7}, {%8,%9}, {%0,%1,%2,%3};"
        : "+f"(c[0]), "+f"(c[1]), "+f"(c[2]), "+f"(c[3])
        : "r"(a[0]), "r"(a[1]), "r"(a[2]), "r"(a[3]), "r"(b[0]), "r"(b[1]));
}

// ---------------- fp32 -> bf16 convert (grid-stride) ----------------
__global__ void f2bf_kernel(const float* __restrict__ s, bf16* __restrict__ d, int n) {
    int i = blockIdx.x * blockDim.x + threadIdx.x;
    int stride = gridDim.x * blockDim.x;
    for (; i < n; i += stride) d[i] = __float2bfloat16(s[i]);
}

// ---------------- positional encoding (fp64 to match numpy) ----------------
__global__ void pe_kernel() {
    int i = blockIdx.x * blockDim.x + threadIdx.x;
    if (i >= LT * D_MODEL) return;
    int t = i / D_MODEL, d = i % D_MODEL;
    int e = d & ~1;
    double div = exp(-(double)e * (log(10000.0) / (double)D_MODEL));
    double ang = (double)t * div;
    g_pe[i] = (float)((d & 1) ? cos(ang) : sin(ang));
}

// ---------------- embedding + PE ----------------
__global__ void embed_kernel(const int* __restrict__ ids, const float* __restrict__ emb) {
    int i = blockIdx.x * blockDim.x + threadIdx.x;
    if (i >= MT * D_MODEL) return;
    int row = i / D_MODEL, d = i % D_MODEL;
    int b = row / LT, t = row % LT;
    int tok = ids[b * LFULL + t];
    g_x[i] = emb[tok * D_MODEL + d] * 22.62741699796952f + g_pe[t * D_MODEL + d];
}

// ---------------- layernorm (ddof=1, denom = std + eps), bf16 out ----------------
__global__ void ln_kernel(const float* __restrict__ x, bf16* __restrict__ y,
                          const float* __restrict__ ga, const float* __restrict__ gb) {
    int row = blockIdx.x;
    const float* xr = x + (size_t)row * D_MODEL;
    bf16*        yr = y + (size_t)row * D_MODEL;
    int t = threadIdx.x;  // 128 threads
    float v[4], s = 0.f, s2 = 0.f;
#pragma unroll
    for (int j = 0; j < 4; j++) {
        v[j] = xr[t + j * 128];
        s += v[j]; s2 += v[j] * v[j];
    }
    __shared__ float red[2][4];
#pragma unroll
    for (int o = 16; o > 0; o >>= 1) {
        s  += __shfl_down_sync(0xffffffffu, s,  o);
        s2 += __shfl_down_sync(0xffffffffu, s2, o);
    }
    if ((t & 31) == 0) { red[0][t >> 5] = s; red[1][t >> 5] = s2; }
    __syncthreads();
    if (t == 0) {
        float S1 = red[0][0] + red[0][1] + red[0][2] + red[0][3];
        float S2 = red[1][0] + red[1][1] + red[1][2] + red[1][3];
        float mean = S1 / 512.0f;
        float var  = fmaxf(0.f, S2 - 512.0f * mean * mean) / 511.0f;
        red[0][0] = mean;
        red[1][0] = 1.0f / (sqrtf(var) + 1e-6f);
    }
    __syncthreads();
    float mean = red[0][0], inv = red[1][0];
#pragma unroll
    for (int j = 0; j < 4; j++) {
        int c = t + j * 128;
        yr[c] = __float2bfloat16(ga[c] * (v[j] - mean) * inv + gb[c]);
    }
}

// =====================================================================
// bf16 tensor-core GEMM: C = A(MxK,row) @ W(KxN,row) + bias [+res][relu]
// BM=128 BN=128 BK=32, 256 threads, 8 warps (2m x 4n), warp tile 64x32.
// Outputs: Cb (bf16, optional) and/or Cf (fp32, optional).
// =====================================================================
__global__ void __launch_bounds__(256) gemm_bf(
        const bf16* __restrict__ A, const bf16* __restrict__ W,
        const float* __restrict__ bias, const float* __restrict__ res,
        bf16* __restrict__ Cb, float* __restrict__ Cf,
        int M, int N, int K, int relu) {
    __shared__ __align__(16) bf16 As[2][128][40];   // stride 80B
    __shared__ __align__(16) bf16 Bs[2][32][136];   // stride 272B
    int row0 = blockIdx.y * 128, col0 = blockIdx.x * 128;
    int tid = threadIdx.x;
    int wid = tid >> 5, lane = tid & 31;
    int g = lane >> 2, t = lane & 3;
    int wm = wid & 1, wn = wid >> 1;
    int tl = lane >> 3, rr = lane & 7;   // ldmatrix tile/row

    float c[4][4][4];
#pragma unroll
    for (int i = 0; i < 4; i++)
#pragma unroll
        for (int j = 0; j < 4; j++)
#pragma unroll
            for (int r = 0; r < 4; r++) c[i][j][r] = 0.f;

    int nIter = K >> 5;
    {
#pragma unroll
        for (int i = 0; i < 2; i++) {
            int idx = tid + i * 256;
            int m = idx >> 2, kq = (idx & 3) * 8;
            cpa16(&As[0][m][kq], A + (size_t)(row0 + m) * K + kq);
        }
#pragma unroll
        for (int i = 0; i < 2; i++) {
            int idx = tid + i * 256;
            int k = idx >> 4, nq = (idx & 15) * 8;
            cpa16(&Bs[0][k][nq], W + (size_t)k * N + col0 + nq);
        }
        cp_commit();
    }
    int s = 0;
    for (int it = 0; it < nIter; ++it) {
        if (it + 1 < nIter) {
            int k0g = (it + 1) << 5;
#pragma unroll
            for (int i = 0; i < 2; i++) {
                int idx = tid + i * 256;
                int m = idx >> 2, kq = (idx & 3) * 8;
                cpa16(&As[s ^ 1][m][kq], A + (size_t)(row0 + m) * K + k0g + kq);
            }
#pragma unroll
            for (int i = 0; i < 2; i++) {
                int idx = tid + i * 256;
                int k = idx >> 4, nq = (idx & 15) * 8;
                cpa16(&Bs[s ^ 1][k][nq], W + (size_t)(k0g + k) * N + col0 + nq);
            }
            cp_commit();
            cp_wait1();
        } else {
            cp_wait0();
        }
        __syncthreads();
#pragma unroll
        for (int ks = 0; ks < 2; ks++) {
            int k0 = ks * 16;
            unsigned af[4][4];
#pragma unroll
            for (int mt = 0; mt < 4; mt++) {
                int mr = wm * 64 + mt * 16 + g;
                af[mt][0] = *(const unsigned*)&As[s][mr    ][k0 + 2 * t];
                af[mt][1] = *(const unsigned*)&As[s][mr + 8][k0 + 2 * t];
                af[mt][2] = *(const unsigned*)&As[s][mr    ][k0 + 8 + 2 * t];
                af[mt][3] = *(const unsigned*)&As[s][mr + 8][k0 + 8 + 2 * t];
            }
            unsigned bf[4][2];
#pragma unroll
            for (int nb = 0; nb < 2; nb++) {
                unsigned r4[4];
                ldm_x4_t(r4, &Bs[s][k0 + (tl & 1) * 8 + rr][wn * 32 + nb * 16 + (tl >> 1) * 8]);
                bf[nb * 2 + 0][0] = r4[0]; bf[nb * 2 + 0][1] = r4[1];
                bf[nb * 2 + 1][0] = r4[2]; bf[nb * 2 + 1][1] = r4[3];
            }
#pragma unroll
            for (int mt = 0; mt < 4; mt++)
#pragma unroll
                for (int nt = 0; nt < 4; nt++) mmabf(c[mt][nt], af[mt], bf[nt]);
        }
        __syncthreads();
        s ^= 1;
    }
    // ---- epilogue ----
#pragma unroll
    for (int mt = 0; mt < 4; mt++) {
        int r = row0 + wm * 64 + mt * 16 + g;
#pragma unroll
        for (int nt = 0; nt < 4; nt++) {
            int cc = col0 + wn * 32 + nt * 8 + 2 * t;
            float b0 = bias[cc], b1 = bias[cc + 1];
            float v0 = c[mt][nt][0] + b0, v1 = c[mt][nt][1] + b1;
            float v2 = c[mt][nt][2] + b0, v3 = c[mt][nt][3] + b1;
            if (res) {
                v0 += res[(size_t)r * N + cc];       v1 += res[(size_t)r * N + cc + 1];
                v2 += res[(size_t)(r + 8) * N + cc]; v3 += res[(size_t)(r + 8) * N + cc + 1];
            }
            if (relu) {
                v0 = fmaxf(v0, 0.f); v1 = fmaxf(v1, 0.f);
                v2 = fmaxf(v2, 0.f); v3 = fmaxf(v3, 0.f);
            }
            if (Cf) {
                *(float2*)(Cf + (size_t)r * N + cc)       = make_float2(v0, v1);
                *(float2*)(Cf + (size_t)(r + 8) * N + cc) = make_float2(v2, v3);
            }
            if (Cb) {
                *(bf162*)(Cb + (size_t)r * N + cc)       = __float22bfloat162_rn(make_float2(v0, v1));
                *(bf162*)(Cb + (size_t)(r + 8) * N + cc) = __float22bfloat162_rn(make_float2(v2, v3));
            }
        }
    }
}

// =====================================================================
// bf16 QK^T (NT): S = scale * Q . K^T, fp32 out. BM=BN=128, K=64, 1 stage.
// =====================================================================
__global__ void __launch_bounds__(256) qk_bf(
        const bf16* __restrict__ Q, const bf16* __restrict__ Kc,
        float* __restrict__ Sc, int Lq, int Lk, float scale) {
    __shared__ __align__(16) bf16 Qs[128][72];
    __shared__ __align__(16) bf16 Ks[128][72];
    int z = blockIdx.z, b = z / NHEAD, h = z % NHEAD;
    const bf16* Qb = Q  + (size_t)b * Lq * D_MODEL + h * DK;
    const bf16* Kb = Kc + (size_t)b * Lk * D_MODEL + h * DK;
    float* Sb = Sc + (size_t)z * Lq * Lk;
    int m0 = blockIdx.y * 128, n0b = blockIdx.x * 128;
    int tid = threadIdx.x;
    int wid = tid >> 5, lane = tid & 31;
    int g = lane >> 2, t = lane & 3;
    int wm = wid & 1, wn = wid >> 1;

    float c[4][4][4];
#pragma unroll
    for (int i = 0; i < 4; i++)
#pragma unroll
        for (int j = 0; j < 4; j++)
#pragma unroll
            for (int r = 0; r < 4; r++) c[i][j][r] = 0.f;

#pragma unroll
    for (int i = 0; i < 4; i++) {
        int idx = tid + i * 256;
        int m = idx >> 3, kq = (idx & 7) * 8;
        cpa16(&Qs[m][kq], Qb + (size_t)(m0 + m)  * D_MODEL + kq);
        cpa16(&Ks[m][kq], Kb + (size_t)(n0b + m) * D_MODEL + kq);
    }
    cp_commit();
    cp_wait0();
    __syncthreads();

#pragma unroll
    for (int ks = 0; ks < 4; ks++) {
        int k0 = ks * 16;
        unsigned af[4][4];
#pragma unroll
        for (int mt = 0; mt < 4; mt++) {
            int mr = wm * 64 + mt * 16 + g;
            af[mt][0] = *(const unsigned*)&Qs[mr    ][k0 + 2 * t];
            af[mt][1] = *(const unsigned*)&Qs[mr + 8][k0 + 2 * t];
            af[mt][2] = *(const unsigned*)&Qs[mr    ][k0 + 8 + 2 * t];
            af[mt][3] = *(const unsigned*)&Qs[mr + 8][k0 + 8 + 2 * t];
        }
        unsigned bf[4][2];
#pragma unroll
        for (int nt = 0; nt < 4; nt++) {
            int nc = wn * 32 + nt * 8 + g;
            bf[nt][0] = *(const unsigned*)&Ks[nc][k0 + 2 * t];
            bf[nt][1] = *(const unsigned*)&Ks[nc][k0 + 8 + 2 * t];
        }
#pragma unroll
        for (int mt = 0; mt < 4; mt++)
#pragma unroll
            for (int nt = 0; nt < 4; nt++) mmabf(c[mt][nt], af[mt], bf[nt]);
    }

#pragma unroll
    for (int mt = 0; mt < 4; mt++) {
        int r = m0 + wm * 64 + mt * 16 + g;
#pragma unroll
        for (int nt = 0; nt < 4; nt++) {
            int cc = n0b + wn * 32 + nt * 8 + 2 * t;
            *(float2*)(Sb + (size_t)r * Lk + cc) =
                make_float2(c[mt][nt][0] * scale, c[mt][nt][1] * scale);
            *(float2*)(Sb + (size_t)(r + 8) * Lk + cc) =
                make_float2(c[mt][nt][2] * scale, c[mt][nt][3] * scale);
        }
    }
}

// =====================================================================
// bf16 P@V: O = P . V, bf16 out. BM=128, BN=64, BK=32. 8 warps (4m x 2n).
// =====================================================================
__global__ void __launch_bounds__(256) pv_bf(
        const bf16* __restrict__ P, const bf16* __restrict__ V,
        bf16* __restrict__ O, int Lq, int Lk) {
    __shared__ __align__(16) bf16 Ps[2][128][40];
    __shared__ __align__(16) bf16 Vs[2][32][72];
    int z = blockIdx.z, b = z / NHEAD, h = z % NHEAD;
    const bf16* Pb = P + (size_t)z * Lq * Lk;
    const bf16* Vb = V + (size_t)b * Lk * D_MODEL + h * DK;
    bf16*       Ob = O + (size_t)b * Lq * D_MODEL + h * DK;
    int m0 = blockIdx.y * 128;
    int tid = threadIdx.x;
    int wid = tid >> 5, lane = tid & 31;
    int g = lane >> 2, t = lane & 3;
    int wm = wid >> 1, wn = wid & 1;
    int tl = lane >> 3, rr = lane & 7;

    float c[2][4][4];
#pragma unroll
    for (int i = 0; i < 2; i++)
#pragma unroll
        for (int j = 0; j < 4; j++)
#pragma unroll
            for (int r = 0; r < 4; r++) c[i][j][r] = 0.f;

    int nIter = Lk >> 5;
    {
#pragma unroll
        for (int i = 0; i < 2; i++) {
            int idx = tid + i * 256;
            int m = idx >> 2, kq = (idx & 3) * 8;
            cpa16(&Ps[0][m][kq], Pb + (size_t)(m0 + m) * Lk + kq);
        }
        { int k = tid >> 3, nq = (tid & 7) * 8;
          cpa16(&Vs[0][k][nq], Vb + (size_t)k * D_MODEL + nq); }
        cp_commit();
    }
    int s = 0;
    for (int it = 0; it < nIter; ++it) {
        if (it + 1 < nIter) {
            int k0g = (it + 1) << 5;
#pragma unroll
            for (int i = 0; i < 2; i++) {
                int idx = tid + i * 256;
                int m = idx >> 2, kq = (idx & 3) * 8;
                cpa16(&Ps[s ^ 1][m][kq], Pb + (size_t)(m0 + m) * Lk + k0g + kq);
            }
            { int k = tid >> 3, nq = (tid & 7) * 8;
              cpa16(&Vs[s ^ 1][k][nq], Vb + (size_t)(k0g + k) * D_MODEL + nq); }
            cp_commit();
            cp_wait1();
        } else {
            cp_wait0();
        }
        __syncthreads();
#pragma unroll
        for (int ks = 0; ks < 2; ks++) {
            int k0 = ks * 16;
            unsigned af[2][4];
#pragma unroll
            for (int mt = 0; mt < 2; mt++) {
                int mr = wm * 32 + mt * 16 + g;
                af[mt][0] = *(const unsigned*)&Ps[s][mr    ][k0 + 2 * t];
                af[mt][1] = *(const unsigned*)&Ps[s][mr + 8][k0 + 2 * t];
                af[mt][2] = *(const unsigned*)&Ps[s][mr    ][k0 + 8 + 2 * t];
                af[mt][3] = *(const unsigned*)&Ps[s][mr + 8][k0 + 8 + 2 * t];
            }
            unsigned bf[4][2];
#pragma unroll
            for (int nb = 0; nb < 2; nb++) {
                unsigned r4[4];
                ldm_x4_t(r4, &Vs[s][k0 + (tl & 1) * 8 + rr][wn * 32 + nb * 16 + (tl >> 1) * 8]);
                bf[nb * 2 + 0][0] = r4[0]; bf[nb * 2 + 0][1] = r4[1];
                bf[nb * 2 + 1][0] = r4[2]; bf[nb * 2 + 1][1] = r4[3];
            }
#pragma unroll
            for (int mt = 0; mt < 2; mt++)
#pragma unroll
                for (int nt = 0; nt < 4; nt++) mmabf(c[mt][nt], af[mt], bf[nt]);
        }
        __syncthreads();
        s ^= 1;
    }
#pragma unroll
    for (int mt = 0; mt < 2; mt++) {
        int r = m0 + wm * 32 + mt * 16 + g;
#pragma unroll
        for (int nt = 0; nt < 4; nt++) {
            int cc = wn * 32 + nt * 8 + 2 * t;
            *(bf162*)(Ob + (size_t)r * D_MODEL + cc) =
                __float22bfloat162_rn(make_float2(c[mt][nt][0], c[mt][nt][1]));
            *(bf162*)(Ob + (size_t)(r + 8) * D_MODEL + cc) =
                __float22bfloat162_rn(make_float2(c[mt][nt][2], c[mt][nt][3]));
        }
    }
}

// ---------------- masked softmax: fp32 in -> bf16 probs out ----------------
template <int LK>
__global__ void softmax_kernel(const float* __restrict__ Sc, bf16* __restrict__ Pr,
                               const int* __restrict__ amask,
                               int Lq, int maskStride, int causal) {
    int warp = (blockIdx.x * blockDim.x + threadIdx.x) >> 5;
    int lane = threadIdx.x & 31;
    int total = BATCH * NHEAD * Lq;
    if (warp >= total) return;
    int qi = warp % Lq;
    int b  = warp / (NHEAD * Lq);
    const float* row = Sc + (size_t)warp * LK;
    bf16* prow = Pr + (size_t)warp * LK;
    const int* mrow = amask + (size_t)b * maskStride;
    const int NPER = LK / 32;
    float vals[NPER];
    float mx = -1e30f;
#pragma unroll
    for (int j = 0; j < NPER; j++) {
        int ki = lane + j * 32;
        bool ok = (mrow[ki] != 0) && (!causal || ki <= qi);
        float v = ok ? row[ki] : -10000.0f;
        vals[j] = v; mx = fmaxf(mx, v);
    }
#pragma unroll
    for (int o = 16; o > 0; o >>= 1) mx = fmaxf(mx, __shfl_xor_sync(0xffffffffu, mx, o));
    float sum = 0.f;
#pragma unroll
    for (int j = 0; j < NPER; j++) { vals[j] = expf(vals[j] - mx); sum += vals[j]; }
#pragma unroll
    for (int o = 16; o > 0; o >>= 1) sum += __shfl_xor_sync(0xffffffffu, sum, o);
    float inv = 1.0f / sum;
#pragma unroll
    for (int j = 0; j < NPER; j++) prow[lane + j * 32] = __float2bfloat16(vals[j] * inv);
}

// ---------------- final log_softmax (warp per row, 512 cols) ----------------
__global__ void logsoftmax_kernel(const float* __restrict__ X, float* __restrict__ Out) {
    int warp = (blockIdx.x * blockDim.x + threadIdx.x) >> 5;
    int lane = threadIdx.x & 31;
    if (warp >= MT) return;
    const float* r = X + (size_t)warp * VOCAB;
    float v[16], mx = -1e30f;
#pragma unroll
    for (int j = 0; j < 16; j++) { v[j] = r[lane + j * 32]; mx = fmaxf(mx, v[j]); }
#pragma unroll
    for (int o = 16; o > 0; o >>= 1) mx = fmaxf(mx, __shfl_xor_sync(0xffffffffu, mx, o));
    float sum = 0.f;
#pragma unroll
    for (int j = 0; j < 16; j++) sum += expf(v[j] - mx);
#pragma unroll
    for (int o = 16; o > 0; o >>= 1) sum += __shfl_xor_sync(0xffffffffu, sum, o);
    float lse = mx + logf(sum);
    float* out = Out + (size_t)warp * VOCAB;
#pragma unroll
    for (int j = 0; j < 16; j++) out[lane + j * 32] = v[j] - lse;
}

// ---------------- host driver ----------------
template <typename T>
static T* symp(const void* s) {
    void* p = nullptr;
    cudaGetSymbolAddress(&p, s);
    return (T*)p;
}

extern "C" void kernel_launch(void* const* d_in, const int* in_sizes, int n_in,
                              void* d_out, int out_size) {
    const int*   ids    = (const int*)d_in[0];
    const int*   attm   = (const int*)d_in[1];
    const float* src    = (const float*)d_in[2];
    const int*   srcm   = (const int*)d_in[3];
    const float* emb    = (const float*)d_in[4];
    const float* sa_W   = (const float*)d_in[5];
    const float* sa_b   = (const float*)d_in[6];
    const float* ca_W   = (const float*)d_in[7];
    const float* ca_b   = (const float*)d_in[8];
    const float* ln_a   = (const float*)d_in[9];
    const float* ln_b   = (const float*)d_in[10];
    const float* ffn_w1 = (const float*)d_in[11];
    const float* ffn_b1 = (const float*)d_in[12];
    const float* ffn_w2 = (const float*)d_in[13];
    const float* ffn_b2 = (const float*)d_in[14];
    const float* fin_a  = (const float*)d_in[15];
    const float* fin_b  = (const float*)d_in[16];
    const float* lm_W   = (const float*)d_in[17];
    const float* lm_b   = (const float*)d_in[18];
    float* out = (float*)d_out;

    float* x   = symp<float>(g_x);
    float* sc  = symp<float>(g_sc);
    float* lg  = symp<float>(g_lg);
    bf16* hb   = symp<bf16>(g_hb);
    bf16* qb   = symp<bf16>(g_qb);
    bf16* kbb  = symp<bf16>(g_kb);
    bf16* vbb  = symp<bf16>(g_vb);
    bf16* ab   = symp<bf16>(g_ab);
    bf16* fb   = symp<bf16>(g_fb);
    bf16* pb   = symp<bf16>(g_pb);
    bf16* wsa  = symp<bf16>(g_wsa);
    bf16* wca  = symp<bf16>(g_wca);
    bf16* w1   = symp<bf16>(g_w1);
    bf16* w2   = symp<bf16>(g_w2);
    bf16* wlm  = symp<bf16>(g_wlm);
    bf16* srcb = symp<bf16>(g_srcb);

    const float scale = 1.0f / 8.0f;  // 1/sqrt(64)

    // ---- one-time-per-launch conversions (fp32 -> bf16) ----
    {
        int nW = NLAYER * 4 * D_MODEL * D_MODEL;
        int nF = NLAYER * D_MODEL * D_FF;
        f2bf_kernel<<<(nW + 1023) / 1024, 256>>>(sa_W, wsa, nW);
        f2bf_kernel<<<(nW + 1023) / 1024, 256>>>(ca_W, wca, nW);
        f2bf_kernel<<<(nF + 1023) / 1024, 256>>>(ffn_w1, w1, nF);
        f2bf_kernel<<<(nF + 1023) / 1024, 256>>>(ffn_w2, w2, nF);
        f2bf_kernel<<<(D_MODEL * VOCAB + 1023) / 1024, 256>>>(lm_W, wlm, D_MODEL * VOCAB);
        f2bf_kernel<<<(MS * D_MODEL + 1023) / 1024, 256>>>(src, srcb, MS * D_MODEL);
    }

    pe_kernel<<<(LT * D_MODEL + 255) / 256, 256>>>();
    embed_kernel<<<(MT * D_MODEL + 255) / 256, 256>>>(ids, emb);

    dim3 gProjT(D_MODEL / 128, MT / 128);
    dim3 gProjS(D_MODEL / 128, MS / 128);
    dim3 gFfn1(D_FF / 128, MT / 128);
    dim3 gFfn2(D_MODEL / 128, MT / 128);

    for (int i = 0; i < NLAYER; i++) {
        const bf16* saW = wsa + (size_t)i * 4 * D_MODEL * D_MODEL;
        const float* sab = sa_b + (size_t)i * 4 * D_MODEL;
        const bf16* caW = wca + (size_t)i * 4 * D_MODEL * D_MODEL;
        const float* cab = ca_b + (size_t)i * 4 * D_MODEL;
        const float* lnA = ln_a + (size_t)i * 3 * D_MODEL;
        const float* lnB = ln_b + (size_t)i * 3 * D_MODEL;

        // ---- self-attention ----
        ln_kernel<<<MT, 128>>>(x, hb, lnA + 0 * D_MODEL, lnB + 0 * D_MODEL);
        gemm_bf<<<gProjT, 256>>>(hb, saW + 0 * D_MODEL * D_MODEL, sab + 0 * D_MODEL, nullptr, qb,  nullptr, MT, D_MODEL, D_MODEL, 0);
        gemm_bf<<<gProjT, 256>>>(hb, saW + 1 * D_MODEL * D_MODEL, sab + 1 * D_MODEL, nullptr, kbb, nullptr, MT, D_MODEL, D_MODEL, 0);
        gemm_bf<<<gProjT, 256>>>(hb, saW + 2 * D_MODEL * D_MODEL, sab + 2 * D_MODEL, nullptr, vbb, nullptr, MT, D_MODEL, D_MODEL, 0);
        qk_bf<<<dim3(LT / 128, LT / 128, BATCH * NHEAD), 256>>>(qb, kbb, sc, LT, LT, scale);
        softmax_kernel<LT><<<(BATCH * NHEAD * LT) / 8, 256>>>(sc, pb, attm, LT, LFULL, 1);
        pv_bf<<<dim3(1, LT / 128, BATCH * NHEAD), 256>>>(pb, vbb, ab, LT, LT);
        gemm_bf<<<gProjT, 256>>>(ab, saW + 3 * D_MODEL * D_MODEL, sab + 3 * D_MODEL, x, nullptr, x, MT, D_MODEL, D_MODEL, 0);

        // ---- cross-attention ----
        ln_kernel<<<MT, 128>>>(x, hb, lnA + 1 * D_MODEL, lnB + 1 * D_MODEL);
        gemm_bf<<<gProjT, 256>>>(hb,   caW + 0 * D_MODEL * D_MODEL, cab + 0 * D_MODEL, nullptr, qb,  nullptr, MT, D_MODEL, D_MODEL, 0);
        gemm_bf<<<gProjS, 256>>>(srcb, caW + 1 * D_MODEL * D_MODEL, cab + 1 * D_MODEL, nullptr, kbb, nullptr, MS, D_MODEL, D_MODEL, 0);
        gemm_bf<<<gProjS, 256>>>(srcb, caW + 2 * D_MODEL * D_MODEL, cab + 2 * D_MODEL, nullptr, vbb, nullptr, MS, D_MODEL, D_MODEL, 0);
        qk_bf<<<dim3(SRC_S / 128, LT / 128, BATCH * NHEAD), 256>>>(qb, kbb, sc, LT, SRC_S, scale);
        softmax_kernel<SRC_S><<<(BATCH * NHEAD * LT) / 8, 256>>>(sc, pb, srcm, LT, SRC_S, 0);
        pv_bf<<<dim3(1, LT / 128, BATCH * NHEAD), 256>>>(pb, vbb, ab, LT, SRC_S);
        gemm_bf<<<gProjT, 256>>>(ab, caW + 3 * D_MODEL * D_MODEL, cab + 3 * D_MODEL, x, nullptr, x, MT, D_MODEL, D_MODEL, 0);

        // ---- FFN ----
        ln_kernel<<<MT, 128>>>(x, hb, lnA + 2 * D_MODEL, lnB + 2 * D_MODEL);
        gemm_bf<<<gFfn1, 256>>>(hb, w1 + (size_t)i * D_MODEL * D_FF, ffn_b1 + (size_t)i * D_FF, nullptr, fb, nullptr, MT, D_FF, D_MODEL, 1);
        gemm_bf<<<gFfn2, 256>>>(fb, w2 + (size_t)i * D_FF * D_MODEL, ffn_b2 + (size_t)i * D_MODEL, x, nullptr, x, MT, D_MODEL, D_FF, 0);
    }

    ln_kernel<<<MT, 128>>>(x, hb, fin_a, fin_b);
    gemm_bf<<<dim3(VOCAB / 128, MT / 128), 256>>>(hb, wlm, lm_b, nullptr, nullptr, lg, MT, VOCAB, D_MODEL, 0);
    logsoftmax_kernel<<<(MT * 32 + 255) / 256, 256>>>(lg, out);
}

// round 7
// speedup vs baseline: 5.4644x; 1.1804x over previous
#include <cuda_runtime.h>
#include <cuda_bf16.h>
#include <math.h>

// ---------------- problem constants ----------------
#define D_MODEL 512
#define D_FF    2048
#define NHEAD   8
#define DK      64
#define NLAYER  4
#define VOCAB   512
#define BATCH   16
#define LFULL   513
#define LT      512
#define SRC_S   256
#define MT      (BATCH*LT)
#define MS      (BATCH*SRC_S)

typedef __nv_bfloat16 bf16;
typedef __nv_bfloat162 bf162;

// ---------------- device scratch (static, no allocation) ----------------
__device__ float g_x  [MT*D_MODEL];                  // residual stream (fp32)
__device__ float g_pe [LT*D_MODEL];
__device__ float g_lg [MT*VOCAB];

__device__ bf16 g_hb [MT*D_MODEL];                   // ln output
__device__ bf16 g_qb [MT*D_MODEL];                   // cross-attn Q
__device__ bf16 g_qkv[MT*3*D_MODEL];                 // fused self QKV
__device__ bf16 g_kv [MS*2*D_MODEL];                 // fused cross KV
__device__ bf16 g_ab [MT*D_MODEL];                   // attention output
__device__ bf16 g_fb [MT*D_FF];                      // ffn intermediate
__device__ bf16 g_wsa[NLAYER*4*D_MODEL*D_MODEL];
__device__ bf16 g_wca[NLAYER*4*D_MODEL*D_MODEL];
__device__ bf16 g_wqkv[NLAYER*D_MODEL*3*D_MODEL];    // packed self QKV weights
__device__ bf16 g_wkv [NLAYER*D_MODEL*2*D_MODEL];    // packed cross KV weights
__device__ float g_bqkv[NLAYER*3*D_MODEL];
__device__ float g_bkv [NLAYER*2*D_MODEL];
__device__ bf16 g_w1 [NLAYER*D_MODEL*D_FF];
__device__ bf16 g_w2 [NLAYER*D_FF*D_MODEL];
__device__ bf16 g_wlm[D_MODEL*VOCAB];
__device__ bf16 g_srcb[MS*D_MODEL];

// ---------------- PTX helpers ----------------
__device__ __forceinline__ void cpa16(void* s, const void* g) {
    unsigned a = (unsigned)__cvta_generic_to_shared(s);
    asm volatile("cp.async.ca.shared.global [%0], [%1], 16;" :: "r"(a), "l"(g));
}
__device__ __forceinline__ void cp_commit() { asm volatile("cp.async.commit_group;"); }
__device__ __forceinline__ void cp_wait0()  { asm volatile("cp.async.wait_group 0;"); }
__device__ __forceinline__ void cp_wait1()  { asm volatile("cp.async.wait_group 1;"); }
__device__ __forceinline__ void ldm_x4(unsigned* r, const void* p) {
    unsigned a = (unsigned)__cvta_generic_to_shared(p);
    asm volatile("ldmatrix.sync.aligned.m8n8.x4.shared.b16 {%0,%1,%2,%3}, [%4];"
        : "=r"(r[0]), "=r"(r[1]), "=r"(r[2]), "=r"(r[3]) : "r"(a));
}
__device__ __forceinline__ void ldm_x4_t(unsigned* r, const void* p) {
    unsigned a = (unsigned)__cvta_generic_to_shared(p);
    asm volatile("ldmatrix.sync.aligned.m8n8.x4.trans.shared.b16 {%0,%1,%2,%3}, [%4];"
        : "=r"(r[0]), "=r"(r[1]), "=r"(r[2]), "=r"(r[3]) : "r"(a));
}
__device__ __forceinline__ void mmabf(float* c, const unsigned* a, const unsigned* b) {
    asm volatile(
        "mma.sync.aligned.m16n8k16.row.col.f32.bf16.bf16.f32 "
        "{%0,%1,%2,%3}, {%4,%5,%6,%7}, {%8,%9}, {%0,%1,%2,%3};"
        : "+f"(c[0]), "+f"(c[1]), "+f"(c[2]), "+f"(c[3])
        : "r"(a[0]), "r"(a[1]), "r"(a[2]), "r"(a[3]), "r"(b[0]), "r"(b[1]));
}
__device__ __forceinline__ unsigned packbf(float x, float y) {
    bf162 v = __float22bfloat162_rn(make_float2(x, y));
    return *(unsigned*)&v;
}

// ---------------- conversions / repacks ----------------
__global__ void f2bf_kernel(const float* __restrict__ s, bf16* __restrict__ d, int n) {
    int i = blockIdx.x * blockDim.x + threadIdx.x;
    int stride = gridDim.x * blockDim.x;
    for (; i < n; i += stride) d[i] = __float2bfloat16(s[i]);
}
// W layout [L][4][512][512] -> out [L][512][nmat*512] (concat mats mat0..mat0+nmat-1 along n)
__global__ void pack_w(const float* __restrict__ W, bf16* __restrict__ out,
                       int nmat, int mat0, int total) {
    int i = blockIdx.x * blockDim.x + threadIdx.x;
    int stride = gridDim.x * blockDim.x;
    int perL = D_MODEL * nmat * D_MODEL;
    for (; i < total; i += stride) {
        int l = i / perL, rem = i % perL;
        int k = rem / (nmat * D_MODEL), j = rem % (nmat * D_MODEL);
        int m = mat0 + (j >> 9), c = j & 511;
        out[i] = __float2bfloat16(W[(((size_t)l * 4 + m) * D_MODEL + k) * D_MODEL + c]);
    }
}
__global__ void pack_b(const float* __restrict__ B, float* __restrict__ out,
                       int nmat, int mat0, int total) {
    int i = blockIdx.x * blockDim.x + threadIdx.x;
    if (i >= total) return;
    int perL = nmat * D_MODEL;
    int l = i / perL, j = i % perL;
    int m = mat0 + (j >> 9), c = j & 511;
    out[i] = B[((size_t)l * 4 + m) * D_MODEL + c];
}

// ---------------- positional encoding (fp64 to match numpy) ----------------
__global__ void pe_kernel() {
    int i = blockIdx.x * blockDim.x + threadIdx.x;
    if (i >= LT * D_MODEL) return;
    int t = i / D_MODEL, d = i % D_MODEL;
    int e = d & ~1;
    double div = exp(-(double)e * (log(10000.0) / (double)D_MODEL));
    double ang = (double)t * div;
    g_pe[i] = (float)((d & 1) ? cos(ang) : sin(ang));
}

// ---------------- embedding + PE ----------------
__global__ void embed_kernel(const int* __restrict__ ids, const float* __restrict__ emb) {
    int i = blockIdx.x * blockDim.x + threadIdx.x;
    if (i >= MT * D_MODEL) return;
    int row = i / D_MODEL, d = i % D_MODEL;
    int b = row / LT, t = row % LT;
    int tok = ids[b * LFULL + t];
    g_x[i] = emb[tok * D_MODEL + d] * 22.62741699796952f + g_pe[t * D_MODEL + d];
}

// ---------------- layernorm (ddof=1, denom = std + eps), bf16 out ----------------
__global__ void ln_kernel(const float* __restrict__ x, bf16* __restrict__ y,
                          const float* __restrict__ ga, const float* __restrict__ gb) {
    int row = blockIdx.x;
    const float* xr = x + (size_t)row * D_MODEL;
    bf16*        yr = y + (size_t)row * D_MODEL;
    int t = threadIdx.x;  // 128 threads
    float v[4], s = 0.f, s2 = 0.f;
#pragma unroll
    for (int j = 0; j < 4; j++) {
        v[j] = xr[t + j * 128];
        s += v[j]; s2 += v[j] * v[j];
    }
    __shared__ float red[2][4];
#pragma unroll
    for (int o = 16; o > 0; o >>= 1) {
        s  += __shfl_down_sync(0xffffffffu, s,  o);
        s2 += __shfl_down_sync(0xffffffffu, s2, o);
    }
    if ((t & 31) == 0) { red[0][t >> 5] = s; red[1][t >> 5] = s2; }
    __syncthreads();
    if (t == 0) {
        float S1 = red[0][0] + red[0][1] + red[0][2] + red[0][3];
        float S2 = red[1][0] + red[1][1] + red[1][2] + red[1][3];
        float mean = S1 / 512.0f;
        float var  = fmaxf(0.f, S2 - 512.0f * mean * mean) / 511.0f;
        red[0][0] = mean;
        red[1][0] = 1.0f / (sqrtf(var) + 1e-6f);
    }
    __syncthreads();
    float mean = red[0][0], inv = red[1][0];
#pragma unroll
    for (int j = 0; j < 4; j++) {
        int c = t + j * 128;
        yr[c] = __float2bfloat16(ga[c] * (v[j] - mean) * inv + gb[c]);
    }
}

// =====================================================================
// bf16 tensor-core GEMM: C = A(MxK,row) @ W(KxN,row) + bias [+res][relu]
// BM=128 BN=128 BK=32, 256 threads, 8 warps (2m x 4n), warp tile 64x32.
// A fragments via ldmatrix.x4, B via ldmatrix.x4.trans.
// =====================================================================
__global__ void __launch_bounds__(256) gemm_bf(
        const bf16* __restrict__ A, const bf16* __restrict__ W,
        const float* __restrict__ bias, const float* __restrict__ res,
        bf16* __restrict__ Cb, float* __restrict__ Cf,
        int M, int N, int K, int relu) {
    __shared__ __align__(16) bf16 As[2][128][40];
    __shared__ __align__(16) bf16 Bs[2][32][136];
    int row0 = blockIdx.y * 128, col0 = blockIdx.x * 128;
    int tid = threadIdx.x;
    int wid = tid >> 5, lane = tid & 31;
    int g = lane >> 2, t = lane & 3;
    int wm = wid & 1, wn = wid >> 1;
    int tl = lane >> 3, rr = lane & 7;

    float c[4][4][4];
#pragma unroll
    for (int i = 0; i < 4; i++)
#pragma unroll
        for (int j = 0; j < 4; j++)
#pragma unroll
            for (int r = 0; r < 4; r++) c[i][j][r] = 0.f;

    int nIter = K >> 5;
    {
#pragma unroll
        for (int i = 0; i < 2; i++) {
            int idx = tid + i * 256;
            int m = idx >> 2, kq = (idx & 3) * 8;
            cpa16(&As[0][m][kq], A + (size_t)(row0 + m) * K + kq);
        }
#pragma unroll
        for (int i = 0; i < 2; i++) {
            int idx = tid + i * 256;
            int k = idx >> 4, nq = (idx & 15) * 8;
            cpa16(&Bs[0][k][nq], W + (size_t)k * N + col0 + nq);
        }
        cp_commit();
    }
    int s = 0;
    for (int it = 0; it < nIter; ++it) {
        if (it + 1 < nIter) {
            int k0g = (it + 1) << 5;
#pragma unroll
            for (int i = 0; i < 2; i++) {
                int idx = tid + i * 256;
                int m = idx >> 2, kq = (idx & 3) * 8;
                cpa16(&As[s ^ 1][m][kq], A + (size_t)(row0 + m) * K + k0g + kq);
            }
#pragma unroll
            for (int i = 0; i < 2; i++) {
                int idx = tid + i * 256;
                int k = idx >> 4, nq = (idx & 15) * 8;
                cpa16(&Bs[s ^ 1][k][nq], W + (size_t)(k0g + k) * N + col0 + nq);
            }
            cp_commit();
            cp_wait1();
        } else {
            cp_wait0();
        }
        __syncthreads();
#pragma unroll
        for (int ks = 0; ks < 2; ks++) {
            int k0 = ks * 16;
            unsigned af[4][4];
#pragma unroll
            for (int mt = 0; mt < 4; mt++)
                ldm_x4(af[mt], &As[s][wm * 64 + mt * 16 + (lane & 15)][k0 + (lane >> 4) * 8]);
            unsigned bf[4][2];
#pragma unroll
            for (int nb = 0; nb < 2; nb++) {
                unsigned r4[4];
                ldm_x4_t(r4, &Bs[s][k0 + (tl & 1) * 8 + rr][wn * 32 + nb * 16 + (tl >> 1) * 8]);
                bf[nb * 2 + 0][0] = r4[0]; bf[nb * 2 + 0][1] = r4[1];
                bf[nb * 2 + 1][0] = r4[2]; bf[nb * 2 + 1][1] = r4[3];
            }
#pragma unroll
            for (int mt = 0; mt < 4; mt++)
#pragma unroll
                for (int nt = 0; nt < 4; nt++) mmabf(c[mt][nt], af[mt], bf[nt]);
        }
        __syncthreads();
        s ^= 1;
    }
    // ---- epilogue ----
#pragma unroll
    for (int mt = 0; mt < 4; mt++) {
        int r = row0 + wm * 64 + mt * 16 + g;
#pragma unroll
        for (int nt = 0; nt < 4; nt++) {
            int cc = col0 + wn * 32 + nt * 8 + 2 * t;
            float b0 = bias[cc], b1 = bias[cc + 1];
            float v0 = c[mt][nt][0] + b0, v1 = c[mt][nt][1] + b1;
            float v2 = c[mt][nt][2] + b0, v3 = c[mt][nt][3] + b1;
            if (res) {
                v0 += res[(size_t)r * N + cc];       v1 += res[(size_t)r * N + cc + 1];
                v2 += res[(size_t)(r + 8) * N + cc]; v3 += res[(size_t)(r + 8) * N + cc + 1];
            }
            if (relu) {
                v0 = fmaxf(v0, 0.f); v1 = fmaxf(v1, 0.f);
                v2 = fmaxf(v2, 0.f); v3 = fmaxf(v3, 0.f);
            }
            if (Cf) {
                *(float2*)(Cf + (size_t)r * N + cc)       = make_float2(v0, v1);
                *(float2*)(Cf + (size_t)(r + 8) * N + cc) = make_float2(v2, v3);
            }
            if (Cb) {
                *(bf162*)(Cb + (size_t)r * N + cc)       = __float22bfloat162_rn(make_float2(v0, v1));
                *(bf162*)(Cb + (size_t)(r + 8) * N + cc) = __float22bfloat162_rn(make_float2(v2, v3));
            }
        }
    }
}

// =====================================================================
// Fused flash attention: O = softmax(mask(scale*Q.K^T)) @ V
// BM=128 rows/CTA, 8 warps x 16 rows. K/V chunks of 128 keys.
// fp32 online softmax, bf16 P, fp32 O accum. Matches reference -10000 mask.
// =====================================================================
template <int CAUSAL>
__global__ void __launch_bounds__(256, 1) flash_kernel(
        const bf16* __restrict__ Qp, int qStride,
        const bf16* __restrict__ Kp, const bf16* __restrict__ Vp, int kvStride,
        const int* __restrict__ mask, int maskStride,
        bf16* __restrict__ Op, int Lq, int Lk) {
    extern __shared__ char sm[];
    bf16 (*Qs)[72] = (bf16(*)[72])(sm);
    bf16 (*Ks)[72] = (bf16(*)[72])(sm + 18432);
    bf16 (*Vs)[72] = (bf16(*)[72])(sm + 36864);
    int* mS = (int*)(sm + 55296);

    int m0 = blockIdx.x * 128;
    int z = blockIdx.y, b = z / NHEAD, h = z % NHEAD;
    const bf16* Qb = Qp + (size_t)b * Lq * qStride + h * DK;
    const bf16* Kb = Kp + (size_t)b * Lk * kvStride + h * DK;
    const bf16* Vb = Vp + (size_t)b * Lk * kvStride + h * DK;
    bf16* Ob = Op + (size_t)b * Lq * D_MODEL + h * DK;
    const int* mrow = mask + (size_t)b * maskStride;

    int tid = threadIdx.x, w = tid >> 5, lane = tid & 31;
    int g = lane >> 2, t = lane & 3;
    int tl = lane >> 3, rr = lane & 7;
    const float scale = 0.125f;

    // ---- load Q tile (128 x 64) ----
#pragma unroll
    for (int i = 0; i < 4; i++) {
        int idx = tid + i * 256;
        int r = idx >> 3, cq = (idx & 7) * 8;
        cpa16(&Qs[r][cq], Qb + (size_t)(m0 + r) * qStride + cq);
    }
    cp_commit(); cp_wait0();
    __syncthreads();

    unsigned qf[4][4];
#pragma unroll
    for (int ks = 0; ks < 4; ks++)
        ldm_x4(qf[ks], &Qs[w * 16 + (lane & 15)][ks * 16 + (lane >> 4) * 8]);

    float o[8][4];
#pragma unroll
    for (int i = 0; i < 8; i++)
#pragma unroll
        for (int j = 0; j < 4; j++) o[i][j] = 0.f;
    float mrun[2] = {-1e30f, -1e30f}, lrun[2] = {0.f, 0.f};
    int rowg = m0 + w * 16 + g;

    int nChunks = CAUSAL ? (m0 / 128 + 1) : (Lk / 128);
    for (int ch = 0; ch < nChunks; ch++) {
        int n0 = ch * 128;
        __syncthreads();  // protect Ks/Vs reuse
#pragma unroll
        for (int i = 0; i < 4; i++) {
            int idx = tid + i * 256;
            int r = idx >> 3, cq = (idx & 7) * 8;
            cpa16(&Ks[r][cq], Kb + (size_t)(n0 + r) * kvStride + cq);
            cpa16(&Vs[r][cq], Vb + (size_t)(n0 + r) * kvStride + cq);
        }
        if (tid < 128) mS[tid] = mrow[n0 + tid];
        cp_commit(); cp_wait0();
        __syncthreads();

        // ---- S = scale * Q K^T  (per warp: 16 x 128) ----
        float s[16][4];
#pragma unroll
        for (int nt = 0; nt < 16; nt++)
#pragma unroll
            for (int j = 0; j < 4; j++) s[nt][j] = 0.f;
#pragma unroll
        for (int ks = 0; ks < 4; ks++) {
            int k0 = ks * 16;
#pragma unroll
            for (int nt = 0; nt < 16; nt++) {
                unsigned bfr[2];
                int nc = nt * 8 + g;
                bfr[0] = *(const unsigned*)&Ks[nc][k0 + 2 * t];
                bfr[1] = *(const unsigned*)&Ks[nc][k0 + 8 + 2 * t];
                mmabf(s[nt], qf[ks], bfr);
            }
        }
        // ---- scale + mask ----
#pragma unroll
        for (int nt = 0; nt < 16; nt++) {
            int cl = nt * 8 + 2 * t;
            int c0 = n0 + cl, c1 = c0 + 1;
            bool k0ok = mS[cl] != 0, k1ok = mS[cl + 1] != 0;
            bool v0 = k0ok && (!CAUSAL || c0 <= rowg);
            bool v1 = k1ok && (!CAUSAL || c1 <= rowg);
            bool v2 = k0ok && (!CAUSAL || c0 <= rowg + 8);
            bool v3 = k1ok && (!CAUSAL || c1 <= rowg + 8);
            s[nt][0] = v0 ? s[nt][0] * scale : -10000.0f;
            s[nt][1] = v1 ? s[nt][1] * scale : -10000.0f;
            s[nt][2] = v2 ? s[nt][2] * scale : -10000.0f;
            s[nt][3] = v3 ? s[nt][3] * scale : -10000.0f;
        }
        // ---- online softmax ----
        float mg0 = -1e30f, mg1 = -1e30f;
#pragma unroll
        for (int nt = 0; nt < 16; nt++) {
            mg0 = fmaxf(mg0, fmaxf(s[nt][0], s[nt][1]));
            mg1 = fmaxf(mg1, fmaxf(s[nt][2], s[nt][3]));
        }
#pragma unroll
        for (int off = 1; off < 4; off <<= 1) {
            mg0 = fmaxf(mg0, __shfl_xor_sync(0xffffffffu, mg0, off));
            mg1 = fmaxf(mg1, __shfl_xor_sync(0xffffffffu, mg1, off));
        }
        float mn0 = fmaxf(mrun[0], mg0), mn1 = fmaxf(mrun[1], mg1);
        float a0 = __expf(mrun[0] - mn0), a1 = __expf(mrun[1] - mn1);
        float sum0 = 0.f, sum1 = 0.f;
#pragma unroll
        for (int nt = 0; nt < 16; nt++) {
            s[nt][0] = __expf(s[nt][0] - mn0);
            s[nt][1] = __expf(s[nt][1] - mn0);
            s[nt][2] = __expf(s[nt][2] - mn1);
            s[nt][3] = __expf(s[nt][3] - mn1);
            sum0 += s[nt][0] + s[nt][1];
            sum1 += s[nt][2] + s[nt][3];
        }
#pragma unroll
        for (int off = 1; off < 4; off <<= 1) {
            sum0 += __shfl_xor_sync(0xffffffffu, sum0, off);
            sum1 += __shfl_xor_sync(0xffffffffu, sum1, off);
        }
        lrun[0] = lrun[0] * a0 + sum0;
        lrun[1] = lrun[1] * a1 + sum1;
        mrun[0] = mn0; mrun[1] = mn1;
#pragma unroll
        for (int ot = 0; ot < 8; ot++) {
            o[ot][0] *= a0; o[ot][1] *= a0;
            o[ot][2] *= a1; o[ot][3] *= a1;
        }
        // ---- O += P @ V ----
#pragma unroll
        for (int j = 0; j < 8; j++) {
            unsigned pa[4];
            pa[0] = packbf(s[2 * j][0],     s[2 * j][1]);
            pa[1] = packbf(s[2 * j][2],     s[2 * j][3]);
            pa[2] = packbf(s[2 * j + 1][0], s[2 * j + 1][1]);
            pa[3] = packbf(s[2 * j + 1][2], s[2 * j + 1][3]);
#pragma unroll
            for (int nb = 0; nb < 4; nb++) {
                unsigned r4[4];
                ldm_x4_t(r4, &Vs[j * 16 + (tl & 1) * 8 + rr][nb * 16 + (tl >> 1) * 8]);
                mmabf(o[nb * 2 + 0], pa, r4);
                mmabf(o[nb * 2 + 1], pa, r4 + 2);
            }
        }
    }
    // ---- finalize ----
    float inv0 = 1.0f / lrun[0], inv1 = 1.0f / lrun[1];
#pragma unroll
    for (int ot = 0; ot < 8; ot++) {
        int col = ot * 8 + 2 * t;
        *(bf162*)(Ob + (size_t)rowg * D_MODEL + col) =
            __float22bfloat162_rn(make_float2(o[ot][0] * inv0, o[ot][1] * inv0));
        *(bf162*)(Ob + (size_t)(rowg + 8) * D_MODEL + col) =
            __float22bfloat162_rn(make_float2(o[ot][2] * inv1, o[ot][3] * inv1));
    }
}

// ---------------- final log_softmax (warp per row, 512 cols) ----------------
__global__ void logsoftmax_kernel(const float* __restrict__ X, float* __restrict__ Out) {
    int warp = (blockIdx.x * blockDim.x + threadIdx.x) >> 5;
    int lane = threadIdx.x & 31;
    if (warp >= MT) return;
    const float* r = X + (size_t)warp * VOCAB;
    float v[16], mx = -1e30f;
#pragma unroll
    for (int j = 0; j < 16; j++) { v[j] = r[lane + j * 32]; mx = fmaxf(mx, v[j]); }
#pragma unroll
    for (int o = 16; o > 0; o >>= 1) mx = fmaxf(mx, __shfl_xor_sync(0xffffffffu, mx, o));
    float sum = 0.f;
#pragma unroll
    for (int j = 0; j < 16; j++) sum += expf(v[j] - mx);
#pragma unroll
    for (int o = 16; o > 0; o >>= 1) sum += __shfl_xor_sync(0xffffffffu, sum, o);
    float lse = mx + logf(sum);
    float* out = Out + (size_t)warp * VOCAB;
#pragma unroll
    for (int j = 0; j < 16; j++) out[lane + j * 32] = v[j] - lse;
}

// ---------------- host driver ----------------
template <typename T>
static T* symp(const void* s) {
    void* p = nullptr;
    cudaGetSymbolAddress(&p, s);
    return (T*)p;
}

extern "C" void kernel_launch(void* const* d_in, const int* in_sizes, int n_in,
                              void* d_out, int out_size) {
    const int*   ids    = (const int*)d_in[0];
    const int*   attm   = (const int*)d_in[1];
    const float* src    = (const float*)d_in[2];
    const int*   srcm   = (const int*)d_in[3];
    const float* emb    = (const float*)d_in[4];
    const float* sa_W   = (const float*)d_in[5];
    const float* sa_b   = (const float*)d_in[6];
    const float* ca_W   = (const float*)d_in[7];
    const float* ca_b   = (const float*)d_in[8];
    const float* ln_a   = (const float*)d_in[9];
    const float* ln_b   = (const float*)d_in[10];
    const float* ffn_w1 = (const float*)d_in[11];
    const float* ffn_b1 = (const float*)d_in[12];
    const float* ffn_w2 = (const float*)d_in[13];
    const float* ffn_b2 = (const float*)d_in[14];
    const float* fin_a  = (const float*)d_in[15];
    const float* fin_b  = (const float*)d_in[16];
    const float* lm_W   = (const float*)d_in[17];
    const float* lm_b   = (const float*)d_in[18];
    float* out = (float*)d_out;

    float* x    = symp<float>(g_x);
    float* lg   = symp<float>(g_lg);
    bf16* hb    = symp<bf16>(g_hb);
    bf16* qb    = symp<bf16>(g_qb);
    bf16* qkv   = symp<bf16>(g_qkv);
    bf16* kv    = symp<bf16>(g_kv);
    bf16* ab    = symp<bf16>(g_ab);
    bf16* fb    = symp<bf16>(g_fb);
    bf16* wsa   = symp<bf16>(g_wsa);
    bf16* wca   = symp<bf16>(g_wca);
    bf16* wqkv  = symp<bf16>(g_wqkv);
    bf16* wkv   = symp<bf16>(g_wkv);
    float* bqkv = symp<float>(g_bqkv);
    float* bkv  = symp<float>(g_bkv);
    bf16* w1    = symp<bf16>(g_w1);
    bf16* w2    = symp<bf16>(g_w2);
    bf16* wlm   = symp<bf16>(g_wlm);
    bf16* srcb  = symp<bf16>(g_srcb);

    static bool attrSet = false;
    const int flashSmem = 55296 + 512;
    if (!attrSet) {
        cudaFuncSetAttribute(flash_kernel<1>, cudaFuncAttributeMaxDynamicSharedMemorySize, flashSmem);
        cudaFuncSetAttribute(flash_kernel<0>, cudaFuncAttributeMaxDynamicSharedMemorySize, flashSmem);
        attrSet = true;
    }

    // ---- one-time-per-launch conversions / repacks ----
    {
        int nW = NLAYER * 4 * D_MODEL * D_MODEL;
        int nF = NLAYER * D_MODEL * D_FF;
        f2bf_kernel<<<(nW + 1023) / 1024, 256>>>(sa_W, wsa, nW);
        f2bf_kernel<<<(nW + 1023) / 1024, 256>>>(ca_W, wca, nW);
        f2bf_kernel<<<(nF + 1023) / 1024, 256>>>(ffn_w1, w1, nF);
        f2bf_kernel<<<(nF + 1023) / 1024, 256>>>(ffn_w2, w2, nF);
        f2bf_kernel<<<(D_MODEL * VOCAB + 1023) / 1024, 256>>>(lm_W, wlm, D_MODEL * VOCAB);
        f2bf_kernel<<<(MS * D_MODEL + 1023) / 1024, 256>>>(src, srcb, MS * D_MODEL);
        int tq = NLAYER * D_MODEL * 3 * D_MODEL;
        int tk = NLAYER * D_MODEL * 2 * D_MODEL;
        pack_w<<<(tq + 1023) / 1024, 256>>>(sa_W, wqkv, 3, 0, tq);
        pack_w<<<(tk + 1023) / 1024, 256>>>(ca_W, wkv, 2, 1, tk);
        pack_b<<<(NLAYER * 3 * D_MODEL + 255) / 256, 256>>>(sa_b, bqkv, 3, 0, NLAYER * 3 * D_MODEL);
        pack_b<<<(NLAYER * 2 * D_MODEL + 255) / 256, 256>>>(ca_b, bkv, 2, 1, NLAYER * 2 * D_MODEL);
    }

    pe_kernel<<<(LT * D_MODEL + 255) / 256, 256>>>();
    embed_kernel<<<(MT * D_MODEL + 255) / 256, 256>>>(ids, emb);

    dim3 gProjT(D_MODEL / 128, MT / 128);
    dim3 gQKV(3 * D_MODEL / 128, MT / 128);
    dim3 gKV(2 * D_MODEL / 128, MS / 128);
    dim3 gFfn1(D_FF / 128, MT / 128);
    dim3 gFfn2(D_MODEL / 128, MT / 128);
    dim3 gFlash(LT / 128, BATCH * NHEAD);

    for (int i = 0; i < NLAYER; i++) {
        const bf16*  saW = wsa + (size_t)i * 4 * D_MODEL * D_MODEL;
        const float* sab = sa_b + (size_t)i * 4 * D_MODEL;
        const bf16*  caW = wca + (size_t)i * 4 * D_MODEL * D_MODEL;
        const float* cab = ca_b + (size_t)i * 4 * D_MODEL;
        const float* lnA = ln_a + (size_t)i * 3 * D_MODEL;
        const float* lnB = ln_b + (size_t)i * 3 * D_MODEL;

        // ---- self-attention ----
        ln_kernel<<<MT, 128>>>(x, hb, lnA + 0 * D_MODEL, lnB + 0 * D_MODEL);
        gemm_bf<<<gQKV, 256>>>(hb, wqkv + (size_t)i * D_MODEL * 3 * D_MODEL,
                               bqkv + (size_t)i * 3 * D_MODEL, nullptr, qkv, nullptr,
                               MT, 3 * D_MODEL, D_MODEL, 0);
        flash_kernel<1><<<gFlash, 256, flashSmem>>>(
            qkv, 3 * D_MODEL, qkv + D_MODEL, qkv + 2 * D_MODEL, 3 * D_MODEL,
            attm, LFULL, ab, LT, LT);
        gemm_bf<<<gProjT, 256>>>(ab, saW + 3 * D_MODEL * D_MODEL, sab + 3 * D_MODEL,
                                 x, nullptr, x, MT, D_MODEL, D_MODEL, 0);

        // ---- cross-attention ----
        ln_kernel<<<MT, 128>>>(x, hb, lnA + 1 * D_MODEL, lnB + 1 * D_MODEL);
        gemm_bf<<<gProjT, 256>>>(hb, caW + 0 * D_MODEL * D_MODEL, cab + 0 * D_MODEL,
                                 nullptr, qb, nullptr, MT, D_MODEL, D_MODEL, 0);
        gemm_bf<<<gKV, 256>>>(srcb, wkv + (size_t)i * D_MODEL * 2 * D_MODEL,
                              bkv + (size_t)i * 2 * D_MODEL, nullptr, kv, nullptr,
                              MS, 2 * D_MODEL, D_MODEL, 0);
        flash_kernel<0><<<gFlash, 256, flashSmem>>>(
            qb, D_MODEL, kv, kv + D_MODEL, 2 * D_MODEL,
            srcm, SRC_S, ab, LT, SRC_S);
        gemm_bf<<<gProjT, 256>>>(ab, caW + 3 * D_MODEL * D_MODEL, cab + 3 * D_MODEL,
                                 x, nullptr, x, MT, D_MODEL, D_MODEL, 0);

        // ---- FFN ----
        ln_kernel<<<MT, 128>>>(x, hb, lnA + 2 * D_MODEL, lnB + 2 * D_MODEL);
        gemm_bf<<<gFfn1, 256>>>(hb, w1 + (size_t)i * D_MODEL * D_FF,
                                ffn_b1 + (size_t)i * D_FF, nullptr, fb, nullptr,
                                MT, D_FF, D_MODEL, 1);
        gemm_bf<<<gFfn2, 256>>>(fb, w2 + (size_t)i * D_FF * D_MODEL,
                                ffn_b2 + (size_t)i * D_MODEL, x, nullptr, x,
                                MT, D_MODEL, D_FF, 0);
    }

    ln_kernel<<<MT, 128>>>(x, hb, fin_a, fin_b);
    gemm_bf<<<dim3(VOCAB / 128, MT / 128), 256>>>(hb, wlm, lm_b, nullptr, nullptr, lg,
                                                  MT, VOCAB, D_MODEL, 0);
    logsoftmax_kernel<<<(MT * 32 + 255) / 256, 256>>>(lg, out);
}

// round 8
// speedup vs baseline: 5.9671x; 1.0920x over previous
#include <cuda_runtime.h>
#include <cuda_bf16.h>
#include <math.h>

// ---------------- problem constants ----------------
#define D_MODEL 512
#define D_FF    2048
#define NHEAD   8
#define DK      64
#define NLAYER  4
#define VOCAB   512
#define BATCH   16
#define LFULL   513
#define LT      512
#define SRC_S   256
#define MT      (BATCH*LT)
#define MS      (BATCH*SRC_S)

typedef __nv_bfloat16 bf16;
typedef __nv_bfloat162 bf162;

// ---------------- device scratch (static, no allocation) ----------------
__device__ float g_x  [MT*D_MODEL];                  // residual stream (fp32)
__device__ float g_pe [LT*D_MODEL];
__device__ float g_lg [MT*VOCAB];

__device__ bf16 g_hb [MT*D_MODEL];                   // ln output
__device__ bf16 g_qb [MT*D_MODEL];                   // cross-attn Q
__device__ bf16 g_qkv[MT*3*D_MODEL];                 // fused self QKV
__device__ bf16 g_kv [MS*2*D_MODEL];                 // fused cross KV
__device__ bf16 g_ab [MT*D_MODEL];                   // attention output
__device__ bf16 g_fb [MT*D_FF];                      // ffn intermediate
__device__ bf16 g_wsa[NLAYER*4*D_MODEL*D_MODEL];     // only mat3 used
__device__ bf16 g_wca[NLAYER*4*D_MODEL*D_MODEL];     // only mats 0,3 used
__device__ bf16 g_wqkv[NLAYER*D_MODEL*3*D_MODEL];    // packed self QKV weights
__device__ bf16 g_wkv [NLAYER*D_MODEL*2*D_MODEL];    // packed cross KV weights
__device__ float g_bqkv[NLAYER*3*D_MODEL];
__device__ float g_bkv [NLAYER*2*D_MODEL];
__device__ bf16 g_w1 [NLAYER*D_MODEL*D_FF];
__device__ bf16 g_w2 [NLAYER*D_FF*D_MODEL];
__device__ bf16 g_wlm[D_MODEL*VOCAB];
__device__ bf16 g_srcb[MS*D_MODEL];

// ---------------- PTX helpers ----------------
__device__ __forceinline__ void cpa16(void* s, const void* g) {
    unsigned a = (unsigned)__cvta_generic_to_shared(s);
    asm volatile("cp.async.ca.shared.global [%0], [%1], 16;" :: "r"(a), "l"(g));
}
__device__ __forceinline__ void cp_commit() { asm volatile("cp.async.commit_group;"); }
__device__ __forceinline__ void cp_wait0()  { asm volatile("cp.async.wait_group 0;"); }
__device__ __forceinline__ void cp_wait2()  { asm volatile("cp.async.wait_group 2;"); }
__device__ __forceinline__ void ldm_x4(unsigned* r, const void* p) {
    unsigned a = (unsigned)__cvta_generic_to_shared(p);
    asm volatile("ldmatrix.sync.aligned.m8n8.x4.shared.b16 {%0,%1,%2,%3}, [%4];"
        : "=r"(r[0]), "=r"(r[1]), "=r"(r[2]), "=r"(r[3]) : "r"(a));
}
__device__ __forceinline__ void ldm_x4_t(unsigned* r, const void* p) {
    unsigned a = (unsigned)__cvta_generic_to_shared(p);
    asm volatile("ldmatrix.sync.aligned.m8n8.x4.trans.shared.b16 {%0,%1,%2,%3}, [%4];"
        : "=r"(r[0]), "=r"(r[1]), "=r"(r[2]), "=r"(r[3]) : "r"(a));
}
__device__ __forceinline__ void mmabf(float* c, const unsigned* a, const unsigned* b) {
    asm volatile(
        "mma.sync.aligned.m16n8k16.row.col.f32.bf16.bf16.f32 "
        "{%0,%1,%2,%3}, {%4,%5,%6,%7}, {%8,%9}, {%0,%1,%2,%3};"
        : "+f"(c[0]), "+f"(c[1]), "+f"(c[2]), "+f"(c[3])
        : "r"(a[0]), "r"(a[1]), "r"(a[2]), "r"(a[3]), "r"(b[0]), "r"(b[1]));
}
__device__ __forceinline__ unsigned packbf(float x, float y) {
    bf162 v = __float22bfloat162_rn(make_float2(x, y));
    return *(unsigned*)&v;
}

// ---------------- conversions / repacks ----------------
__global__ void f2bf_kernel(const float* __restrict__ s, bf16* __restrict__ d, int n) {
    int i = blockIdx.x * blockDim.x + threadIdx.x;
    int stride = gridDim.x * blockDim.x;
    for (; i < n; i += stride) d[i] = __float2bfloat16(s[i]);
}
// convert only matrix `mat` of a [L][4][512][512] tensor (into same offsets)
__global__ void conv_mat(const float* __restrict__ W, bf16* __restrict__ out, int mat) {
    int i = blockIdx.x * blockDim.x + threadIdx.x;
    int stride = gridDim.x * blockDim.x;
    int total = NLAYER * D_MODEL * D_MODEL;
    for (; i < total; i += stride) {
        int l = i / (D_MODEL * D_MODEL), r = i % (D_MODEL * D_MODEL);
        size_t off = ((size_t)l * 4 + mat) * D_MODEL * D_MODEL + r;
        out[off] = __float2bfloat16(W[off]);
    }
}
// W layout [L][4][512][512] -> out [L][512][nmat*512]
__global__ void pack_w(const float* __restrict__ W, bf16* __restrict__ out,
                       int nmat, int mat0, int total) {
    int i = blockIdx.x * blockDim.x + threadIdx.x;
    int stride = gridDim.x * blockDim.x;
    int perL = D_MODEL * nmat * D_MODEL;
    for (; i < total; i += stride) {
        int l = i / perL, rem = i % perL;
        int k = rem / (nmat * D_MODEL), j = rem % (nmat * D_MODEL);
        int m = mat0 + (j >> 9), c = j & 511;
        out[i] = __float2bfloat16(W[(((size_t)l * 4 + m) * D_MODEL + k) * D_MODEL + c]);
    }
}
__global__ void pack_b(const float* __restrict__ B, float* __restrict__ out,
                       int nmat, int mat0, int total) {
    int i = blockIdx.x * blockDim.x + threadIdx.x;
    if (i >= total) return;
    int perL = nmat * D_MODEL;
    int l = i / perL, j = i % perL;
    int m = mat0 + (j >> 9), c = j & 511;
    out[i] = B[((size_t)l * 4 + m) * D_MODEL + c];
}

// ---------------- positional encoding (fp64 to match numpy) ----------------
__global__ void pe_kernel() {
    int i = blockIdx.x * blockDim.x + threadIdx.x;
    if (i >= LT * D_MODEL) return;
    int t = i / D_MODEL, d = i % D_MODEL;
    int e = d & ~1;
    double div = exp(-(double)e * (log(10000.0) / (double)D_MODEL));
    double ang = (double)t * div;
    g_pe[i] = (float)((d & 1) ? cos(ang) : sin(ang));
}

// ---------------- embedding + PE ----------------
__global__ void embed_kernel(const int* __restrict__ ids, const float* __restrict__ emb) {
    int i = blockIdx.x * blockDim.x + threadIdx.x;
    if (i >= MT * D_MODEL) return;
    int row = i / D_MODEL, d = i % D_MODEL;
    int b = row / LT, t = row % LT;
    int tok = ids[b * LFULL + t];
    g_x[i] = emb[tok * D_MODEL + d] * 22.62741699796952f + g_pe[t * D_MODEL + d];
}

// ---------------- layernorm: warp per row (ddof=1, denom = std + eps) ----------------
__global__ void ln_kernel(const float* __restrict__ x, bf16* __restrict__ y,
                          const float* __restrict__ ga, const float* __restrict__ gb) {
    int w = threadIdx.x >> 5, lane = threadIdx.x & 31;
    int row = blockIdx.x * 8 + w;
    const float4* xr = (const float4*)(x + (size_t)row * D_MODEL);
    const float4* gav = (const float4*)ga;
    const float4* gbv = (const float4*)gb;
    bf16* yr = y + (size_t)row * D_MODEL;
    float4 v[4];
    float s = 0.f, s2 = 0.f;
#pragma unroll
    for (int j = 0; j < 4; j++) {
        v[j] = xr[lane + j * 32];
        s  += v[j].x + v[j].y + v[j].z + v[j].w;
        s2 += v[j].x * v[j].x + v[j].y * v[j].y + v[j].z * v[j].z + v[j].w * v[j].w;
    }
#pragma unroll
    for (int o = 16; o > 0; o >>= 1) {
        s  += __shfl_xor_sync(0xffffffffu, s,  o);
        s2 += __shfl_xor_sync(0xffffffffu, s2, o);
    }
    float mean = s / 512.0f;
    float var  = fmaxf(0.f, s2 - 512.0f * mean * mean) / 511.0f;
    float inv  = 1.0f / (sqrtf(var) + 1e-6f);
#pragma unroll
    for (int j = 0; j < 4; j++) {
        int c4 = lane + j * 32;
        float4 a = gav[c4], b = gbv[c4];
        float r0 = a.x * (v[j].x - mean) * inv + b.x;
        float r1 = a.y * (v[j].y - mean) * inv + b.y;
        float r2 = a.z * (v[j].z - mean) * inv + b.z;
        float r3 = a.w * (v[j].w - mean) * inv + b.w;
        *(bf162*)(yr + c4 * 4)     = __float22bfloat162_rn(make_float2(r0, r1));
        *(bf162*)(yr + c4 * 4 + 2) = __float22bfloat162_rn(make_float2(r2, r3));
    }
}

// =====================================================================
// bf16 tensor-core GEMM: C = A(MxK,row) @ W(KxN,row) + bias [+res][relu]
// BM=128 BN=256 BK=32, 3-stage cp.async ring, 256 threads,
// 8 warps (2m x 4n), warp tile 64x64. A via ldmatrix.x4, B via x4.trans.
// =====================================================================
#define ASZ 10240   // 128 x 40 bf16
#define BSZ 16896   // 32 x 264 bf16
#define GEMM_SMEM (3*(ASZ+BSZ))

__global__ void __launch_bounds__(256, 1) gemm_bf(
        const bf16* __restrict__ A, const bf16* __restrict__ W,
        const float* __restrict__ bias, const float* __restrict__ res,
        bf16* __restrict__ Cb, float* __restrict__ Cf,
        int M, int N, int K, int relu) {
    extern __shared__ char smg[];
    int row0 = blockIdx.y * 128, col0 = blockIdx.x * 256;
    int tid = threadIdx.x;
    int wid = tid >> 5, lane = tid & 31;
    int g = lane >> 2, t = lane & 3;
    int wm = wid & 1, wn = wid >> 1;           // warp tile origin (wm*64, wn*64)
    int tl = lane >> 3, rr = lane & 7;

    float c[4][8][4];
#pragma unroll
    for (int i = 0; i < 4; i++)
#pragma unroll
        for (int j = 0; j < 8; j++)
#pragma unroll
            for (int r = 0; r < 4; r++) c[i][j][r] = 0.f;

    int nIter = K >> 5;
    // load helpers
    auto loadStage = [&](int st, int k0g) {
        bf16 (*As)[40]  = (bf16(*)[40])(smg + st * ASZ);
        bf16 (*Bs)[264] = (bf16(*)[264])(smg + 3 * ASZ + st * BSZ);
#pragma unroll
        for (int i = 0; i < 2; i++) {
            int idx = tid + i * 256;
            int m = idx >> 2, kq = (idx & 3) * 8;
            cpa16(&As[m][kq], A + (size_t)(row0 + m) * K + k0g + kq);
        }
#pragma unroll
        for (int i = 0; i < 4; i++) {
            int idx = tid + i * 256;
            int k = idx >> 5, nq = (idx & 31) * 8;
            cpa16(&Bs[k][nq], W + (size_t)(k0g + k) * N + col0 + nq);
        }
    };
    // prologue: stages 0..2
#pragma unroll
    for (int p = 0; p < 3; p++) {
        if (p < nIter) loadStage(p, p << 5);
        cp_commit();
    }
    for (int it = 0; it < nIter; ++it) {
        int st = it % 3;
        bf16 (*As)[40]  = (bf16(*)[40])(smg + st * ASZ);
        bf16 (*Bs)[264] = (bf16(*)[264])(smg + 3 * ASZ + st * BSZ);
        cp_wait2();
        __syncthreads();
#pragma unroll
        for (int ks = 0; ks < 2; ks++) {
            int k0 = ks * 16;
            unsigned af[4][4];
#pragma unroll
            for (int mt = 0; mt < 4; mt++)
                ldm_x4(af[mt], &As[wm * 64 + mt * 16 + (lane & 15)][k0 + (lane >> 4) * 8]);
            unsigned bf[8][2];
#pragma unroll
            for (int nb = 0; nb < 4; nb++) {
                unsigned r4[4];
                ldm_x4_t(r4, &Bs[k0 + (tl & 1) * 8 + rr][wn * 64 + nb * 16 + (tl >> 1) * 8]);
                bf[nb * 2 + 0][0] = r4[0]; bf[nb * 2 + 0][1] = r4[1];
                bf[nb * 2 + 1][0] = r4[2]; bf[nb * 2 + 1][1] = r4[3];
            }
#pragma unroll
            for (int mt = 0; mt < 4; mt++)
#pragma unroll
                for (int nt = 0; nt < 8; nt++) mmabf(c[mt][nt], af[mt], bf[nt]);
        }
        __syncthreads();
        int nx = it + 3;
        if (nx < nIter) loadStage(nx % 3, nx << 5);
        cp_commit();
    }
    // ---- epilogue ----
#pragma unroll
    for (int mt = 0; mt < 4; mt++) {
        int r = row0 + wm * 64 + mt * 16 + g;
#pragma unroll
        for (int nt = 0; nt < 8; nt++) {
            int cc = col0 + wn * 64 + nt * 8 + 2 * t;
            float b0 = bias[cc], b1 = bias[cc + 1];
            float v0 = c[mt][nt][0] + b0, v1 = c[mt][nt][1] + b1;
            float v2 = c[mt][nt][2] + b0, v3 = c[mt][nt][3] + b1;
            if (res) {
                v0 += res[(size_t)r * N + cc];       v1 += res[(size_t)r * N + cc + 1];
                v2 += res[(size_t)(r + 8) * N + cc]; v3 += res[(size_t)(r + 8) * N + cc + 1];
            }
            if (relu) {
                v0 = fmaxf(v0, 0.f); v1 = fmaxf(v1, 0.f);
                v2 = fmaxf(v2, 0.f); v3 = fmaxf(v3, 0.f);
            }
            if (Cf) {
                *(float2*)(Cf + (size_t)r * N + cc)       = make_float2(v0, v1);
                *(float2*)(Cf + (size_t)(r + 8) * N + cc) = make_float2(v2, v3);
            }
            if (Cb) {
                *(bf162*)(Cb + (size_t)r * N + cc)       = __float22bfloat162_rn(make_float2(v0, v1));
                *(bf162*)(Cb + (size_t)(r + 8) * N + cc) = __float22bfloat162_rn(make_float2(v2, v3));
            }
        }
    }
}

// =====================================================================
// Fused flash attention (unchanged from R6)
// =====================================================================
template <int CAUSAL>
__global__ void __launch_bounds__(256, 1) flash_kernel(
        const bf16* __restrict__ Qp, int qStride,
        const bf16* __restrict__ Kp, const bf16* __restrict__ Vp, int kvStride,
        const int* __restrict__ mask, int maskStride,
        bf16* __restrict__ Op, int Lq, int Lk) {
    extern __shared__ char sm[];
    bf16 (*Qs)[72] = (bf16(*)[72])(sm);
    bf16 (*Ks)[72] = (bf16(*)[72])(sm + 18432);
    bf16 (*Vs)[72] = (bf16(*)[72])(sm + 36864);
    int* mS = (int*)(sm + 55296);

    int m0 = blockIdx.x * 128;
    int z = blockIdx.y, b = z / NHEAD, h = z % NHEAD;
    const bf16* Qb = Qp + (size_t)b * Lq * qStride + h * DK;
    const bf16* Kb = Kp + (size_t)b * Lk * kvStride + h * DK;
    const bf16* Vb = Vp + (size_t)b * Lk * kvStride + h * DK;
    bf16* Ob = Op + (size_t)b * Lq * D_MODEL + h * DK;
    const int* mrow = mask + (size_t)b * maskStride;

    int tid = threadIdx.x, w = tid >> 5, lane = tid & 31;
    int g = lane >> 2, t = lane & 3;
    int tl = lane >> 3, rr = lane & 7;
    const float scale = 0.125f;

#pragma unroll
    for (int i = 0; i < 4; i++) {
        int idx = tid + i * 256;
        int r = idx >> 3, cq = (idx & 7) * 8;
        cpa16(&Qs[r][cq], Qb + (size_t)(m0 + r) * qStride + cq);
    }
    cp_commit(); cp_wait0();
    __syncthreads();

    unsigned qf[4][4];
#pragma unroll
    for (int ks = 0; ks < 4; ks++)
        ldm_x4(qf[ks], &Qs[w * 16 + (lane & 15)][ks * 16 + (lane >> 4) * 8]);

    float o[8][4];
#pragma unroll
    for (int i = 0; i < 8; i++)
#pragma unroll
        for (int j = 0; j < 4; j++) o[i][j] = 0.f;
    float mrun[2] = {-1e30f, -1e30f}, lrun[2] = {0.f, 0.f};
    int rowg = m0 + w * 16 + g;

    int nChunks = CAUSAL ? (m0 / 128 + 1) : (Lk / 128);
    for (int ch = 0; ch < nChunks; ch++) {
        int n0 = ch * 128;
        __syncthreads();
#pragma unroll
        for (int i = 0; i < 4; i++) {
            int idx = tid + i * 256;
            int r = idx >> 3, cq = (idx & 7) * 8;
            cpa16(&Ks[r][cq], Kb + (size_t)(n0 + r) * kvStride + cq);
            cpa16(&Vs[r][cq], Vb + (size_t)(n0 + r) * kvStride + cq);
        }
        if (tid < 128) mS[tid] = mrow[n0 + tid];
        cp_commit(); cp_wait0();
        __syncthreads();

        float s[16][4];
#pragma unroll
        for (int nt = 0; nt < 16; nt++)
#pragma unroll
            for (int j = 0; j < 4; j++) s[nt][j] = 0.f;
#pragma unroll
        for (int ks = 0; ks < 4; ks++) {
            int k0 = ks * 16;
#pragma unroll
            for (int nt = 0; nt < 16; nt++) {
                unsigned bfr[2];
                int nc = nt * 8 + g;
                bfr[0] = *(const unsigned*)&Ks[nc][k0 + 2 * t];
                bfr[1] = *(const unsigned*)&Ks[nc][k0 + 8 + 2 * t];
                mmabf(s[nt], qf[ks], bfr);
            }
        }
#pragma unroll
        for (int nt = 0; nt < 16; nt++) {
            int cl = nt * 8 + 2 * t;
            int c0 = n0 + cl, c1 = c0 + 1;
            bool k0ok = mS[cl] != 0, k1ok = mS[cl + 1] != 0;
            bool v0 = k0ok && (!CAUSAL || c0 <= rowg);
            bool v1 = k1ok && (!CAUSAL || c1 <= rowg);
            bool v2 = k0ok && (!CAUSAL || c0 <= rowg + 8);
            bool v3 = k1ok && (!CAUSAL || c1 <= rowg + 8);
            s[nt][0] = v0 ? s[nt][0] * scale : -10000.0f;
            s[nt][1] = v1 ? s[nt][1] * scale : -10000.0f;
            s[nt][2] = v2 ? s[nt][2] * scale : -10000.0f;
            s[nt][3] = v3 ? s[nt][3] * scale : -10000.0f;
        }
        float mg0 = -1e30f, mg1 = -1e30f;
#pragma unroll
        for (int nt = 0; nt < 16; nt++) {
            mg0 = fmaxf(mg0, fmaxf(s[nt][0], s[nt][1]));
            mg1 = fmaxf(mg1, fmaxf(s[nt][2], s[nt][3]));
        }
#pragma unroll
        for (int off = 1; off < 4; off <<= 1) {
            mg0 = fmaxf(mg0, __shfl_xor_sync(0xffffffffu, mg0, off));
            mg1 = fmaxf(mg1, __shfl_xor_sync(0xffffffffu, mg1, off));
        }
        float mn0 = fmaxf(mrun[0], mg0), mn1 = fmaxf(mrun[1], mg1);
        float a0 = __expf(mrun[0] - mn0), a1 = __expf(mrun[1] - mn1);
        float sum0 = 0.f, sum1 = 0.f;
#pragma unroll
        for (int nt = 0; nt < 16; nt++) {
            s[nt][0] = __expf(s[nt][0] - mn0);
            s[nt][1] = __expf(s[nt][1] - mn0);
            s[nt][2] = __expf(s[nt][2] - mn1);
            s[nt][3] = __expf(s[nt][3] - mn1);
            sum0 += s[nt][0] + s[nt][1];
            sum1 += s[nt][2] + s[nt][3];
        }
#pragma unroll
        for (int off = 1; off < 4; off <<= 1) {
            sum0 += __shfl_xor_sync(0xffffffffu, sum0, off);
            sum1 += __shfl_xor_sync(0xffffffffu, sum1, off);
        }
        lrun[0] = lrun[0] * a0 + sum0;
        lrun[1] = lrun[1] * a1 + sum1;
        mrun[0] = mn0; mrun[1] = mn1;
#pragma unroll
        for (int ot = 0; ot < 8; ot++) {
            o[ot][0] *= a0; o[ot][1] *= a0;
            o[ot][2] *= a1; o[ot][3] *= a1;
        }
#pragma unroll
        for (int j = 0; j < 8; j++) {
            unsigned pa[4];
            pa[0] = packbf(s[2 * j][0],     s[2 * j][1]);
            pa[1] = packbf(s[2 * j][2],     s[2 * j][3]);
            pa[2] = packbf(s[2 * j + 1][0], s[2 * j + 1][1]);
            pa[3] = packbf(s[2 * j + 1][2], s[2 * j + 1][3]);
#pragma unroll
            for (int nb = 0; nb < 4; nb++) {
                unsigned r4[4];
                ldm_x4_t(r4, &Vs[j * 16 + (tl & 1) * 8 + rr][nb * 16 + (tl >> 1) * 8]);
                mmabf(o[nb * 2 + 0], pa, r4);
                mmabf(o[nb * 2 + 1], pa, r4 + 2);
            }
        }
    }
    float inv0 = 1.0f / lrun[0], inv1 = 1.0f / lrun[1];
#pragma unroll
    for (int ot = 0; ot < 8; ot++) {
        int col = ot * 8 + 2 * t;
        *(bf162*)(Ob + (size_t)rowg * D_MODEL + col) =
            __float22bfloat162_rn(make_float2(o[ot][0] * inv0, o[ot][1] * inv0));
        *(bf162*)(Ob + (size_t)(rowg + 8) * D_MODEL + col) =
            __float22bfloat162_rn(make_float2(o[ot][2] * inv1, o[ot][3] * inv1));
    }
}

// ---------------- final log_softmax (warp per row, 512 cols) ----------------
__global__ void logsoftmax_kernel(const float* __restrict__ X, float* __restrict__ Out) {
    int warp = (blockIdx.x * blockDim.x + threadIdx.x) >> 5;
    int lane = threadIdx.x & 31;
    if (warp >= MT) return;
    const float* r = X + (size_t)warp * VOCAB;
    float v[16], mx = -1e30f;
#pragma unroll
    for (int j = 0; j < 16; j++) { v[j] = r[lane + j * 32]; mx = fmaxf(mx, v[j]); }
#pragma unroll
    for (int o = 16; o > 0; o >>= 1) mx = fmaxf(mx, __shfl_xor_sync(0xffffffffu, mx, o));
    float sum = 0.f;
#pragma unroll
    for (int j = 0; j < 16; j++) sum += expf(v[j] - mx);
#pragma unroll
    for (int o = 16; o > 0; o >>= 1) sum += __shfl_xor_sync(0xffffffffu, sum, o);
    float lse = mx + logf(sum);
    float* out = Out + (size_t)warp * VOCAB;
#pragma unroll
    for (int j = 0; j < 16; j++) out[lane + j * 32] = v[j] - lse;
}

// ---------------- host driver ----------------
template <typename T>
static T* symp(const void* s) {
    void* p = nullptr;
    cudaGetSymbolAddress(&p, s);
    return (T*)p;
}

extern "C" void kernel_launch(void* const* d_in, const int* in_sizes, int n_in,
                              void* d_out, int out_size) {
    const int*   ids    = (const int*)d_in[0];
    const int*   attm   = (const int*)d_in[1];
    const float* src    = (const float*)d_in[2];
    const int*   srcm   = (const int*)d_in[3];
    const float* emb    = (const float*)d_in[4];
    const float* sa_W   = (const float*)d_in[5];
    const float* sa_b   = (const float*)d_in[6];
    const float* ca_W   = (const float*)d_in[7];
    const float* ca_b   = (const float*)d_in[8];
    const float* ln_a   = (const float*)d_in[9];
    const float* ln_b   = (const float*)d_in[10];
    const float* ffn_w1 = (const float*)d_in[11];
    const float* ffn_b1 = (const float*)d_in[12];
    const float* ffn_w2 = (const float*)d_in[13];
    const float* ffn_b2 = (const float*)d_in[14];
    const float* fin_a  = (const float*)d_in[15];
    const float* fin_b  = (const float*)d_in[16];
    const float* lm_W   = (const float*)d_in[17];
    const float* lm_b   = (const float*)d_in[18];
    float* out = (float*)d_out;

    float* x    = symp<float>(g_x);
    float* lg   = symp<float>(g_lg);
    bf16* hb    = symp<bf16>(g_hb);
    bf16* qb    = symp<bf16>(g_qb);
    bf16* qkv   = symp<bf16>(g_qkv);
    bf16* kv    = symp<bf16>(g_kv);
    bf16* ab    = symp<bf16>(g_ab);
    bf16* fb    = symp<bf16>(g_fb);
    bf16* wsa   = symp<bf16>(g_wsa);
    bf16* wca   = symp<bf16>(g_wca);
    bf16* wqkv  = symp<bf16>(g_wqkv);
    bf16* wkv   = symp<bf16>(g_wkv);
    float* bqkv = symp<float>(g_bqkv);
    float* bkv  = symp<float>(g_bkv);
    bf16* w1    = symp<bf16>(g_w1);
    bf16* w2    = symp<bf16>(g_w2);
    bf16* wlm   = symp<bf16>(g_wlm);
    bf16* srcb  = symp<bf16>(g_srcb);

    static bool attrSet = false;
    const int flashSmem = 55296 + 512;
    if (!attrSet) {
        cudaFuncSetAttribute(flash_kernel<1>, cudaFuncAttributeMaxDynamicSharedMemorySize, flashSmem);
        cudaFuncSetAttribute(flash_kernel<0>, cudaFuncAttributeMaxDynamicSharedMemorySize, flashSmem);
        cudaFuncSetAttribute(gemm_bf, cudaFuncAttributeMaxDynamicSharedMemorySize, GEMM_SMEM);
        attrSet = true;
    }

    // ---- one-time-per-launch conversions / repacks ----
    {
        int nF = NLAYER * D_MODEL * D_FF;
        int nM = NLAYER * D_MODEL * D_MODEL;
        conv_mat<<<(nM + 1023) / 1024, 256>>>(sa_W, wsa, 3);
        conv_mat<<<(nM + 1023) / 1024, 256>>>(ca_W, wca, 0);
        conv_mat<<<(nM + 1023) / 1024, 256>>>(ca_W, wca, 3);
        f2bf_kernel<<<(nF + 1023) / 1024, 256>>>(ffn_w1, w1, nF);
        f2bf_kernel<<<(nF + 1023) / 1024, 256>>>(ffn_w2, w2, nF);
        f2bf_kernel<<<(D_MODEL * VOCAB + 1023) / 1024, 256>>>(lm_W, wlm, D_MODEL * VOCAB);
        f2bf_kernel<<<(MS * D_MODEL + 1023) / 1024, 256>>>(src, srcb, MS * D_MODEL);
        int tq = NLAYER * D_MODEL * 3 * D_MODEL;
        int tk = NLAYER * D_MODEL * 2 * D_MODEL;
        pack_w<<<(tq + 1023) / 1024, 256>>>(sa_W, wqkv, 3, 0, tq);
        pack_w<<<(tk + 1023) / 1024, 256>>>(ca_W, wkv, 2, 1, tk);
        pack_b<<<(NLAYER * 3 * D_MODEL + 255) / 256, 256>>>(sa_b, bqkv, 3, 0, NLAYER * 3 * D_MODEL);
        pack_b<<<(NLAYER * 2 * D_MODEL + 255) / 256, 256>>>(ca_b, bkv, 2, 1, NLAYER * 2 * D_MODEL);
    }

    pe_kernel<<<(LT * D_MODEL + 255) / 256, 256>>>();
    embed_kernel<<<(MT * D_MODEL + 255) / 256, 256>>>(ids, emb);

    dim3 gProjT(D_MODEL / 256, MT / 128);     // (2, 64)
    dim3 gQKV(3 * D_MODEL / 256, MT / 128);   // (6, 64)
    dim3 gKV(2 * D_MODEL / 256, MS / 128);    // (4, 32)
    dim3 gFfn1(D_FF / 256, MT / 128);         // (8, 64)
    dim3 gFfn2(D_MODEL / 256, MT / 128);      // (2, 64)
    dim3 gFlash(LT / 128, BATCH * NHEAD);
    const int lnGrid = MT / 8;

    for (int i = 0; i < NLAYER; i++) {
        const bf16*  saW = wsa + (size_t)i * 4 * D_MODEL * D_MODEL;
        const float* sab = sa_b + (size_t)i * 4 * D_MODEL;
        const bf16*  caW = wca + (size_t)i * 4 * D_MODEL * D_MODEL;
        const float* cab = ca_b + (size_t)i * 4 * D_MODEL;
        const float* lnA = ln_a + (size_t)i * 3 * D_MODEL;
        const float* lnB = ln_b + (size_t)i * 3 * D_MODEL;

        // ---- self-attention ----
        ln_kernel<<<lnGrid, 256>>>(x, hb, lnA + 0 * D_MODEL, lnB + 0 * D_MODEL);
        gemm_bf<<<gQKV, 256, GEMM_SMEM>>>(hb, wqkv + (size_t)i * D_MODEL * 3 * D_MODEL,
                               bqkv + (size_t)i * 3 * D_MODEL, nullptr, qkv, nullptr,
                               MT, 3 * D_MODEL, D_MODEL, 0);
        flash_kernel<1><<<gFlash, 256, flashSmem>>>(
            qkv, 3 * D_MODEL, qkv + D_MODEL, qkv + 2 * D_MODEL, 3 * D_MODEL,
            attm, LFULL, ab, LT, LT);
        gemm_bf<<<gProjT, 256, GEMM_SMEM>>>(ab, saW + 3 * D_MODEL * D_MODEL, sab + 3 * D_MODEL,
                                 x, nullptr, x, MT, D_MODEL, D_MODEL, 0);

        // ---- cross-attention ----
        ln_kernel<<<lnGrid, 256>>>(x, hb, lnA + 1 * D_MODEL, lnB + 1 * D_MODEL);
        gemm_bf<<<gProjT, 256, GEMM_SMEM>>>(hb, caW + 0 * D_MODEL * D_MODEL, cab + 0 * D_MODEL,
                                 nullptr, qb, nullptr, MT, D_MODEL, D_MODEL, 0);
        gemm_bf<<<gKV, 256, GEMM_SMEM>>>(srcb, wkv + (size_t)i * D_MODEL * 2 * D_MODEL,
                              bkv + (size_t)i * 2 * D_MODEL, nullptr, kv, nullptr,
                              MS, 2 * D_MODEL, D_MODEL, 0);
        flash_kernel<0><<<gFlash, 256, flashSmem>>>(
            qb, D_MODEL, kv, kv + D_MODEL, 2 * D_MODEL,
            srcm, SRC_S, ab, LT, SRC_S);
        gemm_bf<<<gProjT, 256, GEMM_SMEM>>>(ab, caW + 3 * D_MODEL * D_MODEL, cab + 3 * D_MODEL,
                                 x, nullptr, x, MT, D_MODEL, D_MODEL, 0);

        // ---- FFN ----
        ln_kernel<<<lnGrid, 256>>>(x, hb, lnA + 2 * D_MODEL, lnB + 2 * D_MODEL);
        gemm_bf<<<gFfn1, 256, GEMM_SMEM>>>(hb, w1 + (size_t)i * D_MODEL * D_FF,
                                ffn_b1 + (size_t)i * D_FF, nullptr, fb, nullptr,
                                MT, D_FF, D_MODEL, 1);
        gemm_bf<<<gFfn2, 256, GEMM_SMEM>>>(fb, w2 + (size_t)i * D_FF * D_MODEL,
                                ffn_b2 + (size_t)i * D_MODEL, x, nullptr, x,
                                MT, D_MODEL, D_FF, 0);
    }

    ln_kernel<<<lnGrid, 256>>>(x, hb, fin_a, fin_b);
    gemm_bf<<<dim3(VOCAB / 256, MT / 128), 256, GEMM_SMEM>>>(hb, wlm, lm_b, nullptr, nullptr, lg,
                                                  MT, VOCAB, D_MODEL, 0);
    logsoftmax_kernel<<<(MT * 32 + 255) / 256, 256>>>(lg, out);
}

// round 10
// speedup vs baseline: 6.2145x; 1.0415x over previous
#include <cuda_runtime.h>
#include <cuda_bf16.h>
#include <math.h>

// ---------------- problem constants ----------------
#define D_MODEL 512
#define D_FF    2048
#define NHEAD   8
#define DK      64
#define NLAYER  4
#define VOCAB   512
#define BATCH   16
#define LFULL   513
#define LT      512
#define SRC_S   256
#define MT      (BATCH*LT)
#define MS      (BATCH*SRC_S)

typedef __nv_bfloat16 bf16;
typedef __nv_bfloat162 bf162;

// ---------------- device scratch (static, no allocation) ----------------
__device__ float g_x  [MT*D_MODEL];                  // residual stream (fp32)
__device__ float g_pe [LT*D_MODEL];
__device__ float g_lg [MT*VOCAB];

__device__ bf16 g_hb [MT*D_MODEL];                   // ln output
__device__ bf16 g_qb [MT*D_MODEL];                   // cross-attn Q
__device__ bf16 g_qkv[MT*3*D_MODEL];                 // fused self QKV
__device__ bf16 g_kv [MS*2*D_MODEL];                 // fused cross KV
__device__ bf16 g_ab [MT*D_MODEL];                   // attention output
__device__ bf16 g_fb [MT*D_FF];                      // ffn intermediate
__device__ bf16 g_wsa[NLAYER*4*D_MODEL*D_MODEL];     // only mat3 used
__device__ bf16 g_wca[NLAYER*4*D_MODEL*D_MODEL];     // only mats 0,3 used
__device__ bf16 g_wqkv[NLAYER*D_MODEL*3*D_MODEL];    // packed self QKV weights
__device__ bf16 g_wkv [NLAYER*D_MODEL*2*D_MODEL];    // packed cross KV weights
__device__ float g_bqkv[NLAYER*3*D_MODEL];
__device__ float g_bkv [NLAYER*2*D_MODEL];
__device__ bf16 g_w1 [NLAYER*D_MODEL*D_FF];
__device__ bf16 g_w2 [NLAYER*D_FF*D_MODEL];
__device__ bf16 g_wlm[D_MODEL*VOCAB];
__device__ bf16 g_srcb[MS*D_MODEL];

// ---------------- PTX helpers ----------------
__device__ __forceinline__ void cpa16(void* s, const void* g) {
    unsigned a = (unsigned)__cvta_generic_to_shared(s);
    asm volatile("cp.async.ca.shared.global [%0], [%1], 16;" :: "r"(a), "l"(g));
}
__device__ __forceinline__ void cp_commit() { asm volatile("cp.async.commit_group;"); }
__device__ __forceinline__ void cp_wait0()  { asm volatile("cp.async.wait_group 0;"); }
__device__ __forceinline__ void cp_wait1()  { asm volatile("cp.async.wait_group 1;"); }
__device__ __forceinline__ void ldm_x4(unsigned* r, const void* p) {
    unsigned a = (unsigned)__cvta_generic_to_shared(p);
    asm volatile("ldmatrix.sync.aligned.m8n8.x4.shared.b16 {%0,%1,%2,%3}, [%4];"
        : "=r"(r[0]), "=r"(r[1]), "=r"(r[2]), "=r"(r[3]) : "r"(a));
}
__device__ __forceinline__ void ldm_x4_t(unsigned* r, const void* p) {
    unsigned a = (unsigned)__cvta_generic_to_shared(p);
    asm volatile("ldmatrix.sync.aligned.m8n8.x4.trans.shared.b16 {%0,%1,%2,%3}, [%4];"
        : "=r"(r[0]), "=r"(r[1]), "=r"(r[2]), "=r"(r[3]) : "r"(a));
}
__device__ __forceinline__ void mmabf(float* c, const unsigned* a, const unsigned* b) {
    asm volatile(
        "mma.sync.aligned.m16n8k16.row.col.f32.bf16.bf16.f32 "
        "{%0,%1,%2,%3}, {%4,%5,%6,%7}, {%8,%9}, {%0,%1,%2,%3};"
        : "+f"(c[0]), "+f"(c[1]), "+f"(c[2]), "+f"(c[3])
        : "r"(a[0]), "r"(a[1]), "r"(a[2]), "r"(a[3]), "r"(b[0]), "r"(b[1]));
}
__device__ __forceinline__ unsigned packbf(float x, float y) {
    bf162 v = __float22bfloat162_rn(make_float2(x, y));
    return *(unsigned*)&v;
}

// ---------------- conversions / repacks ----------------
__global__ void f2bf_kernel(const float* __restrict__ s, bf16* __restrict__ d, int n) {
    int i = blockIdx.x * blockDim.x + threadIdx.x;
    int stride = gridDim.x * blockDim.x;
    for (; i < n; i += stride) d[i] = __float2bfloat16(s[i]);
}
// convert only matrix `mat` of a [L][4][512][512] tensor (into same offsets)
__global__ void conv_mat(const float* __restrict__ W, bf16* __restrict__ out, int mat) {
    int i = blockIdx.x * blockDim.x + threadIdx.x;
    int stride = gridDim.x * blockDim.x;
    int total = NLAYER * D_MODEL * D_MODEL;
    for (; i < total; i += stride) {
        int l = i / (D_MODEL * D_MODEL), r = i % (D_MODEL * D_MODEL);
        size_t off = ((size_t)l * 4 + mat) * D_MODEL * D_MODEL + r;
        out[off] = __float2bfloat16(W[off]);
    }
}
// W layout [L][4][512][512] -> out [L][512][nmat*512]
__global__ void pack_w(const float* __restrict__ W, bf16* __restrict__ out,
                       int nmat, int mat0, int total) {
    int i = blockIdx.x * blockDim.x + threadIdx.x;
    int stride = gridDim.x * blockDim.x;
    int perL = D_MODEL * nmat * D_MODEL;
    for (; i < total; i += stride) {
        int l = i / perL, rem = i % perL;
        int k = rem / (nmat * D_MODEL), j = rem % (nmat * D_MODEL);
        int m = mat0 + (j >> 9), c = j & 511;
        out[i] = __float2bfloat16(W[(((size_t)l * 4 + m) * D_MODEL + k) * D_MODEL + c]);
    }
}
__global__ void pack_b(const float* __restrict__ B, float* __restrict__ out,
                       int nmat, int mat0, int total) {
    int i = blockIdx.x * blockDim.x + threadIdx.x;
    if (i >= total) return;
    int perL = nmat * D_MODEL;
    int l = i / perL, j = i % perL;
    int m = mat0 + (j >> 9), c = j & 511;
    out[i] = B[((size_t)l * 4 + m) * D_MODEL + c];
}

// ---------------- positional encoding (fp64 to match numpy) ----------------
__global__ void pe_kernel() {
    int i = blockIdx.x * blockDim.x + threadIdx.x;
    if (i >= LT * D_MODEL) return;
    int t = i / D_MODEL, d = i % D_MODEL;
    int e = d & ~1;
    double div = exp(-(double)e * (log(10000.0) / (double)D_MODEL));
    double ang = (double)t * div;
    g_pe[i] = (float)((d & 1) ? cos(ang) : sin(ang));
}

// ---------------- embedding + PE ----------------
__global__ void embed_kernel(const int* __restrict__ ids, const float* __restrict__ emb) {
    int i = blockIdx.x * blockDim.x + threadIdx.x;
    if (i >= MT * D_MODEL) return;
    int row = i / D_MODEL, d = i % D_MODEL;
    int b = row / LT, t = row % LT;
    int tok = ids[b * LFULL + t];
    g_x[i] = emb[tok * D_MODEL + d] * 22.62741699796952f + g_pe[t * D_MODEL + d];
}

// ---------------- layernorm: warp per row (ddof=1, denom = std + eps) ----------------
__global__ void ln_kernel(const float* __restrict__ x, bf16* __restrict__ y,
                          const float* __restrict__ ga, const float* __restrict__ gb) {
    int w = threadIdx.x >> 5, lane = threadIdx.x & 31;
    int row = blockIdx.x * 8 + w;
    const float4* xr = (const float4*)(x + (size_t)row * D_MODEL);
    const float4* gav = (const float4*)ga;
    const float4* gbv = (const float4*)gb;
    bf16* yr = y + (size_t)row * D_MODEL;
    float4 v[4];
    float s = 0.f, s2 = 0.f;
#pragma unroll
    for (int j = 0; j < 4; j++) {
        v[j] = xr[lane + j * 32];
        s  += v[j].x + v[j].y + v[j].z + v[j].w;
        s2 += v[j].x * v[j].x + v[j].y * v[j].y + v[j].z * v[j].z + v[j].w * v[j].w;
    }
#pragma unroll
    for (int o = 16; o > 0; o >>= 1) {
        s  += __shfl_xor_sync(0xffffffffu, s,  o);
        s2 += __shfl_xor_sync(0xffffffffu, s2, o);
    }
    float mean = s / 512.0f;
    float var  = fmaxf(0.f, s2 - 512.0f * mean * mean) / 511.0f;
    float inv  = 1.0f / (sqrtf(var) + 1e-6f);
#pragma unroll
    for (int j = 0; j < 4; j++) {
        int c4 = lane + j * 32;
        float4 a = gav[c4], b = gbv[c4];
        float r0 = a.x * (v[j].x - mean) * inv + b.x;
        float r1 = a.y * (v[j].y - mean) * inv + b.y;
        float r2 = a.z * (v[j].z - mean) * inv + b.z;
        float r3 = a.w * (v[j].w - mean) * inv + b.w;
        *(bf162*)(yr + c4 * 4)     = __float22bfloat162_rn(make_float2(r0, r1));
        *(bf162*)(yr + c4 * 4 + 2) = __float22bfloat162_rn(make_float2(r2, r3));
    }
}

// =====================================================================
// bf16 tensor-core GEMM: C = A(MxK,row) @ W(KxN,row) + bias [+res][relu]
// BM=128 BN=256 BK=32, 3-stage cp.async ring, SINGLE sync per iter,
// 8 warps (2m x 4n), warp tile 64x64. A via ldmatrix.x4, B via x4.trans.
// =====================================================================
#define ASZ 10240   // 128 x 40 bf16
#define BSZ 16896   // 32 x 264 bf16
#define GEMM_SMEM (3*(ASZ+BSZ))

__global__ void __launch_bounds__(256, 1) gemm_bf(
        const bf16* __restrict__ A, const bf16* __restrict__ W,
        const float* __restrict__ bias, const float* __restrict__ res,
        bf16* __restrict__ Cb, float* __restrict__ Cf,
        int M, int N, int K, int relu) {
    extern __shared__ char smg[];
    int row0 = blockIdx.y * 128, col0 = blockIdx.x * 256;
    int tid = threadIdx.x;
    int wid = tid >> 5, lane = tid & 31;
    int g = lane >> 2, t = lane & 3;
    int wm = wid & 1, wn = wid >> 1;           // warp tile origin (wm*64, wn*64)
    int tl = lane >> 3, rr = lane & 7;

    float c[4][8][4];
#pragma unroll
    for (int i = 0; i < 4; i++)
#pragma unroll
        for (int j = 0; j < 8; j++)
#pragma unroll
            for (int r = 0; r < 4; r++) c[i][j][r] = 0.f;

    int nIter = K >> 5;
    auto loadStage = [&](int st, int k0g) {
        bf16 (*As)[40]  = (bf16(*)[40])(smg + st * ASZ);
        bf16 (*Bs)[264] = (bf16(*)[264])(smg + 3 * ASZ + st * BSZ);
#pragma unroll
        for (int i = 0; i < 2; i++) {
            int idx = tid + i * 256;
            int m = idx >> 2, kq = (idx & 3) * 8;
            cpa16(&As[m][kq], A + (size_t)(row0 + m) * K + k0g + kq);
        }
#pragma unroll
        for (int i = 0; i < 4; i++) {
            int idx = tid + i * 256;
            int k = idx >> 5, nq = (idx & 31) * 8;
            cpa16(&Bs[k][nq], W + (size_t)(k0g + k) * N + col0 + nq);
        }
    };
    // prologue: stages 0,1
#pragma unroll
    for (int p = 0; p < 2; p++) {
        if (p < nIter) loadStage(p, p << 5);
        cp_commit();
    }
    for (int it = 0; it < nIter; ++it) {
        int st = it % 3;
        bf16 (*As)[40]  = (bf16(*)[40])(smg + st * ASZ);
        bf16 (*Bs)[264] = (bf16(*)[264])(smg + 3 * ASZ + st * BSZ);
        if (it + 1 < nIter) cp_wait1(); else cp_wait0();
        __syncthreads();
        // prefetch stage it+2 (its buffer was consumed at iter it-1)
        int nx = it + 2;
        if (nx < nIter) loadStage(nx % 3, nx << 5);
        cp_commit();
#pragma unroll
        for (int ks = 0; ks < 2; ks++) {
            int k0 = ks * 16;
            unsigned af[4][4];
#pragma unroll
            for (int mt = 0; mt < 4; mt++)
                ldm_x4(af[mt], &As[wm * 64 + mt * 16 + (lane & 15)][k0 + (lane >> 4) * 8]);
            unsigned bf[8][2];
#pragma unroll
            for (int nb = 0; nb < 4; nb++) {
                unsigned r4[4];
                ldm_x4_t(r4, &Bs[k0 + (tl & 1) * 8 + rr][wn * 64 + nb * 16 + (tl >> 1) * 8]);
                bf[nb * 2 + 0][0] = r4[0]; bf[nb * 2 + 0][1] = r4[1];
                bf[nb * 2 + 1][0] = r4[2]; bf[nb * 2 + 1][1] = r4[3];
            }
#pragma unroll
            for (int mt = 0; mt < 4; mt++)
#pragma unroll
                for (int nt = 0; nt < 8; nt++) mmabf(c[mt][nt], af[mt], bf[nt]);
        }
    }
    // ---- epilogue ----
#pragma unroll
    for (int mt = 0; mt < 4; mt++) {
        int r = row0 + wm * 64 + mt * 16 + g;
#pragma unroll
        for (int nt = 0; nt < 8; nt++) {
            int cc = col0 + wn * 64 + nt * 8 + 2 * t;
            float b0 = bias[cc], b1 = bias[cc + 1];
            float v0 = c[mt][nt][0] + b0, v1 = c[mt][nt][1] + b1;
            float v2 = c[mt][nt][2] + b0, v3 = c[mt][nt][3] + b1;
            if (res) {
                v0 += res[(size_t)r * N + cc];       v1 += res[(size_t)r * N + cc + 1];
                v2 += res[(size_t)(r + 8) * N + cc]; v3 += res[(size_t)(r + 8) * N + cc + 1];
            }
            if (relu) {
                v0 = fmaxf(v0, 0.f); v1 = fmaxf(v1, 0.f);
                v2 = fmaxf(v2, 0.f); v3 = fmaxf(v3, 0.f);
            }
            if (Cf) {
                *(float2*)(Cf + (size_t)r * N + cc)       = make_float2(v0, v1);
                *(float2*)(Cf + (size_t)(r + 8) * N + cc) = make_float2(v2, v3);
            }
            if (Cb) {
                *(bf162*)(Cb + (size_t)r * N + cc)       = __float22bfloat162_rn(make_float2(v0, v1));
                *(bf162*)(Cb + (size_t)(r + 8) * N + cc) = __float22bfloat162_rn(make_float2(v2, v3));
            }
        }
    }
}

// =====================================================================
// Fused flash attention, double-buffered K/V chunks.
// smem: Q[0,18432) | K0 | V0 | K1 | V1 | mask[2][128]
// =====================================================================
#define KVB 36864
#define FLASH_SMEM (18432 + 2*KVB + 1024)

template <int CAUSAL>
__global__ void __launch_bounds__(256, 1) flash_kernel(
        const bf16* __restrict__ Qp, int qStride,
        const bf16* __restrict__ Kp, const bf16* __restrict__ Vp, int kvStride,
        const int* __restrict__ mask, int maskStride,
        bf16* __restrict__ Op, int Lq, int Lk) {
    extern __shared__ char sm[];
    bf16 (*Qs)[72] = (bf16(*)[72])(sm);
    int* mS = (int*)(sm + 18432 + 2 * KVB);

    int m0 = blockIdx.x * 128;
    int z = blockIdx.y, b = z / NHEAD, h = z % NHEAD;
    const bf16* Qb = Qp + (size_t)b * Lq * qStride + h * DK;
    const bf16* Kb = Kp + (size_t)b * Lk * kvStride + h * DK;
    const bf16* Vb = Vp + (size_t)b * Lk * kvStride + h * DK;
    bf16* Ob = Op + (size_t)b * Lq * D_MODEL + h * DK;
    const int* mrow = mask + (size_t)b * maskStride;

    int tid = threadIdx.x, w = tid >> 5, lane = tid & 31;
    int g = lane >> 2, t = lane & 3;
    int tl = lane >> 3, rr = lane & 7;
    const float scale = 0.125f;

    auto loadKV = [&](int buf, int n0) {
        bf16 (*Ks)[72] = (bf16(*)[72])(sm + 18432 + buf * KVB);
        bf16 (*Vs)[72] = (bf16(*)[72])(sm + 18432 + buf * KVB + KVB / 2);
#pragma unroll
        for (int i = 0; i < 4; i++) {
            int idx = tid + i * 256;
            int r = idx >> 3, cq = (idx & 7) * 8;
            cpa16(&Ks[r][cq], Kb + (size_t)(n0 + r) * kvStride + cq);
            cpa16(&Vs[r][cq], Vb + (size_t)(n0 + r) * kvStride + cq);
        }
        if (tid < 128) mS[buf * 128 + tid] = mrow[n0 + tid];
    };

    int nChunks = CAUSAL ? (m0 / 128 + 1) : (Lk / 128);

    // prologue: Q (group 0), then KV chunk 0 (group 1)
#pragma unroll
    for (int i = 0; i < 4; i++) {
        int idx = tid + i * 256;
        int r = idx >> 3, cq = (idx & 7) * 8;
        cpa16(&Qs[r][cq], Qb + (size_t)(m0 + r) * qStride + cq);
    }
    cp_commit();
    loadKV(0, 0);
    cp_commit();
    cp_wait1();       // Q done
    __syncthreads();

    unsigned qf[4][4];
#pragma unroll
    for (int ks = 0; ks < 4; ks++)
        ldm_x4(qf[ks], &Qs[w * 16 + (lane & 15)][ks * 16 + (lane >> 4) * 8]);

    float o[8][4];
#pragma unroll
    for (int i = 0; i < 8; i++)
#pragma unroll
        for (int j = 0; j < 4; j++) o[i][j] = 0.f;
    float mrun[2] = {-1e30f, -1e30f}, lrun[2] = {0.f, 0.f};
    int rowg = m0 + w * 16 + g;

    for (int ch = 0; ch < nChunks; ch++) {
        int n0 = ch * 128;
        int bu = ch & 1;
        bf16 (*Ks)[72] = (bf16(*)[72])(sm + 18432 + bu * KVB);
        bf16 (*Vs)[72] = (bf16(*)[72])(sm + 18432 + bu * KVB + KVB / 2);
        const int* mSb = mS + bu * 128;
        // prefetch next chunk into the other buffer (freed at end of ch-1)
        if (ch + 1 < nChunks) { loadKV(bu ^ 1, n0 + 128); cp_commit(); cp_wait1(); }
        else                  { cp_commit(); cp_wait0(); }
        __syncthreads();   // chunk ch visible to all warps

        float s[16][4];
#pragma unroll
        for (int nt = 0; nt < 16; nt++)
#pragma unroll
            for (int j = 0; j < 4; j++) s[nt][j] = 0.f;
#pragma unroll
        for (int ks = 0; ks < 4; ks++) {
            int k0 = ks * 16;
#pragma unroll
            for (int nt = 0; nt < 16; nt++) {
                unsigned bfr[2];
                int nc = nt * 8 + g;
                bfr[0] = *(const unsigned*)&Ks[nc][k0 + 2 * t];
                bfr[1] = *(const unsigned*)&Ks[nc][k0 + 8 + 2 * t];
                mmabf(s[nt], qf[ks], bfr);
            }
        }
#pragma unroll
        for (int nt = 0; nt < 16; nt++) {
            int cl = nt * 8 + 2 * t;
            int c0 = n0 + cl, c1 = c0 + 1;
            bool k0ok = mSb[cl] != 0, k1ok = mSb[cl + 1] != 0;
            bool v0 = k0ok && (!CAUSAL || c0 <= rowg);
            bool v1 = k1ok && (!CAUSAL || c1 <= rowg);
            bool v2 = k0ok && (!CAUSAL || c0 <= rowg + 8);
            bool v3 = k1ok && (!CAUSAL || c1 <= rowg + 8);
            s[nt][0] = v0 ? s[nt][0] * scale : -10000.0f;
            s[nt][1] = v1 ? s[nt][1] * scale : -10000.0f;
            s[nt][2] = v2 ? s[nt][2] * scale : -10000.0f;
            s[nt][3] = v3 ? s[nt][3] * scale : -10000.0f;
        }
        float mg0 = -1e30f, mg1 = -1e30f;
#pragma unroll
        for (int nt = 0; nt < 16; nt++) {
            mg0 = fmaxf(mg0, fmaxf(s[nt][0], s[nt][1]));
            mg1 = fmaxf(mg1, fmaxf(s[nt][2], s[nt][3]));
        }
#pragma unroll
        for (int off = 1; off < 4; off <<= 1) {
            mg0 = fmaxf(mg0, __shfl_xor_sync(0xffffffffu, mg0, off));
            mg1 = fmaxf(mg1, __shfl_xor_sync(0xffffffffu, mg1, off));
        }
        float mn0 = fmaxf(mrun[0], mg0), mn1 = fmaxf(mrun[1], mg1);
        float a0 = __expf(mrun[0] - mn0), a1 = __expf(mrun[1] - mn1);
        float sum0 = 0.f, sum1 = 0.f;
#pragma unroll
        for (int nt = 0; nt < 16; nt++) {
            s[nt][0] = __expf(s[nt][0] - mn0);
            s[nt][1] = __expf(s[nt][1] - mn0);
            s[nt][2] = __expf(s[nt][2] - mn1);
            s[nt][3] = __expf(s[nt][3] - mn1);
            sum0 += s[nt][0] + s[nt][1];
            sum1 += s[nt][2] + s[nt][3];
        }
#pragma unroll
        for (int off = 1; off < 4; off <<= 1) {
            sum0 += __shfl_xor_sync(0xffffffffu, sum0, off);
            sum1 += __shfl_xor_sync(0xffffffffu, sum1, off);
        }
        lrun[0] = lrun[0] * a0 + sum0;
        lrun[1] = lrun[1] * a1 + sum1;
        mrun[0] = mn0; mrun[1] = mn1;
#pragma unroll
        for (int ot = 0; ot < 8; ot++) {
            o[ot][0] *= a0; o[ot][1] *= a0;
            o[ot][2] *= a1; o[ot][3] *= a1;
        }
#pragma unroll
        for (int j = 0; j < 8; j++) {
            unsigned pa[4];
            pa[0] = packbf(s[2 * j][0],     s[2 * j][1]);
            pa[1] = packbf(s[2 * j][2],     s[2 * j][3]);
            pa[2] = packbf(s[2 * j + 1][0], s[2 * j + 1][1]);
            pa[3] = packbf(s[2 * j + 1][2], s[2 * j + 1][3]);
#pragma unroll
            for (int nb = 0; nb < 4; nb++) {
                unsigned r4[4];
                ldm_x4_t(r4, &Vs[j * 16 + (tl & 1) * 8 + rr][nb * 16 + (tl >> 1) * 8]);
                mmabf(o[nb * 2 + 0], pa, r4);
                mmabf(o[nb * 2 + 1], pa, r4 + 2);
            }
        }
        __syncthreads();   // all warps done with buffer bu before ch+1 prefetches into it
    }
    float inv0 = 1.0f / lrun[0], inv1 = 1.0f / lrun[1];
#pragma unroll
    for (int ot = 0; ot < 8; ot++) {
        int col = ot * 8 + 2 * t;
        *(bf162*)(Ob + (size_t)rowg * D_MODEL + col) =
            __float22bfloat162_rn(make_float2(o[ot][0] * inv0, o[ot][1] * inv0));
        *(bf162*)(Ob + (size_t)(rowg + 8) * D_MODEL + col) =
            __float22bfloat162_rn(make_float2(o[ot][2] * inv1, o[ot][3] * inv1));
    }
}

// ---------------- final log_softmax (warp per row, 512 cols) ----------------
__global__ void logsoftmax_kernel(const float* __restrict__ X, float* __restrict__ Out) {
    int warp = (blockIdx.x * blockDim.x + threadIdx.x) >> 5;
    int lane = threadIdx.x & 31;
    if (warp >= MT) return;
    const float* r = X + (size_t)warp * VOCAB;
    float v[16], mx = -1e30f;
#pragma unroll
    for (int j = 0; j < 16; j++) { v[j] = r[lane + j * 32]; mx = fmaxf(mx, v[j]); }
#pragma unroll
    for (int o = 16; o > 0; o >>= 1) mx = fmaxf(mx, __shfl_xor_sync(0xffffffffu, mx, o));
    float sum = 0.f;
#pragma unroll
    for (int j = 0; j < 16; j++) sum += expf(v[j] - mx);
#pragma unroll
    for (int o = 16; o > 0; o >>= 1) sum += __shfl_xor_sync(0xffffffffu, sum, o);
    float lse = mx + logf(sum);
    float* out = Out + (size_t)warp * VOCAB;
#pragma unroll
    for (int j = 0; j < 16; j++) out[lane + j * 32] = v[j] - lse;
}

// ---------------- host driver ----------------
template <typename T>
static T* symp(const void* s) {
    void* p = nullptr;
    cudaGetSymbolAddress(&p, s);
    return (T*)p;
}

extern "C" void kernel_launch(void* const* d_in, const int* in_sizes, int n_in,
                              void* d_out, int out_size) {
    const int*   ids    = (const int*)d_in[0];
    const int*   attm   = (const int*)d_in[1];
    const float* src    = (const float*)d_in[2];
    const int*   srcm   = (const int*)d_in[3];
    const float* emb    = (const float*)d_in[4];
    const float* sa_W   = (const float*)d_in[5];
    const float* sa_b   = (const float*)d_in[6];
    const float* ca_W   = (const float*)d_in[7];
    const float* ca_b   = (const float*)d_in[8];
    const float* ln_a   = (const float*)d_in[9];
    const float* ln_b   = (const float*)d_in[10];
    const float* ffn_w1 = (const float*)d_in[11];
    const float* ffn_b1 = (const float*)d_in[12];
    const float* ffn_w2 = (const float*)d_in[13];
    const float* ffn_b2 = (const float*)d_in[14];
    const float* fin_a  = (const float*)d_in[15];
    const float* fin_b  = (const float*)d_in[16];
    const float* lm_W   = (const float*)d_in[17];
    const float* lm_b   = (const float*)d_in[18];
    float* out = (float*)d_out;

    float* x    = symp<float>(g_x);
    float* lg   = symp<float>(g_lg);
    bf16* hb    = symp<bf16>(g_hb);
    bf16* qb    = symp<bf16>(g_qb);
    bf16* qkv   = symp<bf16>(g_qkv);
    bf16* kv    = symp<bf16>(g_kv);
    bf16* ab    = symp<bf16>(g_ab);
    bf16* fb    = symp<bf16>(g_fb);
    bf16* wsa   = symp<bf16>(g_wsa);
    bf16* wca   = symp<bf16>(g_wca);
    bf16* wqkv  = symp<bf16>(g_wqkv);
    bf16* wkv   = symp<bf16>(g_wkv);
    float* bqkv = symp<float>(g_bqkv);
    float* bkv  = symp<float>(g_bkv);
    bf16* w1    = symp<bf16>(g_w1);
    bf16* w2    = symp<bf16>(g_w2);
    bf16* wlm   = symp<bf16>(g_wlm);
    bf16* srcb  = symp<bf16>(g_srcb);

    static bool attrSet = false;
    if (!attrSet) {
        cudaFuncSetAttribute(flash_kernel<1>, cudaFuncAttributeMaxDynamicSharedMemorySize, FLASH_SMEM);
        cudaFuncSetAttribute(flash_kernel<0>, cudaFuncAttributeMaxDynamicSharedMemorySize, FLASH_SMEM);
        cudaFuncSetAttribute(gemm_bf, cudaFuncAttributeMaxDynamicSharedMemorySize, GEMM_SMEM);
        attrSet = true;
    }

    // ---- one-time-per-launch conversions / repacks ----
    {
        int nF = NLAYER * D_MODEL * D_FF;
        int nM = NLAYER * D_MODEL * D_MODEL;
        conv_mat<<<(nM + 1023) / 1024, 256>>>(sa_W, wsa, 3);
        conv_mat<<<(nM + 1023) / 1024, 256>>>(ca_W, wca, 0);
        conv_mat<<<(nM + 1023) / 1024, 256>>>(ca_W, wca, 3);
        f2bf_kernel<<<(nF + 1023) / 1024, 256>>>(ffn_w1, w1, nF);
        f2bf_kernel<<<(nF + 1023) / 1024, 256>>>(ffn_w2, w2, nF);
        f2bf_kernel<<<(D_MODEL * VOCAB + 1023) / 1024, 256>>>(lm_W, wlm, D_MODEL * VOCAB);
        f2bf_kernel<<<(MS * D_MODEL + 1023) / 1024, 256>>>(src, srcb, MS * D_MODEL);
        int tq = NLAYER * D_MODEL * 3 * D_MODEL;
        int tk = NLAYER * D_MODEL * 2 * D_MODEL;
        pack_w<<<(tq + 1023) / 1024, 256>>>(sa_W, wqkv, 3, 0, tq);
        pack_w<<<(tk + 1023) / 1024, 256>>>(ca_W, wkv, 2, 1, tk);
        pack_b<<<(NLAYER * 3 * D_MODEL + 255) / 256, 256>>>(sa_b, bqkv, 3, 0, NLAYER * 3 * D_MODEL);
        pack_b<<<(NLAYER * 2 * D_MODEL + 255) / 256, 256>>>(ca_b, bkv, 2, 1, NLAYER * 2 * D_MODEL);
    }

    pe_kernel<<<(LT * D_MODEL + 255) / 256, 256>>>();
    embed_kernel<<<(MT * D_MODEL + 255) / 256, 256>>>(ids, emb);

    dim3 gProjT(D_MODEL / 256, MT / 128);     // (2, 64)
    dim3 gQKV(3 * D_MODEL / 256, MT / 128);   // (6, 64)
    dim3 gKV(2 * D_MODEL / 256, MS / 128);    // (4, 32)
    dim3 gFfn1(D_FF / 256, MT / 128);         // (8, 64)
    dim3 gFlash(LT / 128, BATCH * NHEAD);
    const int lnGrid = MT / 8;

    for (int i = 0; i < NLAYER; i++) {
        const bf16*  saW = wsa + (size_t)i * 4 * D_MODEL * D_MODEL;
        const float* sab = sa_b + (size_t)i * 4 * D_MODEL;
        const bf16*  caW = wca + (size_t)i * 4 * D_MODEL * D_MODEL;
        const float* cab = ca_b + (size_t)i * 4 * D_MODEL;
        const float* lnA = ln_a + (size_t)i * 3 * D_MODEL;
        const float* lnB = ln_b + (size_t)i * 3 * D_MODEL;

        // ---- self-attention ----
        ln_kernel<<<lnGrid, 256>>>(x, hb, lnA + 0 * D_MODEL, lnB + 0 * D_MODEL);
        gemm_bf<<<gQKV, 256, GEMM_SMEM>>>(hb, wqkv + (size_t)i * D_MODEL * 3 * D_MODEL,
                               bqkv + (size_t)i * 3 * D_MODEL, nullptr, qkv, nullptr,
                               MT, 3 * D_MODEL, D_MODEL, 0);
        flash_kernel<1><<<gFlash, 256, FLASH_SMEM>>>(
            qkv, 3 * D_MODEL, qkv + D_MODEL, qkv + 2 * D_MODEL, 3 * D_MODEL,
            attm, LFULL, ab, LT, LT);
        gemm_bf<<<gProjT, 256, GEMM_SMEM>>>(ab, saW + 3 * D_MODEL * D_MODEL, sab + 3 * D_MODEL,
                                 x, nullptr, x, MT, D_MODEL, D_MODEL, 0);

        // ---- cross-attention ----
        ln_kernel<<<lnGrid, 256>>>(x, hb, lnA + 1 * D_MODEL, lnB + 1 * D_MODEL);
        gemm_bf<<<gProjT, 256, GEMM_SMEM>>>(hb, caW + 0 * D_MODEL * D_MODEL, cab + 0 * D_MODEL,
                                 nullptr, qb, nullptr, MT, D_MODEL, D_MODEL, 0);
        gemm_bf<<<gKV, 256, GEMM_SMEM>>>(srcb, wkv + (size_t)i * D_MODEL * 2 * D_MODEL,
                              bkv + (size_t)i * 2 * D_MODEL, nullptr, kv, nullptr,
                              MS, 2 * D_MODEL, D_MODEL, 0);
        flash_kernel<0><<<gFlash, 256, FLASH_SMEM>>>(
            qb, D_MODEL, kv, kv + D_MODEL, 2 * D_MODEL,
            srcm, SRC_S, ab, LT, SRC_S);
        gemm_bf<<<gProjT, 256, GEMM_SMEM>>>(ab, caW + 3 * D_MODEL * D_MODEL, cab + 3 * D_MODEL,
                                 x, nullptr, x, MT, D_MODEL, D_MODEL, 0);

        // ---- FFN ----
        ln_kernel<<<lnGrid, 256>>>(x, hb, lnA + 2 * D_MODEL, lnB + 2 * D_MODEL);
        gemm_bf<<<gFfn1, 256, GEMM_SMEM>>>(hb, w1 + (size_t)i * D_MODEL * D_FF,
                                ffn_b1 + (size_t)i * D_FF, nullptr, fb, nullptr,
                                MT, D_FF, D_MODEL, 1);
        gemm_bf<<<gProjT, 256, GEMM_SMEM>>>(fb, w2 + (size_t)i * D_FF * D_MODEL,
                                ffn_b2 + (size_t)i * D_MODEL, x, nullptr, x,
                                MT, D_MODEL, D_FF, 0);
    }

    ln_kernel<<<lnGrid, 256>>>(x, hb, fin_a, fin_b);
    gemm_bf<<<dim3(VOCAB / 256, MT / 128), 256, GEMM_SMEM>>>(hb, wlm, lm_b, nullptr, nullptr, lg,
                                                  MT, VOCAB, D_MODEL, 0);
    logsoftmax_kernel<<<(MT * 32 + 255) / 256, 256>>>(lg, out);
}

// round 11
// speedup vs baseline: 6.8736x; 1.1060x over previous
#include <cuda_runtime.h>
#include <cuda_bf16.h>
#include <math.h>

// ---------------- problem constants ----------------
#define D_MODEL 512
#define D_FF    2048
#define NHEAD   8
#define DK      64
#define NLAYER  4
#define VOCAB   512
#define BATCH   16
#define LFULL   513
#define LT      512
#define SRC_S   256
#define MT      (BATCH*LT)
#define MS      (BATCH*SRC_S)

typedef __nv_bfloat16 bf16;
typedef __nv_bfloat162 bf162;

// ---------------- device scratch (static, no allocation) ----------------
__device__ float g_x  [MT*D_MODEL];                  // residual stream (fp32)
__device__ float g_pe [LT*D_MODEL];
__device__ float g_lg [MT*VOCAB];

__device__ bf16 g_hb [MT*D_MODEL];                   // ln output
__device__ bf16 g_qb [MT*D_MODEL];                   // cross-attn Q
__device__ bf16 g_qkv[MT*3*D_MODEL];                 // fused self QKV
__device__ bf16 g_kv [MS*2*D_MODEL];                 // fused cross KV
__device__ bf16 g_ab [MT*D_MODEL];                   // attention output
__device__ bf16 g_fb [MT*D_FF];                      // ffn intermediate
__device__ bf16 g_wsa[NLAYER*4*D_MODEL*D_MODEL];     // only mat3 used
__device__ bf16 g_wca[NLAYER*4*D_MODEL*D_MODEL];     // only mats 0,3 used
__device__ bf16 g_wqkv[NLAYER*D_MODEL*3*D_MODEL];    // packed self QKV weights
__device__ bf16 g_wkv [NLAYER*D_MODEL*2*D_MODEL];    // packed cross KV weights
__device__ float g_bqkv[NLAYER*3*D_MODEL];
__device__ float g_bkv [NLAYER*2*D_MODEL];
__device__ bf16 g_w1 [NLAYER*D_MODEL*D_FF];
__device__ bf16 g_w2 [NLAYER*D_FF*D_MODEL];
__device__ bf16 g_wlm[D_MODEL*VOCAB];
__device__ bf16 g_srcb[MS*D_MODEL];

// ---------------- PTX helpers ----------------
__device__ __forceinline__ void cpa16(void* s, const void* g) {
    unsigned a = (unsigned)__cvta_generic_to_shared(s);
    asm volatile("cp.async.ca.shared.global [%0], [%1], 16;" :: "r"(a), "l"(g));
}
__device__ __forceinline__ void cp_commit() { asm volatile("cp.async.commit_group;"); }
__device__ __forceinline__ void cp_wait0()  { asm volatile("cp.async.wait_group 0;"); }
__device__ __forceinline__ void cp_wait1()  { asm volatile("cp.async.wait_group 1;"); }
__device__ __forceinline__ void ldm_x4(unsigned* r, const void* p) {
    unsigned a = (unsigned)__cvta_generic_to_shared(p);
    asm volatile("ldmatrix.sync.aligned.m8n8.x4.shared.b16 {%0,%1,%2,%3}, [%4];"
        : "=r"(r[0]), "=r"(r[1]), "=r"(r[2]), "=r"(r[3]) : "r"(a));
}
__device__ __forceinline__ void ldm_x4_t(unsigned* r, const void* p) {
    unsigned a = (unsigned)__cvta_generic_to_shared(p);
    asm volatile("ldmatrix.sync.aligned.m8n8.x4.trans.shared.b16 {%0,%1,%2,%3}, [%4];"
        : "=r"(r[0]), "=r"(r[1]), "=r"(r[2]), "=r"(r[3]) : "r"(a));
}
__device__ __forceinline__ void mmabf(float* c, const unsigned* a, const unsigned* b) {
    asm volatile(
        "mma.sync.aligned.m16n8k16.row.col.f32.bf16.bf16.f32 "
        "{%0,%1,%2,%3}, {%4,%5,%6,%7}, {%8,%9}, {%0,%1,%2,%3};"
        : "+f"(c[0]), "+f"(c[1]), "+f"(c[2]), "+f"(c[3])
        : "r"(a[0]), "r"(a[1]), "r"(a[2]), "r"(a[3]), "r"(b[0]), "r"(b[1]));
}
__device__ __forceinline__ unsigned packbf(float x, float y) {
    bf162 v = __float22bfloat162_rn(make_float2(x, y));
    return *(unsigned*)&v;
}

// ---------------- conversions / repacks ----------------
__global__ void f2bf_kernel(const float* __restrict__ s, bf16* __restrict__ d, int n) {
    int i = blockIdx.x * blockDim.x + threadIdx.x;
    int stride = gridDim.x * blockDim.x;
    for (; i < n; i += stride) d[i] = __float2bfloat16(s[i]);
}
// convert only matrix `mat` of a [L][4][512][512] tensor (into same offsets)
__global__ void conv_mat(const float* __restrict__ W, bf16* __restrict__ out, int mat) {
    int i = blockIdx.x * blockDim.x + threadIdx.x;
    int stride = gridDim.x * blockDim.x;
    int total = NLAYER * D_MODEL * D_MODEL;
    for (; i < total; i += stride) {
        int l = i / (D_MODEL * D_MODEL), r = i % (D_MODEL * D_MODEL);
        size_t off = ((size_t)l * 4 + mat) * D_MODEL * D_MODEL + r;
        out[off] = __float2bfloat16(W[off]);
    }
}
// W layout [L][4][512][512] -> out [L][512][nmat*512]
__global__ void pack_w(const float* __restrict__ W, bf16* __restrict__ out,
                       int nmat, int mat0, int total) {
    int i = blockIdx.x * blockDim.x + threadIdx.x;
    int stride = gridDim.x * blockDim.x;
    int perL = D_MODEL * nmat * D_MODEL;
    for (; i < total; i += stride) {
        int l = i / perL, rem = i % perL;
        int k = rem / (nmat * D_MODEL), j = rem % (nmat * D_MODEL);
        int m = mat0 + (j >> 9), c = j & 511;
        out[i] = __float2bfloat16(W[(((size_t)l * 4 + m) * D_MODEL + k) * D_MODEL + c]);
    }
}
__global__ void pack_b(const float* __restrict__ B, float* __restrict__ out,
                       int nmat, int mat0, int total) {
    int i = blockIdx.x * blockDim.x + threadIdx.x;
    if (i >= total) return;
    int perL = nmat * D_MODEL;
    int l = i / perL, j = i % perL;
    int m = mat0 + (j >> 9), c = j & 511;
    out[i] = B[((size_t)l * 4 + m) * D_MODEL + c];
}

// ---------------- positional encoding (fp64 to match numpy) ----------------
__global__ void pe_kernel() {
    int i = blockIdx.x * blockDim.x + threadIdx.x;
    if (i >= LT * D_MODEL) return;
    int t = i / D_MODEL, d = i % D_MODEL;
    int e = d & ~1;
    double div = exp(-(double)e * (log(10000.0) / (double)D_MODEL));
    double ang = (double)t * div;
    g_pe[i] = (float)((d & 1) ? cos(ang) : sin(ang));
}

// ---------------- embedding + PE ----------------
__global__ void embed_kernel(const int* __restrict__ ids, const float* __restrict__ emb) {
    int i = blockIdx.x * blockDim.x + threadIdx.x;
    if (i >= MT * D_MODEL) return;
    int row = i / D_MODEL, d = i % D_MODEL;
    int b = row / LT, t = row % LT;
    int tok = ids[b * LFULL + t];
    g_x[i] = emb[tok * D_MODEL + d] * 22.62741699796952f + g_pe[t * D_MODEL + d];
}

// ---------------- layernorm: warp per row (ddof=1, denom = std + eps) ----------------
__global__ void ln_kernel(const float* __restrict__ x, bf16* __restrict__ y,
                          const float* __restrict__ ga, const float* __restrict__ gb) {
    int w = threadIdx.x >> 5, lane = threadIdx.x & 31;
    int row = blockIdx.x * 8 + w;
    const float4* xr = (const float4*)(x + (size_t)row * D_MODEL);
    const float4* gav = (const float4*)ga;
    const float4* gbv = (const float4*)gb;
    bf16* yr = y + (size_t)row * D_MODEL;
    float4 v[4];
    float s = 0.f, s2 = 0.f;
#pragma unroll
    for (int j = 0; j < 4; j++) {
        v[j] = xr[lane + j * 32];
        s  += v[j].x + v[j].y + v[j].z + v[j].w;
        s2 += v[j].x * v[j].x + v[j].y * v[j].y + v[j].z * v[j].z + v[j].w * v[j].w;
    }
#pragma unroll
    for (int o = 16; o > 0; o >>= 1) {
        s  += __shfl_xor_sync(0xffffffffu, s,  o);
        s2 += __shfl_xor_sync(0xffffffffu, s2, o);
    }
    float mean = s / 512.0f;
    float var  = fmaxf(0.f, s2 - 512.0f * mean * mean) / 511.0f;
    float inv  = 1.0f / (sqrtf(var) + 1e-6f);
#pragma unroll
    for (int j = 0; j < 4; j++) {
        int c4 = lane + j * 32;
        float4 a = gav[c4], b = gbv[c4];
        float r0 = a.x * (v[j].x - mean) * inv + b.x;
        float r1 = a.y * (v[j].y - mean) * inv + b.y;
        float r2 = a.z * (v[j].z - mean) * inv + b.z;
        float r3 = a.w * (v[j].w - mean) * inv + b.w;
        *(bf162*)(yr + c4 * 4)     = __float22bfloat162_rn(make_float2(r0, r1));
        *(bf162*)(yr + c4 * 4 + 2) = __float22bfloat162_rn(make_float2(r2, r3));
    }
}

// =====================================================================
// bf16 tensor-core GEMM: C = A(MxK,row) @ W(KxN,row) + bias [+res][relu]
// BM=128 BN=128 BK=32, 3-stage cp.async ring, SINGLE sync per iter,
// 8 warps (2m x 4n), warp tile 64x32, 2 CTAs/SM.
// =====================================================================
#define ASZ 10240   // 128 x 40 bf16
#define BSZ 8704    // 32 x 136 bf16
#define GEMM_SMEM (3*(ASZ+BSZ))

__global__ void __launch_bounds__(256, 2) gemm_bf(
        const bf16* __restrict__ A, const bf16* __restrict__ W,
        const float* __restrict__ bias, const float* __restrict__ res,
        bf16* __restrict__ Cb, float* __restrict__ Cf,
        int M, int N, int K, int relu) {
    extern __shared__ char smg[];
    int row0 = blockIdx.y * 128, col0 = blockIdx.x * 128;
    int tid = threadIdx.x;
    int wid = tid >> 5, lane = tid & 31;
    int g = lane >> 2, t = lane & 3;
    int wm = wid & 1, wn = wid >> 1;           // warp tile origin (wm*64, wn*32)
    int tl = lane >> 3, rr = lane & 7;

    float c[4][4][4];
#pragma unroll
    for (int i = 0; i < 4; i++)
#pragma unroll
        for (int j = 0; j < 4; j++)
#pragma unroll
            for (int r = 0; r < 4; r++) c[i][j][r] = 0.f;

    int nIter = K >> 5;
    auto loadStage = [&](int st, int k0g) {
        bf16 (*As)[40]  = (bf16(*)[40])(smg + st * ASZ);
        bf16 (*Bs)[136] = (bf16(*)[136])(smg + 3 * ASZ + st * BSZ);
#pragma unroll
        for (int i = 0; i < 2; i++) {
            int idx = tid + i * 256;
            int m = idx >> 2, kq = (idx & 3) * 8;
            cpa16(&As[m][kq], A + (size_t)(row0 + m) * K + k0g + kq);
        }
#pragma unroll
        for (int i = 0; i < 2; i++) {
            int idx = tid + i * 256;
            int k = idx >> 4, nq = (idx & 15) * 8;
            cpa16(&Bs[k][nq], W + (size_t)(k0g + k) * N + col0 + nq);
        }
    };
    // prologue: stages 0,1
#pragma unroll
    for (int p = 0; p < 2; p++) {
        if (p < nIter) loadStage(p, p << 5);
        cp_commit();
    }
    for (int it = 0; it < nIter; ++it) {
        int st = it % 3;
        bf16 (*As)[40]  = (bf16(*)[40])(smg + st * ASZ);
        bf16 (*Bs)[136] = (bf16(*)[136])(smg + 3 * ASZ + st * BSZ);
        if (it + 1 < nIter) cp_wait1(); else cp_wait0();
        __syncthreads();
        // prefetch stage it+2 (its buffer was consumed at iter it-1)
        int nx = it + 2;
        if (nx < nIter) loadStage(nx % 3, nx << 5);
        cp_commit();
#pragma unroll
        for (int ks = 0; ks < 2; ks++) {
            int k0 = ks * 16;
            unsigned af[4][4];
#pragma unroll
            for (int mt = 0; mt < 4; mt++)
                ldm_x4(af[mt], &As[wm * 64 + mt * 16 + (lane & 15)][k0 + (lane >> 4) * 8]);
            unsigned bf[4][2];
#pragma unroll
            for (int nb = 0; nb < 2; nb++) {
                unsigned r4[4];
                ldm_x4_t(r4, &Bs[k0 + (tl & 1) * 8 + rr][wn * 32 + nb * 16 + (tl >> 1) * 8]);
                bf[nb * 2 + 0][0] = r4[0]; bf[nb * 2 + 0][1] = r4[1];
                bf[nb * 2 + 1][0] = r4[2]; bf[nb * 2 + 1][1] = r4[3];
            }
#pragma unroll
            for (int mt = 0; mt < 4; mt++)
#pragma unroll
                for (int nt = 0; nt < 4; nt++) mmabf(c[mt][nt], af[mt], bf[nt]);
        }
    }
    // ---- epilogue ----
#pragma unroll
    for (int mt = 0; mt < 4; mt++) {
        int r = row0 + wm * 64 + mt * 16 + g;
#pragma unroll
        for (int nt = 0; nt < 4; nt++) {
            int cc = col0 + wn * 32 + nt * 8 + 2 * t;
            float b0 = bias[cc], b1 = bias[cc + 1];
            float v0 = c[mt][nt][0] + b0, v1 = c[mt][nt][1] + b1;
            float v2 = c[mt][nt][2] + b0, v3 = c[mt][nt][3] + b1;
            if (res) {
                v0 += res[(size_t)r * N + cc];       v1 += res[(size_t)r * N + cc + 1];
                v2 += res[(size_t)(r + 8) * N + cc]; v3 += res[(size_t)(r + 8) * N + cc + 1];
            }
            if (relu) {
                v0 = fmaxf(v0, 0.f); v1 = fmaxf(v1, 0.f);
                v2 = fmaxf(v2, 0.f); v3 = fmaxf(v3, 0.f);
            }
            if (Cf) {
                *(float2*)(Cf + (size_t)r * N + cc)       = make_float2(v0, v1);
                *(float2*)(Cf + (size_t)(r + 8) * N + cc) = make_float2(v2, v3);
            }
            if (Cb) {
                *(bf162*)(Cb + (size_t)r * N + cc)       = __float22bfloat162_rn(make_float2(v0, v1));
                *(bf162*)(Cb + (size_t)(r + 8) * N + cc) = __float22bfloat162_rn(make_float2(v2, v3));
            }
        }
    }
}

// =====================================================================
// Fused flash attention, double-buffered K/V chunks.
// smem: Q[0,18432) | K0 | V0 | K1 | V1 | mask[2][128]
// =====================================================================
#define KVB 36864
#define FLASH_SMEM (18432 + 2*KVB + 1024)

template <int CAUSAL>
__global__ void __launch_bounds__(256, 1) flash_kernel(
        const bf16* __restrict__ Qp, int qStride,
        const bf16* __restrict__ Kp, const bf16* __restrict__ Vp, int kvStride,
        const int* __restrict__ mask, int maskStride,
        bf16* __restrict__ Op, int Lq, int Lk) {
    extern __shared__ char sm[];
    bf16 (*Qs)[72] = (bf16(*)[72])(sm);
    int* mS = (int*)(sm + 18432 + 2 * KVB);

    int m0 = blockIdx.x * 128;
    int z = blockIdx.y, b = z / NHEAD, h = z % NHEAD;
    const bf16* Qb = Qp + (size_t)b * Lq * qStride + h * DK;
    const bf16* Kb = Kp + (size_t)b * Lk * kvStride + h * DK;
    const bf16* Vb = Vp + (size_t)b * Lk * kvStride + h * DK;
    bf16* Ob = Op + (size_t)b * Lq * D_MODEL + h * DK;
    const int* mrow = mask + (size_t)b * maskStride;

    int tid = threadIdx.x, w = tid >> 5, lane = tid & 31;
    int g = lane >> 2, t = lane & 3;
    int tl = lane >> 3, rr = lane & 7;
    const float scale = 0.125f;

    auto loadKV = [&](int buf, int n0) {
        bf16 (*Ks)[72] = (bf16(*)[72])(sm + 18432 + buf * KVB);
        bf16 (*Vs)[72] = (bf16(*)[72])(sm + 18432 + buf * KVB + KVB / 2);
#pragma unroll
        for (int i = 0; i < 4; i++) {
            int idx = tid + i * 256;
            int r = idx >> 3, cq = (idx & 7) * 8;
            cpa16(&Ks[r][cq], Kb + (size_t)(n0 + r) * kvStride + cq);
            cpa16(&Vs[r][cq], Vb + (size_t)(n0 + r) * kvStride + cq);
        }
        if (tid < 128) mS[buf * 128 + tid] = mrow[n0 + tid];
    };

    int nChunks = CAUSAL ? (m0 / 128 + 1) : (Lk / 128);

    // prologue: Q (group 0), then KV chunk 0 (group 1)
#pragma unroll
    for (int i = 0; i < 4; i++) {
        int idx = tid + i * 256;
        int r = idx >> 3, cq = (idx & 7) * 8;
        cpa16(&Qs[r][cq], Qb + (size_t)(m0 + r) * qStride + cq);
    }
    cp_commit();
    loadKV(0, 0);
    cp_commit();
    cp_wait1();       // Q done
    __syncthreads();

    unsigned qf[4][4];
#pragma unroll
    for (int ks = 0; ks < 4; ks++)
        ldm_x4(qf[ks], &Qs[w * 16 + (lane & 15)][ks * 16 + (lane >> 4) * 8]);

    float o[8][4];
#pragma unroll
    for (int i = 0; i < 8; i++)
#pragma unroll
        for (int j = 0; j < 4; j++) o[i][j] = 0.f;
    float mrun[2] = {-1e30f, -1e30f}, lrun[2] = {0.f, 0.f};
    int rowg = m0 + w * 16 + g;

    for (int ch = 0; ch < nChunks; ch++) {
        int n0 = ch * 128;
        int bu = ch & 1;
        bf16 (*Ks)[72] = (bf16(*)[72])(sm + 18432 + bu * KVB);
        bf16 (*Vs)[72] = (bf16(*)[72])(sm + 18432 + bu * KVB + KVB / 2);
        const int* mSb = mS + bu * 128;
        // prefetch next chunk into the other buffer (freed at end of ch-1)
        if (ch + 1 < nChunks) { loadKV(bu ^ 1, n0 + 128); cp_commit(); cp_wait1(); }
        else                  { cp_commit(); cp_wait0(); }
        __syncthreads();   // chunk ch visible to all warps

        float s[16][4];
#pragma unroll
        for (int nt = 0; nt < 16; nt++)
#pragma unroll
            for (int j = 0; j < 4; j++) s[nt][j] = 0.f;
#pragma unroll
        for (int ks = 0; ks < 4; ks++) {
            int k0 = ks * 16;
#pragma unroll
            for (int nt = 0; nt < 16; nt++) {
                unsigned bfr[2];
                int nc = nt * 8 + g;
                bfr[0] = *(const unsigned*)&Ks[nc][k0 + 2 * t];
                bfr[1] = *(const unsigned*)&Ks[nc][k0 + 8 + 2 * t];
                mmabf(s[nt], qf[ks], bfr);
            }
        }
#pragma unroll
        for (int nt = 0; nt < 16; nt++) {
            int cl = nt * 8 + 2 * t;
            int c0 = n0 + cl, c1 = c0 + 1;
            bool k0ok = mSb[cl] != 0, k1ok = mSb[cl + 1] != 0;
            bool v0 = k0ok && (!CAUSAL || c0 <= rowg);
            bool v1 = k1ok && (!CAUSAL || c1 <= rowg);
            bool v2 = k0ok && (!CAUSAL || c0 <= rowg + 8);
            bool v3 = k1ok && (!CAUSAL || c1 <= rowg + 8);
            s[nt][0] = v0 ? s[nt][0] * scale : -10000.0f;
            s[nt][1] = v1 ? s[nt][1] * scale : -10000.0f;
            s[nt][2] = v2 ? s[nt][2] * scale : -10000.0f;
            s[nt][3] = v3 ? s[nt][3] * scale : -10000.0f;
        }
        float mg0 = -1e30f, mg1 = -1e30f;
#pragma unroll
        for (int nt = 0; nt < 16; nt++) {
            mg0 = fmaxf(mg0, fmaxf(s[nt][0], s[nt][1]));
            mg1 = fmaxf(mg1, fmaxf(s[nt][2], s[nt][3]));
        }
#pragma unroll
        for (int off = 1; off < 4; off <<= 1) {
            mg0 = fmaxf(mg0, __shfl_xor_sync(0xffffffffu, mg0, off));
            mg1 = fmaxf(mg1, __shfl_xor_sync(0xffffffffu, mg1, off));
        }
        float mn0 = fmaxf(mrun[0], mg0), mn1 = fmaxf(mrun[1], mg1);
        float a0 = __expf(mrun[0] - mn0), a1 = __expf(mrun[1] - mn1);
        float sum0 = 0.f, sum1 = 0.f;
#pragma unroll
        for (int nt = 0; nt < 16; nt++) {
            s[nt][0] = __expf(s[nt][0] - mn0);
            s[nt][1] = __expf(s[nt][1] - mn0);
            s[nt][2] = __expf(s[nt][2] - mn1);
            s[nt][3] = __expf(s[nt][3] - mn1);
            sum0 += s[nt][0] + s[nt][1];
            sum1 += s[nt][2] + s[nt][3];
        }
#pragma unroll
        for (int off = 1; off < 4; off <<= 1) {
            sum0 += __shfl_xor_sync(0xffffffffu, sum0, off);
            sum1 += __shfl_xor_sync(0xffffffffu, sum1, off);
        }
        lrun[0] = lrun[0] * a0 + sum0;
        lrun[1] = lrun[1] * a1 + sum1;
        mrun[0] = mn0; mrun[1] = mn1;
#pragma unroll
        for (int ot = 0; ot < 8; ot++) {
            o[ot][0] *= a0; o[ot][1] *= a0;
            o[ot][2] *= a1; o[ot][3] *= a1;
        }
#pragma unroll
        for (int j = 0; j < 8; j++) {
            unsigned pa[4];
            pa[0] = packbf(s[2 * j][0],     s[2 * j][1]);
            pa[1] = packbf(s[2 * j][2],     s[2 * j][3]);
            pa[2] = packbf(s[2 * j + 1][0], s[2 * j + 1][1]);
            pa[3] = packbf(s[2 * j + 1][2], s[2 * j + 1][3]);
#pragma unroll
            for (int nb = 0; nb < 4; nb++) {
                unsigned r4[4];
                ldm_x4_t(r4, &Vs[j * 16 + (tl & 1) * 8 + rr][nb * 16 + (tl >> 1) * 8]);
                mmabf(o[nb * 2 + 0], pa, r4);
                mmabf(o[nb * 2 + 1], pa, r4 + 2);
            }
        }
        __syncthreads();   // all warps done with buffer bu before ch+1 prefetches into it
    }
    float inv0 = 1.0f / lrun[0], inv1 = 1.0f / lrun[1];
#pragma unroll
    for (int ot = 0; ot < 8; ot++) {
        int col = ot * 8 + 2 * t;
        *(bf162*)(Ob + (size_t)rowg * D_MODEL + col) =
            __float22bfloat162_rn(make_float2(o[ot][0] * inv0, o[ot][1] * inv0));
        *(bf162*)(Ob + (size_t)(rowg + 8) * D_MODEL + col) =
            __float22bfloat162_rn(make_float2(o[ot][2] * inv1, o[ot][3] * inv1));
    }
}

// ---------------- final log_softmax (warp per row, 512 cols) ----------------
__global__ void logsoftmax_kernel(const float* __restrict__ X, float* __restrict__ Out) {
    int warp = (blockIdx.x * blockDim.x + threadIdx.x) >> 5;
    int lane = threadIdx.x & 31;
    if (warp >= MT) return;
    const float* r = X + (size_t)warp * VOCAB;
    float v[16], mx = -1e30f;
#pragma unroll
    for (int j = 0; j < 16; j++) { v[j] = r[lane + j * 32]; mx = fmaxf(mx, v[j]); }
#pragma unroll
    for (int o = 16; o > 0; o >>= 1) mx = fmaxf(mx, __shfl_xor_sync(0xffffffffu, mx, o));
    float sum = 0.f;
#pragma unroll
    for (int j = 0; j < 16; j++) sum += expf(v[j] - mx);
#pragma unroll
    for (int o = 16; o > 0; o >>= 1) sum += __shfl_xor_sync(0xffffffffu, sum, o);
    float lse = mx + logf(sum);
    float* out = Out + (size_t)warp * VOCAB;
#pragma unroll
    for (int j = 0; j < 16; j++) out[lane + j * 32] = v[j] - lse;
}

// ---------------- host driver ----------------
template <typename T>
static T* symp(const void* s) {
    void* p = nullptr;
    cudaGetSymbolAddress(&p, s);
    return (T*)p;
}

extern "C" void kernel_launch(void* const* d_in, const int* in_sizes, int n_in,
                              void* d_out, int out_size) {
    const int*   ids    = (const int*)d_in[0];
    const int*   attm   = (const int*)d_in[1];
    const float* src    = (const float*)d_in[2];
    const int*   srcm   = (const int*)d_in[3];
    const float* emb    = (const float*)d_in[4];
    const float* sa_W   = (const float*)d_in[5];
    const float* sa_b   = (const float*)d_in[6];
    const float* ca_W   = (const float*)d_in[7];
    const float* ca_b   = (const float*)d_in[8];
    const float* ln_a   = (const float*)d_in[9];
    const float* ln_b   = (const float*)d_in[10];
    const float* ffn_w1 = (const float*)d_in[11];
    const float* ffn_b1 = (const float*)d_in[12];
    const float* ffn_w2 = (const float*)d_in[13];
    const float* ffn_b2 = (const float*)d_in[14];
    const float* fin_a  = (const float*)d_in[15];
    const float* fin_b  = (const float*)d_in[16];
    const float* lm_W   = (const float*)d_in[17];
    const float* lm_b   = (const float*)d_in[18];
    float* out = (float*)d_out;

    float* x    = symp<float>(g_x);
    float* lg   = symp<float>(g_lg);
    bf16* hb    = symp<bf16>(g_hb);
    bf16* qb    = symp<bf16>(g_qb);
    bf16* qkv   = symp<bf16>(g_qkv);
    bf16* kv    = symp<bf16>(g_kv);
    bf16* ab    = symp<bf16>(g_ab);
    bf16* fb    = symp<bf16>(g_fb);
    bf16* wsa   = symp<bf16>(g_wsa);
    bf16* wca   = symp<bf16>(g_wca);
    bf16* wqkv  = symp<bf16>(g_wqkv);
    bf16* wkv   = symp<bf16>(g_wkv);
    float* bqkv = symp<float>(g_bqkv);
    float* bkv  = symp<float>(g_bkv);
    bf16* w1    = symp<bf16>(g_w1);
    bf16* w2    = symp<bf16>(g_w2);
    bf16* wlm   = symp<bf16>(g_wlm);
    bf16* srcb  = symp<bf16>(g_srcb);

    static bool attrSet = false;
    if (!attrSet) {
        cudaFuncSetAttribute(flash_kernel<1>, cudaFuncAttributeMaxDynamicSharedMemorySize, FLASH_SMEM);
        cudaFuncSetAttribute(flash_kernel<0>, cudaFuncAttributeMaxDynamicSharedMemorySize, FLASH_SMEM);
        cudaFuncSetAttribute(gemm_bf, cudaFuncAttributeMaxDynamicSharedMemorySize, GEMM_SMEM);
        attrSet = true;
    }

    // ---- one-time-per-launch conversions / repacks ----
    {
        int nF = NLAYER * D_MODEL * D_FF;
        int nM = NLAYER * D_MODEL * D_MODEL;
        conv_mat<<<(nM + 1023) / 1024, 256>>>(sa_W, wsa, 3);
        conv_mat<<<(nM + 1023) / 1024, 256>>>(ca_W, wca, 0);
        conv_mat<<<(nM + 1023) / 1024, 256>>>(ca_W, wca, 3);
        f2bf_kernel<<<(nF + 1023) / 1024, 256>>>(ffn_w1, w1, nF);
        f2bf_kernel<<<(nF + 1023) / 1024, 256>>>(ffn_w2, w2, nF);
        f2bf_kernel<<<(D_MODEL * VOCAB + 1023) / 1024, 256>>>(lm_W, wlm, D_MODEL * VOCAB);
        f2bf_kernel<<<(MS * D_MODEL + 1023) / 1024, 256>>>(src, srcb, MS * D_MODEL);
        int tq = NLAYER * D_MODEL * 3 * D_MODEL;
        int tk = NLAYER * D_MODEL * 2 * D_MODEL;
        pack_w<<<(tq + 1023) / 1024, 256>>>(sa_W, wqkv, 3, 0, tq);
        pack_w<<<(tk + 1023) / 1024, 256>>>(ca_W, wkv, 2, 1, tk);
        pack_b<<<(NLAYER * 3 * D_MODEL + 255) / 256, 256>>>(sa_b, bqkv, 3, 0, NLAYER * 3 * D_MODEL);
        pack_b<<<(NLAYER * 2 * D_MODEL + 255) / 256, 256>>>(ca_b, bkv, 2, 1, NLAYER * 2 * D_MODEL);
    }

    pe_kernel<<<(LT * D_MODEL + 255) / 256, 256>>>();
    embed_kernel<<<(MT * D_MODEL + 255) / 256, 256>>>(ids, emb);

    dim3 gProjT(D_MODEL / 128, MT / 128);     // (4, 64)
    dim3 gQKV(3 * D_MODEL / 128, MT / 128);   // (12, 64)
    dim3 gKV(2 * D_MODEL / 128, MS / 128);    // (8, 32)
    dim3 gFfn1(D_FF / 128, MT / 128);         // (16, 64)
    dim3 gFlash(LT / 128, BATCH * NHEAD);
    const int lnGrid = MT / 8;

    for (int i = 0; i < NLAYER; i++) {
        const bf16*  saW = wsa + (size_t)i * 4 * D_MODEL * D_MODEL;
        const float* sab = sa_b + (size_t)i * 4 * D_MODEL;
        const bf16*  caW = wca + (size_t)i * 4 * D_MODEL * D_MODEL;
        const float* cab = ca_b + (size_t)i * 4 * D_MODEL;
        const float* lnA = ln_a + (size_t)i * 3 * D_MODEL;
        const float* lnB = ln_b + (size_t)i * 3 * D_MODEL;

        // ---- self-attention ----
        ln_kernel<<<lnGrid, 256>>>(x, hb, lnA + 0 * D_MODEL, lnB + 0 * D_MODEL);
        gemm_bf<<<gQKV, 256, GEMM_SMEM>>>(hb, wqkv + (size_t)i * D_MODEL * 3 * D_MODEL,
                               bqkv + (size_t)i * 3 * D_MODEL, nullptr, qkv, nullptr,
                               MT, 3 * D_MODEL, D_MODEL, 0);
        flash_kernel<1><<<gFlash, 256, FLASH_SMEM>>>(
            qkv, 3 * D_MODEL, qkv + D_MODEL, qkv + 2 * D_MODEL, 3 * D_MODEL,
            attm, LFULL, ab, LT, LT);
        gemm_bf<<<gProjT, 256, GEMM_SMEM>>>(ab, saW + 3 * D_MODEL * D_MODEL, sab + 3 * D_MODEL,
                                 x, nullptr, x, MT, D_MODEL, D_MODEL, 0);

        // ---- cross-attention ----
        ln_kernel<<<lnGrid, 256>>>(x, hb, lnA + 1 * D_MODEL, lnB + 1 * D_MODEL);
        gemm_bf<<<gProjT, 256, GEMM_SMEM>>>(hb, caW + 0 * D_MODEL * D_MODEL, cab + 0 * D_MODEL,
                                 nullptr, qb, nullptr, MT, D_MODEL, D_MODEL, 0);
        gemm_bf<<<gKV, 256, GEMM_SMEM>>>(srcb, wkv + (size_t)i * D_MODEL * 2 * D_MODEL,
                              bkv + (size_t)i * 2 * D_MODEL, nullptr, kv, nullptr,
                              MS, 2 * D_MODEL, D_MODEL, 0);
        flash_kernel<0><<<gFlash, 256, FLASH_SMEM>>>(
            qb, D_MODEL, kv, kv + D_MODEL, 2 * D_MODEL,
            srcm, SRC_S, ab, LT, SRC_S);
        gemm_bf<<<gProjT, 256, GEMM_SMEM>>>(ab, caW + 3 * D_MODEL * D_MODEL, cab + 3 * D_MODEL,
                                 x, nullptr, x, MT, D_MODEL, D_MODEL, 0);

        // ---- FFN ----
        ln_kernel<<<lnGrid, 256>>>(x, hb, lnA + 2 * D_MODEL, lnB + 2 * D_MODEL);
        gemm_bf<<<gFfn1, 256, GEMM_SMEM>>>(hb, w1 + (size_t)i * D_MODEL * D_FF,
                                ffn_b1 + (size_t)i * D_FF, nullptr, fb, nullptr,
                                MT, D_FF, D_MODEL, 1);
        gemm_bf<<<gProjT, 256, GEMM_SMEM>>>(fb, w2 + (size_t)i * D_FF * D_MODEL,
                                ffn_b2 + (size_t)i * D_MODEL, x, nullptr, x,
                                MT, D_MODEL, D_FF, 0);
    }

    ln_kernel<<<lnGrid, 256>>>(x, hb, fin_a, fin_b);
    gemm_bf<<<dim3(VOCAB / 128, MT / 128), 256, GEMM_SMEM>>>(hb, wlm, lm_b, nullptr, nullptr, lg,
                                                  MT, VOCAB, D_MODEL, 0);
    logsoftmax_kernel<<<(MT * 32 + 255) / 256, 256>>>(lg, out);
}

// round 12
// speedup vs baseline: 6.9494x; 1.0110x over previous
#include <cuda_runtime.h>
#include <cuda_bf16.h>
#include <math.h>

// ---------------- problem constants ----------------
#define D_MODEL 512
#define D_FF    2048
#define NHEAD   8
#define DK      64
#define NLAYER  4
#define VOCAB   512
#define BATCH   16
#define LFULL   513
#define LT      512
#define SRC_S   256
#define MT      (BATCH*LT)
#define MS      (BATCH*SRC_S)

typedef __nv_bfloat16 bf16;
typedef __nv_bfloat162 bf162;

// ---------------- device scratch (static, no allocation) ----------------
__device__ float g_x  [MT*D_MODEL];                  // residual stream (fp32)
__device__ float g_pe [LT*D_MODEL];
__device__ float g_lg [MT*VOCAB];

__device__ bf16 g_hb [MT*D_MODEL];                   // ln output
__device__ bf16 g_qb [MT*D_MODEL];                   // cross-attn Q
__device__ bf16 g_qkv[MT*3*D_MODEL];                 // fused self QKV
__device__ bf16 g_kv [MS*2*D_MODEL];                 // fused cross KV
__device__ bf16 g_ab [MT*D_MODEL];                   // attention output
__device__ bf16 g_fb [MT*D_FF];                      // ffn intermediate
__device__ bf16 g_wsa[NLAYER*4*D_MODEL*D_MODEL];     // only mat3 used
__device__ bf16 g_wca[NLAYER*4*D_MODEL*D_MODEL];     // only mats 0,3 used
__device__ bf16 g_wqkv[NLAYER*D_MODEL*3*D_MODEL];    // packed self QKV weights
__device__ bf16 g_wkv [NLAYER*D_MODEL*2*D_MODEL];    // packed cross KV weights
__device__ float g_bqkv[NLAYER*3*D_MODEL];
__device__ float g_bkv [NLAYER*2*D_MODEL];
__device__ bf16 g_w1 [NLAYER*D_MODEL*D_FF];
__device__ bf16 g_w2 [NLAYER*D_FF*D_MODEL];
__device__ bf16 g_wlm[D_MODEL*VOCAB];
__device__ bf16 g_srcb[MS*D_MODEL];

// ---------------- PTX helpers ----------------
__device__ __forceinline__ void cpa16(void* s, const void* g) {
    unsigned a = (unsigned)__cvta_generic_to_shared(s);
    asm volatile("cp.async.ca.shared.global [%0], [%1], 16;" :: "r"(a), "l"(g));
}
__device__ __forceinline__ void cp_commit() { asm volatile("cp.async.commit_group;"); }
__device__ __forceinline__ void cp_wait0()  { asm volatile("cp.async.wait_group 0;"); }
__device__ __forceinline__ void cp_wait1()  { asm volatile("cp.async.wait_group 1;"); }
__device__ __forceinline__ void ldm_x4(unsigned* r, const void* p) {
    unsigned a = (unsigned)__cvta_generic_to_shared(p);
    asm volatile("ldmatrix.sync.aligned.m8n8.x4.shared.b16 {%0,%1,%2,%3}, [%4];"
        : "=r"(r[0]), "=r"(r[1]), "=r"(r[2]), "=r"(r[3]) : "r"(a));
}
__device__ __forceinline__ void ldm_x4_t(unsigned* r, const void* p) {
    unsigned a = (unsigned)__cvta_generic_to_shared(p);
    asm volatile("ldmatrix.sync.aligned.m8n8.x4.trans.shared.b16 {%0,%1,%2,%3}, [%4];"
        : "=r"(r[0]), "=r"(r[1]), "=r"(r[2]), "=r"(r[3]) : "r"(a));
}
__device__ __forceinline__ void mmabf(float* c, const unsigned* a, const unsigned* b) {
    asm volatile(
        "mma.sync.aligned.m16n8k16.row.col.f32.bf16.bf16.f32 "
        "{%0,%1,%2,%3}, {%4,%5,%6,%7}, {%8,%9}, {%0,%1,%2,%3};"
        : "+f"(c[0]), "+f"(c[1]), "+f"(c[2]), "+f"(c[3])
        : "r"(a[0]), "r"(a[1]), "r"(a[2]), "r"(a[3]), "r"(b[0]), "r"(b[1]));
}
__device__ __forceinline__ unsigned packbf(float x, float y) {
    bf162 v = __float22bfloat162_rn(make_float2(x, y));
    return *(unsigned*)&v;
}

// ---------------- vectorized conversions / repacks ----------------
// generic fp32 -> bf16, 4 elts/thread (float4 load, uint2 store)
__global__ void f2bf4_kernel(const float4* __restrict__ s, uint2* __restrict__ d, int n4) {
    int i = blockIdx.x * blockDim.x + threadIdx.x;
    int stride = gridDim.x * blockDim.x;
    for (; i < n4; i += stride) {
        float4 v = s[i];
        uint2 o; o.x = packbf(v.x, v.y); o.y = packbf(v.z, v.w);
        d[i] = o;
    }
}
// convert the 3 used mats of [L][4][512][512] tensors in one kernel:
// seg 0: sa mat3 -> wsa ; seg 1: ca mat0 -> wca ; seg 2: ca mat3 -> wca
__global__ void conv3_kernel(const float4* __restrict__ sa, const float4* __restrict__ ca,
                             uint2* __restrict__ wsa, uint2* __restrict__ wca) {
    const int per4 = NLAYER * D_MODEL * D_MODEL / 4;       // float4 per matrix set
    const int mm4  = D_MODEL * D_MODEL / 4;                // float4 per single matrix
    int i = blockIdx.x * blockDim.x + threadIdx.x;
    int stride = gridDim.x * blockDim.x;
    for (; i < 3 * per4; i += stride) {
        int seg = i / per4, r = i % per4;
        int l = r / mm4, q = r % mm4;
        int mat = (seg == 1) ? 0 : 3;
        const float4* src = (seg == 0) ? sa : ca;
        uint2* dst = (seg == 0) ? wsa : wca;
        size_t off = ((size_t)l * 4 + mat) * mm4 + q;
        float4 v = src[off];
        uint2 o; o.x = packbf(v.x, v.y); o.y = packbf(v.z, v.w);
        dst[off] = o;
    }
}
// [L][4][512][512] -> [L][512][nmat*512], vectorized by 4 along c
__global__ void pack_w4(const float* __restrict__ W, uint2* __restrict__ out,
                        int nmat, int mat0, int total4) {
    int i = blockIdx.x * blockDim.x + threadIdx.x;
    int stride = gridDim.x * blockDim.x;
    int perL4 = D_MODEL * nmat * D_MODEL / 4;
    for (; i < total4; i += stride) {
        int l = i / perL4, rem = i % perL4;
        int k = rem / (nmat * 128), j4 = rem % (nmat * 128);
        int j = j4 * 4;
        int m = mat0 + (j >> 9), c = j & 511;
        float4 v = *(const float4*)&W[(((size_t)l * 4 + m) * D_MODEL + k) * D_MODEL + c];
        uint2 o; o.x = packbf(v.x, v.y); o.y = packbf(v.z, v.w);
        out[i] = o;
    }
}
__global__ void pack_b(const float* __restrict__ B, float* __restrict__ out,
                       int nmat, int mat0, int total) {
    int i = blockIdx.x * blockDim.x + threadIdx.x;
    if (i >= total) return;
    int perL = nmat * D_MODEL;
    int l = i / perL, j = i % perL;
    int m = mat0 + (j >> 9), c = j & 511;
    out[i] = B[((size_t)l * 4 + m) * D_MODEL + c];
}

// ---------------- positional encoding (fp64 to match numpy) ----------------
__global__ void pe_kernel() {
    int i = blockIdx.x * blockDim.x + threadIdx.x;
    if (i >= LT * D_MODEL) return;
    int t = i / D_MODEL, d = i % D_MODEL;
    int e = d & ~1;
    double div = exp(-(double)e * (log(10000.0) / (double)D_MODEL));
    double ang = (double)t * div;
    g_pe[i] = (float)((d & 1) ? cos(ang) : sin(ang));
}

// ---------------- embedding + PE ----------------
__global__ void embed_kernel(const int* __restrict__ ids, const float* __restrict__ emb) {
    int i = blockIdx.x * blockDim.x + threadIdx.x;
    if (i >= MT * D_MODEL) return;
    int row = i / D_MODEL, d = i % D_MODEL;
    int b = row / LT, t = row % LT;
    int tok = ids[b * LFULL + t];
    g_x[i] = emb[tok * D_MODEL + d] * 22.62741699796952f + g_pe[t * D_MODEL + d];
}

// ---------------- layernorm: warp per row (ddof=1, denom = std + eps) ----------------
__global__ void ln_kernel(const float* __restrict__ x, bf16* __restrict__ y,
                          const float* __restrict__ ga, const float* __restrict__ gb) {
    int w = threadIdx.x >> 5, lane = threadIdx.x & 31;
    int row = blockIdx.x * 8 + w;
    const float4* xr = (const float4*)(x + (size_t)row * D_MODEL);
    const float4* gav = (const float4*)ga;
    const float4* gbv = (const float4*)gb;
    bf16* yr = y + (size_t)row * D_MODEL;
    float4 v[4];
    float s = 0.f, s2 = 0.f;
#pragma unroll
    for (int j = 0; j < 4; j++) {
        v[j] = xr[lane + j * 32];
        s  += v[j].x + v[j].y + v[j].z + v[j].w;
        s2 += v[j].x * v[j].x + v[j].y * v[j].y + v[j].z * v[j].z + v[j].w * v[j].w;
    }
#pragma unroll
    for (int o = 16; o > 0; o >>= 1) {
        s  += __shfl_xor_sync(0xffffffffu, s,  o);
        s2 += __shfl_xor_sync(0xffffffffu, s2, o);
    }
    float mean = s / 512.0f;
    float var  = fmaxf(0.f, s2 - 512.0f * mean * mean) / 511.0f;
    float inv  = 1.0f / (sqrtf(var) + 1e-6f);
#pragma unroll
    for (int j = 0; j < 4; j++) {
        int c4 = lane + j * 32;
        float4 a = gav[c4], b = gbv[c4];
        float r0 = a.x * (v[j].x - mean) * inv + b.x;
        float r1 = a.y * (v[j].y - mean) * inv + b.y;
        float r2 = a.z * (v[j].z - mean) * inv + b.z;
        float r3 = a.w * (v[j].w - mean) * inv + b.w;
        *(bf162*)(yr + c4 * 4)     = __float22bfloat162_rn(make_float2(r0, r1));
        *(bf162*)(yr + c4 * 4 + 2) = __float22bfloat162_rn(make_float2(r2, r3));
    }
}

// =====================================================================
// bf16 tensor-core GEMM: C = A(MxK,row) @ W(KxN,row) + bias [+res][relu]
// BM=128 BN=128 BK=32, 3-stage cp.async ring, SINGLE sync per iter,
// 8 warps (2m x 4n), warp tile 64x32, 2 CTAs/SM.
// =====================================================================
#define ASZ 10240   // 128 x 40 bf16
#define BSZ 8704    // 32 x 136 bf16
#define GEMM_SMEM (3*(ASZ+BSZ))

__global__ void __launch_bounds__(256, 2) gemm_bf(
        const bf16* __restrict__ A, const bf16* __restrict__ W,
        const float* __restrict__ bias, const float* __restrict__ res,
        bf16* __restrict__ Cb, float* __restrict__ Cf,
        int M, int N, int K, int relu) {
    extern __shared__ char smg[];
    int row0 = blockIdx.y * 128, col0 = blockIdx.x * 128;
    int tid = threadIdx.x;
    int wid = tid >> 5, lane = tid & 31;
    int g = lane >> 2, t = lane & 3;
    int wm = wid & 1, wn = wid >> 1;           // warp tile origin (wm*64, wn*32)
    int tl = lane >> 3, rr = lane & 7;

    float c[4][4][4];
#pragma unroll
    for (int i = 0; i < 4; i++)
#pragma unroll
        for (int j = 0; j < 4; j++)
#pragma unroll
            for (int r = 0; r < 4; r++) c[i][j][r] = 0.f;

    int nIter = K >> 5;
    auto loadStage = [&](int st, int k0g) {
        bf16 (*As)[40]  = (bf16(*)[40])(smg + st * ASZ);
        bf16 (*Bs)[136] = (bf16(*)[136])(smg + 3 * ASZ + st * BSZ);
#pragma unroll
        for (int i = 0; i < 2; i++) {
            int idx = tid + i * 256;
            int m = idx >> 2, kq = (idx & 3) * 8;
            cpa16(&As[m][kq], A + (size_t)(row0 + m) * K + k0g + kq);
        }
#pragma unroll
        for (int i = 0; i < 2; i++) {
            int idx = tid + i * 256;
            int k = idx >> 4, nq = (idx & 15) * 8;
            cpa16(&Bs[k][nq], W + (size_t)(k0g + k) * N + col0 + nq);
        }
    };
    // prologue: stages 0,1
#pragma unroll
    for (int p = 0; p < 2; p++) {
        if (p < nIter) loadStage(p, p << 5);
        cp_commit();
    }
    for (int it = 0; it < nIter; ++it) {
        int st = it % 3;
        bf16 (*As)[40]  = (bf16(*)[40])(smg + st * ASZ);
        bf16 (*Bs)[136] = (bf16(*)[136])(smg + 3 * ASZ + st * BSZ);
        if (it + 1 < nIter) cp_wait1(); else cp_wait0();
        __syncthreads();
        // prefetch stage it+2 (its buffer was consumed at iter it-1)
        int nx = it + 2;
        if (nx < nIter) loadStage(nx % 3, nx << 5);
        cp_commit();
#pragma unroll
        for (int ks = 0; ks < 2; ks++) {
            int k0 = ks * 16;
            unsigned af[4][4];
#pragma unroll
            for (int mt = 0; mt < 4; mt++)
                ldm_x4(af[mt], &As[wm * 64 + mt * 16 + (lane & 15)][k0 + (lane >> 4) * 8]);
            unsigned bf[4][2];
#pragma unroll
            for (int nb = 0; nb < 2; nb++) {
                unsigned r4[4];
                ldm_x4_t(r4, &Bs[k0 + (tl & 1) * 8 + rr][wn * 32 + nb * 16 + (tl >> 1) * 8]);
                bf[nb * 2 + 0][0] = r4[0]; bf[nb * 2 + 0][1] = r4[1];
                bf[nb * 2 + 1][0] = r4[2]; bf[nb * 2 + 1][1] = r4[3];
            }
#pragma unroll
            for (int mt = 0; mt < 4; mt++)
#pragma unroll
                for (int nt = 0; nt < 4; nt++) mmabf(c[mt][nt], af[mt], bf[nt]);
        }
    }
    // ---- epilogue ----
#pragma unroll
    for (int mt = 0; mt < 4; mt++) {
        int r = row0 + wm * 64 + mt * 16 + g;
#pragma unroll
        for (int nt = 0; nt < 4; nt++) {
            int cc = col0 + wn * 32 + nt * 8 + 2 * t;
            float b0 = bias[cc], b1 = bias[cc + 1];
            float v0 = c[mt][nt][0] + b0, v1 = c[mt][nt][1] + b1;
            float v2 = c[mt][nt][2] + b0, v3 = c[mt][nt][3] + b1;
            if (res) {
                v0 += res[(size_t)r * N + cc];       v1 += res[(size_t)r * N + cc + 1];
                v2 += res[(size_t)(r + 8) * N + cc]; v3 += res[(size_t)(r + 8) * N + cc + 1];
            }
            if (relu) {
                v0 = fmaxf(v0, 0.f); v1 = fmaxf(v1, 0.f);
                v2 = fmaxf(v2, 0.f); v3 = fmaxf(v3, 0.f);
            }
            if (Cf) {
                *(float2*)(Cf + (size_t)r * N + cc)       = make_float2(v0, v1);
                *(float2*)(Cf + (size_t)(r + 8) * N + cc) = make_float2(v2, v3);
            }
            if (Cb) {
                *(bf162*)(Cb + (size_t)r * N + cc)       = __float22bfloat162_rn(make_float2(v0, v1));
                *(bf162*)(Cb + (size_t)(r + 8) * N + cc) = __float22bfloat162_rn(make_float2(v2, v3));
            }
        }
    }
}

// =====================================================================
// Fused flash attention, double-buffered K/V chunks.
// Causal: longest blocks scheduled first (LPT) to shrink the tail wave.
// smem: Q[0,18432) | K0 | V0 | K1 | V1 | mask[2][128]
// =====================================================================
#define KVB 36864
#define FLASH_SMEM (18432 + 2*KVB + 1024)

template <int CAUSAL>
__global__ void __launch_bounds__(256, 1) flash_kernel(
        const bf16* __restrict__ Qp, int qStride,
        const bf16* __restrict__ Kp, const bf16* __restrict__ Vp, int kvStride,
        const int* __restrict__ mask, int maskStride,
        bf16* __restrict__ Op, int Lq, int Lk) {
    extern __shared__ char sm[];
    bf16 (*Qs)[72] = (bf16(*)[72])(sm);
    int* mS = (int*)(sm + 18432 + 2 * KVB);

    int bx = CAUSAL ? (gridDim.x - 1 - blockIdx.x) : blockIdx.x;  // LPT for causal
    int m0 = bx * 128;
    int z = blockIdx.y, b = z / NHEAD, h = z % NHEAD;
    const bf16* Qb = Qp + (size_t)b * Lq * qStride + h * DK;
    const bf16* Kb = Kp + (size_t)b * Lk * kvStride + h * DK;
    const bf16* Vb = Vp + (size_t)b * Lk * kvStride + h * DK;
    bf16* Ob = Op + (size_t)b * Lq * D_MODEL + h * DK;
    const int* mrow = mask + (size_t)b * maskStride;

    int tid = threadIdx.x, w = tid >> 5, lane = tid & 31;
    int g = lane >> 2, t = lane & 3;
    int tl = lane >> 3, rr = lane & 7;
    const float scale = 0.125f;

    auto loadKV = [&](int buf, int n0) {
        bf16 (*Ks)[72] = (bf16(*)[72])(sm + 18432 + buf * KVB);
        bf16 (*Vs)[72] = (bf16(*)[72])(sm + 18432 + buf * KVB + KVB / 2);
#pragma unroll
        for (int i = 0; i < 4; i++) {
            int idx = tid + i * 256;
            int r = idx >> 3, cq = (idx & 7) * 8;
            cpa16(&Ks[r][cq], Kb + (size_t)(n0 + r) * kvStride + cq);
            cpa16(&Vs[r][cq], Vb + (size_t)(n0 + r) * kvStride + cq);
        }
        if (tid < 128) mS[buf * 128 + tid] = mrow[n0 + tid];
    };

    int nChunks = CAUSAL ? (m0 / 128 + 1) : (Lk / 128);

    // prologue: Q (group 0), then KV chunk 0 (group 1)
#pragma unroll
    for (int i = 0; i < 4; i++) {
        int idx = tid + i * 256;
        int r = idx >> 3, cq = (idx & 7) * 8;
        cpa16(&Qs[r][cq], Qb + (size_t)(m0 + r) * qStride + cq);
    }
    cp_commit();
    loadKV(0, 0);
    cp_commit();
    cp_wait1();       // Q done
    __syncthreads();

    unsigned qf[4][4];
#pragma unroll
    for (int ks = 0; ks < 4; ks++)
        ldm_x4(qf[ks], &Qs[w * 16 + (lane & 15)][ks * 16 + (lane >> 4) * 8]);

    float o[8][4];
#pragma unroll
    for (int i = 0; i < 8; i++)
#pragma unroll
        for (int j = 0; j < 4; j++) o[i][j] = 0.f;
    float mrun[2] = {-1e30f, -1e30f}, lrun[2] = {0.f, 0.f};
    int rowg = m0 + w * 16 + g;

    for (int ch = 0; ch < nChunks; ch++) {
        int n0 = ch * 128;
        int bu = ch & 1;
        bf16 (*Ks)[72] = (bf16(*)[72])(sm + 18432 + bu * KVB);
        bf16 (*Vs)[72] = (bf16(*)[72])(sm + 18432 + bu * KVB + KVB / 2);
        const int* mSb = mS + bu * 128;
        // prefetch next chunk into the other buffer (freed at end of ch-1)
        if (ch + 1 < nChunks) { loadKV(bu ^ 1, n0 + 128); cp_commit(); cp_wait1(); }
        else                  { cp_commit(); cp_wait0(); }
        __syncthreads();   // chunk ch visible to all warps

        float s[16][4];
#pragma unroll
        for (int nt = 0; nt < 16; nt++)
#pragma unroll
            for (int j = 0; j < 4; j++) s[nt][j] = 0.f;
#pragma unroll
        for (int ks = 0; ks < 4; ks++) {
            int k0 = ks * 16;
#pragma unroll
            for (int nt = 0; nt < 16; nt++) {
                unsigned bfr[2];
                int nc = nt * 8 + g;
                bfr[0] = *(const unsigned*)&Ks[nc][k0 + 2 * t];
                bfr[1] = *(const unsigned*)&Ks[nc][k0 + 8 + 2 * t];
                mmabf(s[nt], qf[ks], bfr);
            }
        }
#pragma unroll
        for (int nt = 0; nt < 16; nt++) {
            int cl = nt * 8 + 2 * t;
            int c0 = n0 + cl, c1 = c0 + 1;
            bool k0ok = mSb[cl] != 0, k1ok = mSb[cl + 1] != 0;
            bool v0 = k0ok && (!CAUSAL || c0 <= rowg);
            bool v1 = k1ok && (!CAUSAL || c1 <= rowg);
            bool v2 = k0ok && (!CAUSAL || c0 <= rowg + 8);
            bool v3 = k1ok && (!CAUSAL || c1 <= rowg + 8);
            s[nt][0] = v0 ? s[nt][0] * scale : -10000.0f;
            s[nt][1] = v1 ? s[nt][1] * scale : -10000.0f;
            s[nt][2] = v2 ? s[nt][2] * scale : -10000.0f;
            s[nt][3] = v3 ? s[nt][3] * scale : -10000.0f;
        }
        float mg0 = -1e30f, mg1 = -1e30f;
#pragma unroll
        for (int nt = 0; nt < 16; nt++) {
            mg0 = fmaxf(mg0, fmaxf(s[nt][0], s[nt][1]));
            mg1 = fmaxf(mg1, fmaxf(s[nt][2], s[nt][3]));
        }
#pragma unroll
        for (int off = 1; off < 4; off <<= 1) {
            mg0 = fmaxf(mg0, __shfl_xor_sync(0xffffffffu, mg0, off));
            mg1 = fmaxf(mg1, __shfl_xor_sync(0xffffffffu, mg1, off));
        }
        float mn0 = fmaxf(mrun[0], mg0), mn1 = fmaxf(mrun[1], mg1);
        float a0 = __expf(mrun[0] - mn0), a1 = __expf(mrun[1] - mn1);
        float sum0 = 0.f, sum1 = 0.f;
#pragma unroll
        for (int nt = 0; nt < 16; nt++) {
            s[nt][0] = __expf(s[nt][0] - mn0);
            s[nt][1] = __expf(s[nt][1] - mn0);
            s[nt][2] = __expf(s[nt][2] - mn1);
            s[nt][3] = __expf(s[nt][3] - mn1);
            sum0 += s[nt][0] + s[nt][1];
            sum1 += s[nt][2] + s[nt][3];
        }
#pragma unroll
        for (int off = 1; off < 4; off <<= 1) {
            sum0 += __shfl_xor_sync(0xffffffffu, sum0, off);
            sum1 += __shfl_xor_sync(0xffffffffu, sum1, off);
        }
        lrun[0] = lrun[0] * a0 + sum0;
        lrun[1] = lrun[1] * a1 + sum1;
        mrun[0] = mn0; mrun[1] = mn1;
#pragma unroll
        for (int ot = 0; ot < 8; ot++) {
            o[ot][0] *= a0; o[ot][1] *= a0;
            o[ot][2] *= a1; o[ot][3] *= a1;
        }
#pragma unroll
        for (int j = 0; j < 8; j++) {
            unsigned pa[4];
            pa[0] = packbf(s[2 * j][0],     s[2 * j][1]);
            pa[1] = packbf(s[2 * j][2],     s[2 * j][3]);
            pa[2] = packbf(s[2 * j + 1][0], s[2 * j + 1][1]);
            pa[3] = packbf(s[2 * j + 1][2], s[2 * j + 1][3]);
#pragma unroll
            for (int nb = 0; nb < 4; nb++) {
                unsigned r4[4];
                ldm_x4_t(r4, &Vs[j * 16 + (tl & 1) * 8 + rr][nb * 16 + (tl >> 1) * 8]);
                mmabf(o[nb * 2 + 0], pa, r4);
                mmabf(o[nb * 2 + 1], pa, r4 + 2);
            }
        }
        __syncthreads();   // all warps done with buffer bu before ch+1 prefetches into it
    }
    float inv0 = 1.0f / lrun[0], inv1 = 1.0f / lrun[1];
#pragma unroll
    for (int ot = 0; ot < 8; ot++) {
        int col = ot * 8 + 2 * t;
        *(bf162*)(Ob + (size_t)rowg * D_MODEL + col) =
            __float22bfloat162_rn(make_float2(o[ot][0] * inv0, o[ot][1] * inv0));
        *(bf162*)(Ob + (size_t)(rowg + 8) * D_MODEL + col) =
            __float22bfloat162_rn(make_float2(o[ot][2] * inv1, o[ot][3] * inv1));
    }
}

// ---------------- final log_softmax (warp per row, 512 cols) ----------------
__global__ void logsoftmax_kernel(const float* __restrict__ X, float* __restrict__ Out) {
    int warp = (blockIdx.x * blockDim.x + threadIdx.x) >> 5;
    int lane = threadIdx.x & 31;
    if (warp >= MT) return;
    const float* r = X + (size_t)warp * VOCAB;
    float v[16], mx = -1e30f;
#pragma unroll
    for (int j = 0; j < 16; j++) { v[j] = r[lane + j * 32]; mx = fmaxf(mx, v[j]); }
#pragma unroll
    for (int o = 16; o > 0; o >>= 1) mx = fmaxf(mx, __shfl_xor_sync(0xffffffffu, mx, o));
    float sum = 0.f;
#pragma unroll
    for (int j = 0; j < 16; j++) sum += expf(v[j] - mx);
#pragma unroll
    for (int o = 16; o > 0; o >>= 1) sum += __shfl_xor_sync(0xffffffffu, sum, o);
    float lse = mx + logf(sum);
    float* out = Out + (size_t)warp * VOCAB;
#pragma unroll
    for (int j = 0; j < 16; j++) out[lane + j * 32] = v[j] - lse;
}

// ---------------- host driver ----------------
template <typename T>
static T* symp(const void* s) {
    void* p = nullptr;
    cudaGetSymbolAddress(&p, s);
    return (T*)p;
}

extern "C" void kernel_launch(void* const* d_in, const int* in_sizes, int n_in,
                              void* d_out, int out_size) {
    const int*   ids    = (const int*)d_in[0];
    const int*   attm   = (const int*)d_in[1];
    const float* src    = (const float*)d_in[2];
    const int*   srcm   = (const int*)d_in[3];
    const float* emb    = (const float*)d_in[4];
    const float* sa_W   = (const float*)d_in[5];
    const float* sa_b   = (const float*)d_in[6];
    const float* ca_W   = (const float*)d_in[7];
    const float* ca_b   = (const float*)d_in[8];
    const float* ln_a   = (const float*)d_in[9];
    const float* ln_b   = (const float*)d_in[10];
    const float* ffn_w1 = (const float*)d_in[11];
    const float* ffn_b1 = (const float*)d_in[12];
    const float* ffn_w2 = (const float*)d_in[13];
    const float* ffn_b2 = (const float*)d_in[14];
    const float* fin_a  = (const float*)d_in[15];
    const float* fin_b  = (const float*)d_in[16];
    const float* lm_W   = (const float*)d_in[17];
    const float* lm_b   = (const float*)d_in[18];
    float* out = (float*)d_out;

    float* x    = symp<float>(g_x);
    float* lg   = symp<float>(g_lg);
    bf16* hb    = symp<bf16>(g_hb);
    bf16* qb    = symp<bf16>(g_qb);
    bf16* qkv   = symp<bf16>(g_qkv);
    bf16* kv    = symp<bf16>(g_kv);
    bf16* ab    = symp<bf16>(g_ab);
    bf16* fb    = symp<bf16>(g_fb);
    bf16* wsa   = symp<bf16>(g_wsa);
    bf16* wca   = symp<bf16>(g_wca);
    bf16* wqkv  = symp<bf16>(g_wqkv);
    bf16* wkv   = symp<bf16>(g_wkv);
    float* bqkv = symp<float>(g_bqkv);
    float* bkv  = symp<float>(g_bkv);
    bf16* w1    = symp<bf16>(g_w1);
    bf16* w2    = symp<bf16>(g_w2);
    bf16* wlm   = symp<bf16>(g_wlm);
    bf16* srcb  = symp<bf16>(g_srcb);

    static bool attrSet = false;
    if (!attrSet) {
        cudaFuncSetAttribute(flash_kernel<1>, cudaFuncAttributeMaxDynamicSharedMemorySize, FLASH_SMEM);
        cudaFuncSetAttribute(flash_kernel<0>, cudaFuncAttributeMaxDynamicSharedMemorySize, FLASH_SMEM);
        cudaFuncSetAttribute(gemm_bf, cudaFuncAttributeMaxDynamicSharedMemorySize, GEMM_SMEM);
        attrSet = true;
    }

    // ---- one-time-per-launch conversions / repacks (vectorized) ----
    {
        int nF4 = NLAYER * D_MODEL * D_FF / 4;
        conv3_kernel<<<2048, 256>>>((const float4*)sa_W, (const float4*)ca_W,
                                    (uint2*)wsa, (uint2*)wca);
        f2bf4_kernel<<<(nF4 + 1023) / 1024, 256>>>((const float4*)ffn_w1, (uint2*)w1, nF4);
        f2bf4_kernel<<<(nF4 + 1023) / 1024, 256>>>((const float4*)ffn_w2, (uint2*)w2, nF4);
        f2bf4_kernel<<<(D_MODEL * VOCAB / 4 + 1023) / 1024, 256>>>((const float4*)lm_W, (uint2*)wlm, D_MODEL * VOCAB / 4);
        f2bf4_kernel<<<(MS * D_MODEL / 4 + 1023) / 1024, 256>>>((const float4*)src, (uint2*)srcb, MS * D_MODEL / 4);
        int tq4 = NLAYER * D_MODEL * 3 * D_MODEL / 4;
        int tk4 = NLAYER * D_MODEL * 2 * D_MODEL / 4;
        pack_w4<<<(tq4 + 1023) / 1024, 256>>>(sa_W, (uint2*)wqkv, 3, 0, tq4);
        pack_w4<<<(tk4 + 1023) / 1024, 256>>>(ca_W, (uint2*)wkv, 2, 1, tk4);
        pack_b<<<(NLAYER * 3 * D_MODEL + 255) / 256, 256>>>(sa_b, bqkv, 3, 0, NLAYER * 3 * D_MODEL);
        pack_b<<<(NLAYER * 2 * D_MODEL + 255) / 256, 256>>>(ca_b, bkv, 2, 1, NLAYER * 2 * D_MODEL);
    }

    pe_kernel<<<(LT * D_MODEL + 255) / 256, 256>>>();
    embed_kernel<<<(MT * D_MODEL + 255) / 256, 256>>>(ids, emb);

    dim3 gProjT(D_MODEL / 128, MT / 128);     // (4, 64)
    dim3 gQKV(3 * D_MODEL / 128, MT / 128);   // (12, 64)
    dim3 gKV(2 * D_MODEL / 128, MS / 128);    // (8, 32)
    dim3 gFfn1(D_FF / 128, MT / 128);         // (16, 64)
    dim3 gFlash(LT / 128, BATCH * NHEAD);
    const int lnGrid = MT / 8;

    for (int i = 0; i < NLAYER; i++) {
        const bf16*  saW = wsa + (size_t)i * 4 * D_MODEL * D_MODEL;
        const float* sab = sa_b + (size_t)i * 4 * D_MODEL;
        const bf16*  caW = wca + (size_t)i * 4 * D_MODEL * D_MODEL;
        const float* cab = ca_b + (size_t)i * 4 * D_MODEL;
        const float* lnA = ln_a + (size_t)i * 3 * D_MODEL;
        const float* lnB = ln_b + (size_t)i * 3 * D_MODEL;

        // ---- self-attention ----
        ln_kernel<<<lnGrid, 256>>>(x, hb, lnA + 0 * D_MODEL, lnB + 0 * D_MODEL);
        gemm_bf<<<gQKV, 256, GEMM_SMEM>>>(hb, wqkv + (size_t)i * D_MODEL * 3 * D_MODEL,
                               bqkv + (size_t)i * 3 * D_MODEL, nullptr, qkv, nullptr,
                               MT, 3 * D_MODEL, D_MODEL, 0);
        flash_kernel<1><<<gFlash, 256, FLASH_SMEM>>>(
            qkv, 3 * D_MODEL, qkv + D_MODEL, qkv + 2 * D_MODEL, 3 * D_MODEL,
            attm, LFULL, ab, LT, LT);
        gemm_bf<<<gProjT, 256, GEMM_SMEM>>>(ab, saW + 3 * D_MODEL * D_MODEL, sab + 3 * D_MODEL,
                                 x, nullptr, x, MT, D_MODEL, D_MODEL, 0);

        // ---- cross-attention ----
        ln_kernel<<<lnGrid, 256>>>(x, hb, lnA + 1 * D_MODEL, lnB + 1 * D_MODEL);
        gemm_bf<<<gProjT, 256, GEMM_SMEM>>>(hb, caW + 0 * D_MODEL * D_MODEL, cab + 0 * D_MODEL,
                                 nullptr, qb, nullptr, MT, D_MODEL, D_MODEL, 0);
        gemm_bf<<<gKV, 256, GEMM_SMEM>>>(srcb, wkv + (size_t)i * D_MODEL * 2 * D_MODEL,
                              bkv + (size_t)i * 2 * D_MODEL, nullptr, kv, nullptr,
                              MS, 2 * D_MODEL, D_MODEL, 0);
        flash_kernel<0><<<gFlash, 256, FLASH_SMEM>>>(
            qb, D_MODEL, kv, kv + D_MODEL, 2 * D_MODEL,
            srcm, SRC_S, ab, LT, SRC_S);
        gemm_bf<<<gProjT, 256, GEMM_SMEM>>>(ab, caW + 3 * D_MODEL * D_MODEL, cab + 3 * D_MODEL,
                                 x, nullptr, x, MT, D_MODEL, D_MODEL, 0);

        // ---- FFN ----
        ln_kernel<<<lnGrid, 256>>>(x, hb, lnA + 2 * D_MODEL, lnB + 2 * D_MODEL);
        gemm_bf<<<gFfn1, 256, GEMM_SMEM>>>(hb, w1 + (size_t)i * D_MODEL * D_FF,
                                ffn_b1 + (size_t)i * D_FF, nullptr, fb, nullptr,
                                MT, D_FF, D_MODEL, 1);
        gemm_bf<<<gProjT, 256, GEMM_SMEM>>>(fb, w2 + (size_t)i * D_FF * D_MODEL,
                                ffn_b2 + (size_t)i * D_MODEL, x, nullptr, x,
                                MT, D_MODEL, D_FF, 0);
    }

    ln_kernel<<<lnGrid, 256>>>(x, hb, fin_a, fin_b);
    gemm_bf<<<dim3(VOCAB / 128, MT / 128), 256, GEMM_SMEM>>>(hb, wlm, lm_b, nullptr, nullptr, lg,
                                                  MT, VOCAB, D_MODEL, 0);
    logsoftmax_kernel<<<(MT * 32 + 255) / 256, 256>>>(lg, out);
}

// round 13
// speedup vs baseline: 7.0734x; 1.0178x over previous
#include <cuda_runtime.h>
#include <cuda_bf16.h>
#include <math.h>

// ---------------- problem constants ----------------
#define D_MODEL 512
#define D_FF    2048
#define NHEAD   8
#define DK      64
#define NLAYER  4
#define VOCAB   512
#define BATCH   16
#define LFULL   513
#define LT      512
#define SRC_S   256
#define MT      (BATCH*LT)
#define MS      (BATCH*SRC_S)

typedef __nv_bfloat16 bf16;
typedef __nv_bfloat162 bf162;

// ---------------- device scratch (static, no allocation) ----------------
__device__ float g_x  [MT*D_MODEL];                  // residual stream (fp32)
__device__ float g_pe [LT*D_MODEL];
__device__ float g_lg [MT*VOCAB];

__device__ bf16 g_hb [MT*D_MODEL];                   // ln output
__device__ bf16 g_qb [MT*D_MODEL];                   // cross-attn Q
__device__ bf16 g_qkv[MT*3*D_MODEL];                 // fused self QKV
__device__ bf16 g_kvL[NLAYER][MS*2*D_MODEL];         // per-layer cross KV (stream overlap)
__device__ bf16 g_ab [MT*D_MODEL];                   // attention output
__device__ bf16 g_fb [MT*D_FF];                      // ffn intermediate
__device__ bf16 g_wsa[NLAYER*4*D_MODEL*D_MODEL];     // only mat3 used
__device__ bf16 g_wca[NLAYER*4*D_MODEL*D_MODEL];     // only mats 0,3 used
__device__ bf16 g_wqkv[NLAYER*D_MODEL*3*D_MODEL];    // packed self QKV weights
__device__ bf16 g_wkv [NLAYER*D_MODEL*2*D_MODEL];    // packed cross KV weights
__device__ float g_bqkv[NLAYER*3*D_MODEL];
__device__ float g_bkv [NLAYER*2*D_MODEL];
__device__ bf16 g_w1 [NLAYER*D_MODEL*D_FF];
__device__ bf16 g_w2 [NLAYER*D_FF*D_MODEL];
__device__ bf16 g_wlm[D_MODEL*VOCAB];
__device__ bf16 g_srcb[MS*D_MODEL];

// ---------------- PTX helpers ----------------
__device__ __forceinline__ void cpa16(void* s, const void* g) {
    unsigned a = (unsigned)__cvta_generic_to_shared(s);
    asm volatile("cp.async.ca.shared.global [%0], [%1], 16;" :: "r"(a), "l"(g));
}
__device__ __forceinline__ void cp_commit() { asm volatile("cp.async.commit_group;"); }
__device__ __forceinline__ void cp_wait0()  { asm volatile("cp.async.wait_group 0;"); }
__device__ __forceinline__ void cp_wait1()  { asm volatile("cp.async.wait_group 1;"); }
__device__ __forceinline__ void ldm_x4(unsigned* r, const void* p) {
    unsigned a = (unsigned)__cvta_generic_to_shared(p);
    asm volatile("ldmatrix.sync.aligned.m8n8.x4.shared.b16 {%0,%1,%2,%3}, [%4];"
        : "=r"(r[0]), "=r"(r[1]), "=r"(r[2]), "=r"(r[3]) : "r"(a));
}
__device__ __forceinline__ void ldm_x4_t(unsigned* r, const void* p) {
    unsigned a = (unsigned)__cvta_generic_to_shared(p);
    asm volatile("ldmatrix.sync.aligned.m8n8.x4.trans.shared.b16 {%0,%1,%2,%3}, [%4];"
        : "=r"(r[0]), "=r"(r[1]), "=r"(r[2]), "=r"(r[3]) : "r"(a));
}
__device__ __forceinline__ void mmabf(float* c, const unsigned* a, const unsigned* b) {
    asm volatile(
        "mma.sync.aligned.m16n8k16.row.col.f32.bf16.bf16.f32 "
        "{%0,%1,%2,%3}, {%4,%5,%6,%7}, {%8,%9}, {%0,%1,%2,%3};"
        : "+f"(c[0]), "+f"(c[1]), "+f"(c[2]), "+f"(c[3])
        : "r"(a[0]), "r"(a[1]), "r"(a[2]), "r"(a[3]), "r"(b[0]), "r"(b[1]));
}
__device__ __forceinline__ unsigned packbf(float x, float y) {
    bf162 v = __float22bfloat162_rn(make_float2(x, y));
    return *(unsigned*)&v;
}

// ---------------- vectorized conversions / repacks ----------------
__global__ void f2bf4_kernel(const float4* __restrict__ s, uint2* __restrict__ d, int n4) {
    int i = blockIdx.x * blockDim.x + threadIdx.x;
    int stride = gridDim.x * blockDim.x;
    for (; i < n4; i += stride) {
        float4 v = s[i];
        uint2 o; o.x = packbf(v.x, v.y); o.y = packbf(v.z, v.w);
        d[i] = o;
    }
}
// convert the 3 used mats of [L][4][512][512] tensors in one kernel
__global__ void conv3_kernel(const float4* __restrict__ sa, const float4* __restrict__ ca,
                             uint2* __restrict__ wsa, uint2* __restrict__ wca) {
    const int per4 = NLAYER * D_MODEL * D_MODEL / 4;
    const int mm4  = D_MODEL * D_MODEL / 4;
    int i = blockIdx.x * blockDim.x + threadIdx.x;
    int stride = gridDim.x * blockDim.x;
    for (; i < 3 * per4; i += stride) {
        int seg = i / per4, r = i % per4;
        int l = r / mm4, q = r % mm4;
        int mat = (seg == 1) ? 0 : 3;
        const float4* src = (seg == 0) ? sa : ca;
        uint2* dst = (seg == 0) ? wsa : wca;
        size_t off = ((size_t)l * 4 + mat) * mm4 + q;
        float4 v = src[off];
        uint2 o; o.x = packbf(v.x, v.y); o.y = packbf(v.z, v.w);
        dst[off] = o;
    }
}
// [L][4][512][512] -> [L][512][nmat*512], vectorized by 4 along c
__global__ void pack_w4(const float* __restrict__ W, uint2* __restrict__ out,
                        int nmat, int mat0, int total4) {
    int i = blockIdx.x * blockDim.x + threadIdx.x;
    int stride = gridDim.x * blockDim.x;
    int perL4 = D_MODEL * nmat * D_MODEL / 4;
    for (; i < total4; i += stride) {
        int l = i / perL4, rem = i % perL4;
        int k = rem / (nmat * 128), j4 = rem % (nmat * 128);
        int j = j4 * 4;
        int m = mat0 + (j >> 9), c = j & 511;
        float4 v = *(const float4*)&W[(((size_t)l * 4 + m) * D_MODEL + k) * D_MODEL + c];
        uint2 o; o.x = packbf(v.x, v.y); o.y = packbf(v.z, v.w);
        out[i] = o;
    }
}
// both bias packs in one launch: seg0 = sa(3 mats from 0), seg1 = ca(2 mats from 1)
__global__ void pack_b2(const float* __restrict__ Bsa, const float* __restrict__ Bca,
                        float* __restrict__ oq, float* __restrict__ okv) {
    const int nq = NLAYER * 3 * D_MODEL, nk = NLAYER * 2 * D_MODEL;
    int i = blockIdx.x * blockDim.x + threadIdx.x;
    if (i < nq) {
        int l = i / (3 * D_MODEL), j = i % (3 * D_MODEL);
        int m = j >> 9, c = j & 511;
        oq[i] = Bsa[((size_t)l * 4 + m) * D_MODEL + c];
    } else if (i < nq + nk) {
        int i2 = i - nq;
        int l = i2 / (2 * D_MODEL), j = i2 % (2 * D_MODEL);
        int m = 1 + (j >> 9), c = j & 511;
        okv[i2] = Bca[((size_t)l * 4 + m) * D_MODEL + c];
    }
}

// ---------------- positional encoding (fp64 to match numpy) ----------------
__global__ void pe_kernel() {
    int i = blockIdx.x * blockDim.x + threadIdx.x;
    if (i >= LT * D_MODEL) return;
    int t = i / D_MODEL, d = i % D_MODEL;
    int e = d & ~1;
    double div = exp(-(double)e * (log(10000.0) / (double)D_MODEL));
    double ang = (double)t * div;
    g_pe[i] = (float)((d & 1) ? cos(ang) : sin(ang));
}

// ---------------- embedding + PE ----------------
__global__ void embed_kernel(const int* __restrict__ ids, const float* __restrict__ emb) {
    int i = blockIdx.x * blockDim.x + threadIdx.x;
    if (i >= MT * D_MODEL) return;
    int row = i / D_MODEL, d = i % D_MODEL;
    int b = row / LT, t = row % LT;
    int tok = ids[b * LFULL + t];
    g_x[i] = emb[tok * D_MODEL + d] * 22.62741699796952f + g_pe[t * D_MODEL + d];
}

// ---------------- layernorm: warp per row (ddof=1, denom = std + eps) ----------------
__global__ void ln_kernel(const float* __restrict__ x, bf16* __restrict__ y,
                          const float* __restrict__ ga, const float* __restrict__ gb) {
    int w = threadIdx.x >> 5, lane = threadIdx.x & 31;
    int row = blockIdx.x * 8 + w;
    const float4* xr = (const float4*)(x + (size_t)row * D_MODEL);
    const float4* gav = (const float4*)ga;
    const float4* gbv = (const float4*)gb;
    bf16* yr = y + (size_t)row * D_MODEL;
    float4 v[4];
    float s = 0.f, s2 = 0.f;
#pragma unroll
    for (int j = 0; j < 4; j++) {
        v[j] = xr[lane + j * 32];
        s  += v[j].x + v[j].y + v[j].z + v[j].w;
        s2 += v[j].x * v[j].x + v[j].y * v[j].y + v[j].z * v[j].z + v[j].w * v[j].w;
    }
#pragma unroll
    for (int o = 16; o > 0; o >>= 1) {
        s  += __shfl_xor_sync(0xffffffffu, s,  o);
        s2 += __shfl_xor_sync(0xffffffffu, s2, o);
    }
    float mean = s / 512.0f;
    float var  = fmaxf(0.f, s2 - 512.0f * mean * mean) / 511.0f;
    float inv  = 1.0f / (sqrtf(var) + 1e-6f);
#pragma unroll
    for (int j = 0; j < 4; j++) {
        int c4 = lane + j * 32;
        float4 a = gav[c4], b = gbv[c4];
        float r0 = a.x * (v[j].x - mean) * inv + b.x;
        float r1 = a.y * (v[j].y - mean) * inv + b.y;
        float r2 = a.z * (v[j].z - mean) * inv + b.z;
        float r3 = a.w * (v[j].w - mean) * inv + b.w;
        *(bf162*)(yr + c4 * 4)     = __float22bfloat162_rn(make_float2(r0, r1));
        *(bf162*)(yr + c4 * 4 + 2) = __float22bfloat162_rn(make_float2(r2, r3));
    }
}

// =====================================================================
// bf16 tensor-core GEMM (unchanged from R11): BM=128 BN=128 BK=32,
// 3-stage cp.async ring, single sync/iter, 2 CTAs/SM.
// =====================================================================
#define ASZ 10240   // 128 x 40 bf16
#define BSZ 8704    // 32 x 136 bf16
#define GEMM_SMEM (3*(ASZ+BSZ))

__global__ void __launch_bounds__(256, 2) gemm_bf(
        const bf16* __restrict__ A, const bf16* __restrict__ W,
        const float* __restrict__ bias, const float* __restrict__ res,
        bf16* __restrict__ Cb, float* __restrict__ Cf,
        int M, int N, int K, int relu) {
    extern __shared__ char smg[];
    int row0 = blockIdx.y * 128, col0 = blockIdx.x * 128;
    int tid = threadIdx.x;
    int wid = tid >> 5, lane = tid & 31;
    int g = lane >> 2, t = lane & 3;
    int wm = wid & 1, wn = wid >> 1;
    int tl = lane >> 3, rr = lane & 7;

    float c[4][4][4];
#pragma unroll
    for (int i = 0; i < 4; i++)
#pragma unroll
        for (int j = 0; j < 4; j++)
#pragma unroll
            for (int r = 0; r < 4; r++) c[i][j][r] = 0.f;

    int nIter = K >> 5;
    auto loadStage = [&](int st, int k0g) {
        bf16 (*As)[40]  = (bf16(*)[40])(smg + st * ASZ);
        bf16 (*Bs)[136] = (bf16(*)[136])(smg + 3 * ASZ + st * BSZ);
#pragma unroll
        for (int i = 0; i < 2; i++) {
            int idx = tid + i * 256;
            int m = idx >> 2, kq = (idx & 3) * 8;
            cpa16(&As[m][kq], A + (size_t)(row0 + m) * K + k0g + kq);
        }
#pragma unroll
        for (int i = 0; i < 2; i++) {
            int idx = tid + i * 256;
            int k = idx >> 4, nq = (idx & 15) * 8;
            cpa16(&Bs[k][nq], W + (size_t)(k0g + k) * N + col0 + nq);
        }
    };
#pragma unroll
    for (int p = 0; p < 2; p++) {
        if (p < nIter) loadStage(p, p << 5);
        cp_commit();
    }
    for (int it = 0; it < nIter; ++it) {
        int st = it % 3;
        bf16 (*As)[40]  = (bf16(*)[40])(smg + st * ASZ);
        bf16 (*Bs)[136] = (bf16(*)[136])(smg + 3 * ASZ + st * BSZ);
        if (it + 1 < nIter) cp_wait1(); else cp_wait0();
        __syncthreads();
        int nx = it + 2;
        if (nx < nIter) loadStage(nx % 3, nx << 5);
        cp_commit();
#pragma unroll
        for (int ks = 0; ks < 2; ks++) {
            int k0 = ks * 16;
            unsigned af[4][4];
#pragma unroll
            for (int mt = 0; mt < 4; mt++)
                ldm_x4(af[mt], &As[wm * 64 + mt * 16 + (lane & 15)][k0 + (lane >> 4) * 8]);
            unsigned bf[4][2];
#pragma unroll
            for (int nb = 0; nb < 2; nb++) {
                unsigned r4[4];
                ldm_x4_t(r4, &Bs[k0 + (tl & 1) * 8 + rr][wn * 32 + nb * 16 + (tl >> 1) * 8]);
                bf[nb * 2 + 0][0] = r4[0]; bf[nb * 2 + 0][1] = r4[1];
                bf[nb * 2 + 1][0] = r4[2]; bf[nb * 2 + 1][1] = r4[3];
            }
#pragma unroll
            for (int mt = 0; mt < 4; mt++)
#pragma unroll
                for (int nt = 0; nt < 4; nt++) mmabf(c[mt][nt], af[mt], bf[nt]);
        }
    }
#pragma unroll
    for (int mt = 0; mt < 4; mt++) {
        int r = row0 + wm * 64 + mt * 16 + g;
#pragma unroll
        for (int nt = 0; nt < 4; nt++) {
            int cc = col0 + wn * 32 + nt * 8 + 2 * t;
            float b0 = bias[cc], b1 = bias[cc + 1];
            float v0 = c[mt][nt][0] + b0, v1 = c[mt][nt][1] + b1;
            float v2 = c[mt][nt][2] + b0, v3 = c[mt][nt][3] + b1;
            if (res) {
                v0 += res[(size_t)r * N + cc];       v1 += res[(size_t)r * N + cc + 1];
                v2 += res[(size_t)(r + 8) * N + cc]; v3 += res[(size_t)(r + 8) * N + cc + 1];
            }
            if (relu) {
                v0 = fmaxf(v0, 0.f); v1 = fmaxf(v1, 0.f);
                v2 = fmaxf(v2, 0.f); v3 = fmaxf(v3, 0.f);
            }
            if (Cf) {
                *(float2*)(Cf + (size_t)r * N + cc)       = make_float2(v0, v1);
                *(float2*)(Cf + (size_t)(r + 8) * N + cc) = make_float2(v2, v3);
            }
            if (Cb) {
                *(bf162*)(Cb + (size_t)r * N + cc)       = __float22bfloat162_rn(make_float2(v0, v1));
                *(bf162*)(Cb + (size_t)(r + 8) * N + cc) = __float22bfloat162_rn(make_float2(v2, v3));
            }
        }
    }
}

// =====================================================================
// Fused flash attention (unchanged from R11; LPT for causal)
// =====================================================================
#define KVB 36864
#define FLASH_SMEM (18432 + 2*KVB + 1024)

template <int CAUSAL>
__global__ void __launch_bounds__(256, 1) flash_kernel(
        const bf16* __restrict__ Qp, int qStride,
        const bf16* __restrict__ Kp, const bf16* __restrict__ Vp, int kvStride,
        const int* __restrict__ mask, int maskStride,
        bf16* __restrict__ Op, int Lq, int Lk) {
    extern __shared__ char sm[];
    bf16 (*Qs)[72] = (bf16(*)[72])(sm);
    int* mS = (int*)(sm + 18432 + 2 * KVB);

    int bx = CAUSAL ? (gridDim.x - 1 - blockIdx.x) : blockIdx.x;
    int m0 = bx * 128;
    int z = blockIdx.y, b = z / NHEAD, h = z % NHEAD;
    const bf16* Qb = Qp + (size_t)b * Lq * qStride + h * DK;
    const bf16* Kb = Kp + (size_t)b * Lk * kvStride + h * DK;
    const bf16* Vb = Vp + (size_t)b * Lk * kvStride + h * DK;
    bf16* Ob = Op + (size_t)b * Lq * D_MODEL + h * DK;
    const int* mrow = mask + (size_t)b * maskStride;

    int tid = threadIdx.x, w = tid >> 5, lane = tid & 31;
    int g = lane >> 2, t = lane & 3;
    int tl = lane >> 3, rr = lane & 7;
    const float scale = 0.125f;

    auto loadKV = [&](int buf, int n0) {
        bf16 (*Ks)[72] = (bf16(*)[72])(sm + 18432 + buf * KVB);
        bf16 (*Vs)[72] = (bf16(*)[72])(sm + 18432 + buf * KVB + KVB / 2);
#pragma unroll
        for (int i = 0; i < 4; i++) {
            int idx = tid + i * 256;
            int r = idx >> 3, cq = (idx & 7) * 8;
            cpa16(&Ks[r][cq], Kb + (size_t)(n0 + r) * kvStride + cq);
            cpa16(&Vs[r][cq], Vb + (size_t)(n0 + r) * kvStride + cq);
        }
        if (tid < 128) mS[buf * 128 + tid] = mrow[n0 + tid];
    };

    int nChunks = CAUSAL ? (m0 / 128 + 1) : (Lk / 128);

#pragma unroll
    for (int i = 0; i < 4; i++) {
        int idx = tid + i * 256;
        int r = idx >> 3, cq = (idx & 7) * 8;
        cpa16(&Qs[r][cq], Qb + (size_t)(m0 + r) * qStride + cq);
    }
    cp_commit();
    loadKV(0, 0);
    cp_commit();
    cp_wait1();
    __syncthreads();

    unsigned qf[4][4];
#pragma unroll
    for (int ks = 0; ks < 4; ks++)
        ldm_x4(qf[ks], &Qs[w * 16 + (lane & 15)][ks * 16 + (lane >> 4) * 8]);

    float o[8][4];
#pragma unroll
    for (int i = 0; i < 8; i++)
#pragma unroll
        for (int j = 0; j < 4; j++) o[i][j] = 0.f;
    float mrun[2] = {-1e30f, -1e30f}, lrun[2] = {0.f, 0.f};
    int rowg = m0 + w * 16 + g;

    for (int ch = 0; ch < nChunks; ch++) {
        int n0 = ch * 128;
        int bu = ch & 1;
        bf16 (*Ks)[72] = (bf16(*)[72])(sm + 18432 + bu * KVB);
        bf16 (*Vs)[72] = (bf16(*)[72])(sm + 18432 + bu * KVB + KVB / 2);
        const int* mSb = mS + bu * 128;
        if (ch + 1 < nChunks) { loadKV(bu ^ 1, n0 + 128); cp_commit(); cp_wait1(); }
        else                  { cp_commit(); cp_wait0(); }
        __syncthreads();

        float s[16][4];
#pragma unroll
        for (int nt = 0; nt < 16; nt++)
#pragma unroll
            for (int j = 0; j < 4; j++) s[nt][j] = 0.f;
#pragma unroll
        for (int ks = 0; ks < 4; ks++) {
            int k0 = ks * 16;
#pragma unroll
            for (int nt = 0; nt < 16; nt++) {
                unsigned bfr[2];
                int nc = nt * 8 + g;
                bfr[0] = *(const unsigned*)&Ks[nc][k0 + 2 * t];
                bfr[1] = *(const unsigned*)&Ks[nc][k0 + 8 + 2 * t];
                mmabf(s[nt], qf[ks], bfr);
            }
        }
#pragma unroll
        for (int nt = 0; nt < 16; nt++) {
            int cl = nt * 8 + 2 * t;
            int c0 = n0 + cl, c1 = c0 + 1;
            bool k0ok = mSb[cl] != 0, k1ok = mSb[cl + 1] != 0;
            bool v0 = k0ok && (!CAUSAL || c0 <= rowg);
            bool v1 = k1ok && (!CAUSAL || c1 <= rowg);
            bool v2 = k0ok && (!CAUSAL || c0 <= rowg + 8);
            bool v3 = k1ok && (!CAUSAL || c1 <= rowg + 8);
            s[nt][0] = v0 ? s[nt][0] * scale : -10000.0f;
            s[nt][1] = v1 ? s[nt][1] * scale : -10000.0f;
            s[nt][2] = v2 ? s[nt][2] * scale : -10000.0f;
            s[nt][3] = v3 ? s[nt][3] * scale : -10000.0f;
        }
        float mg0 = -1e30f, mg1 = -1e30f;
#pragma unroll
        for (int nt = 0; nt < 16; nt++) {
            mg0 = fmaxf(mg0, fmaxf(s[nt][0], s[nt][1]));
            mg1 = fmaxf(mg1, fmaxf(s[nt][2], s[nt][3]));
        }
#pragma unroll
        for (int off = 1; off < 4; off <<= 1) {
            mg0 = fmaxf(mg0, __shfl_xor_sync(0xffffffffu, mg0, off));
            mg1 = fmaxf(mg1, __shfl_xor_sync(0xffffffffu, mg1, off));
        }
        float mn0 = fmaxf(mrun[0], mg0), mn1 = fmaxf(mrun[1], mg1);
        float a0 = __expf(mrun[0] - mn0), a1 = __expf(mrun[1] - mn1);
        float sum0 = 0.f, sum1 = 0.f;
#pragma unroll
        for (int nt = 0; nt < 16; nt++) {
            s[nt][0] = __expf(s[nt][0] - mn0);
            s[nt][1] = __expf(s[nt][1] - mn0);
            s[nt][2] = __expf(s[nt][2] - mn1);
            s[nt][3] = __expf(s[nt][3] - mn1);
            sum0 += s[nt][0] + s[nt][1];
            sum1 += s[nt][2] + s[nt][3];
        }
#pragma unroll
        for (int off = 1; off < 4; off <<= 1) {
            sum0 += __shfl_xor_sync(0xffffffffu, sum0, off);
            sum1 += __shfl_xor_sync(0xffffffffu, sum1, off);
        }
        lrun[0] = lrun[0] * a0 + sum0;
        lrun[1] = lrun[1] * a1 + sum1;
        mrun[0] = mn0; mrun[1] = mn1;
#pragma unroll
        for (int ot = 0; ot < 8; ot++) {
            o[ot][0] *= a0; o[ot][1] *= a0;
            o[ot][2] *= a1; o[ot][3] *= a1;
        }
#pragma unroll
        for (int j = 0; j < 8; j++) {
            unsigned pa[4];
            pa[0] = packbf(s[2 * j][0],     s[2 * j][1]);
            pa[1] = packbf(s[2 * j][2],     s[2 * j][3]);
            pa[2] = packbf(s[2 * j + 1][0], s[2 * j + 1][1]);
            pa[3] = packbf(s[2 * j + 1][2], s[2 * j + 1][3]);
#pragma unroll
            for (int nb = 0; nb < 4; nb++) {
                unsigned r4[4];
                ldm_x4_t(r4, &Vs[j * 16 + (tl & 1) * 8 + rr][nb * 16 + (tl >> 1) * 8]);
                mmabf(o[nb * 2 + 0], pa, r4);
                mmabf(o[nb * 2 + 1], pa, r4 + 2);
            }
        }
        __syncthreads();
    }
    float inv0 = 1.0f / lrun[0], inv1 = 1.0f / lrun[1];
#pragma unroll
    for (int ot = 0; ot < 8; ot++) {
        int col = ot * 8 + 2 * t;
        *(bf162*)(Ob + (size_t)rowg * D_MODEL + col) =
            __float22bfloat162_rn(make_float2(o[ot][0] * inv0, o[ot][1] * inv0));
        *(bf162*)(Ob + (size_t)(rowg + 8) * D_MODEL + col) =
            __float22bfloat162_rn(make_float2(o[ot][2] * inv1, o[ot][3] * inv1));
    }
}

// ---------------- final log_softmax (warp per row, 512 cols) ----------------
__global__ void logsoftmax_kernel(const float* __restrict__ X, float* __restrict__ Out) {
    int warp = (blockIdx.x * blockDim.x + threadIdx.x) >> 5;
    int lane = threadIdx.x & 31;
    if (warp >= MT) return;
    const float* r = X + (size_t)warp * VOCAB;
    float v[16], mx = -1e30f;
#pragma unroll
    for (int j = 0; j < 16; j++) { v[j] = r[lane + j * 32]; mx = fmaxf(mx, v[j]); }
#pragma unroll
    for (int o = 16; o > 0; o >>= 1) mx = fmaxf(mx, __shfl_xor_sync(0xffffffffu, mx, o));
    float sum = 0.f;
#pragma unroll
    for (int j = 0; j < 16; j++) sum += expf(v[j] - mx);
#pragma unroll
    for (int o = 16; o > 0; o >>= 1) sum += __shfl_xor_sync(0xffffffffu, sum, o);
    float lse = mx + logf(sum);
    float* out = Out + (size_t)warp * VOCAB;
#pragma unroll
    for (int j = 0; j < 16; j++) out[lane + j * 32] = v[j] - lse;
}

// ---------------- host driver ----------------
template <typename T>
static T* symp(const void* s) {
    void* p = nullptr;
    cudaGetSymbolAddress(&p, s);
    return (T*)p;
}

extern "C" void kernel_launch(void* const* d_in, const int* in_sizes, int n_in,
                              void* d_out, int out_size) {
    const int*   ids    = (const int*)d_in[0];
    const int*   attm   = (const int*)d_in[1];
    const float* src    = (const float*)d_in[2];
    const int*   srcm   = (const int*)d_in[3];
    const float* emb    = (const float*)d_in[4];
    const float* sa_W   = (const float*)d_in[5];
    const float* sa_b   = (const float*)d_in[6];
    const float* ca_W   = (const float*)d_in[7];
    const float* ca_b   = (const float*)d_in[8];
    const float* ln_a   = (const float*)d_in[9];
    const float* ln_b   = (const float*)d_in[10];
    const float* ffn_w1 = (const float*)d_in[11];
    const float* ffn_b1 = (const float*)d_in[12];
    const float* ffn_w2 = (const float*)d_in[13];
    const float* ffn_b2 = (const float*)d_in[14];
    const float* fin_a  = (const float*)d_in[15];
    const float* fin_b  = (const float*)d_in[16];
    const float* lm_W   = (const float*)d_in[17];
    const float* lm_b   = (const float*)d_in[18];
    float* out = (float*)d_out;

    float* x    = symp<float>(g_x);
    float* lg   = symp<float>(g_lg);
    bf16* hb    = symp<bf16>(g_hb);
    bf16* qb    = symp<bf16>(g_qb);
    bf16* qkv   = symp<bf16>(g_qkv);
    bf16* kvL   = symp<bf16>(g_kvL);
    bf16* ab    = symp<bf16>(g_ab);
    bf16* fb    = symp<bf16>(g_fb);
    bf16* wsa   = symp<bf16>(g_wsa);
    bf16* wca   = symp<bf16>(g_wca);
    bf16* wqkv  = symp<bf16>(g_wqkv);
    bf16* wkv   = symp<bf16>(g_wkv);
    float* bqkv = symp<float>(g_bqkv);
    float* bkv  = symp<float>(g_bkv);
    bf16* w1    = symp<bf16>(g_w1);
    bf16* w2    = symp<bf16>(g_w2);
    bf16* wlm   = symp<bf16>(g_wlm);
    bf16* srcb  = symp<bf16>(g_srcb);

    static bool inited = false;
    static cudaStream_t s2;
    static cudaEvent_t evFork, evKv[NLAYER];
    if (!inited) {
        cudaFuncSetAttribute(flash_kernel<1>, cudaFuncAttributeMaxDynamicSharedMemorySize, FLASH_SMEM);
        cudaFuncSetAttribute(flash_kernel<0>, cudaFuncAttributeMaxDynamicSharedMemorySize, FLASH_SMEM);
        cudaFuncSetAttribute(gemm_bf, cudaFuncAttributeMaxDynamicSharedMemorySize, GEMM_SMEM);
        cudaStreamCreateWithFlags(&s2, cudaStreamNonBlocking);
        cudaEventCreateWithFlags(&evFork, cudaEventDisableTiming);
        for (int i = 0; i < NLAYER; i++)
            cudaEventCreateWithFlags(&evKv[i], cudaEventDisableTiming);
        inited = true;
    }

    // ---- one-time-per-launch conversions / repacks ----
    {
        int nF4 = NLAYER * D_MODEL * D_FF / 4;
        conv3_kernel<<<2048, 256>>>((const float4*)sa_W, (const float4*)ca_W,
                                    (uint2*)wsa, (uint2*)wca);
        f2bf4_kernel<<<(nF4 + 1023) / 1024, 256>>>((const float4*)ffn_w1, (uint2*)w1, nF4);
        f2bf4_kernel<<<(nF4 + 1023) / 1024, 256>>>((const float4*)ffn_w2, (uint2*)w2, nF4);
        f2bf4_kernel<<<(D_MODEL * VOCAB / 4 + 1023) / 1024, 256>>>((const float4*)lm_W, (uint2*)wlm, D_MODEL * VOCAB / 4);
        f2bf4_kernel<<<(MS * D_MODEL / 4 + 1023) / 1024, 256>>>((const float4*)src, (uint2*)srcb, MS * D_MODEL / 4);
        int tq4 = NLAYER * D_MODEL * 3 * D_MODEL / 4;
        int tk4 = NLAYER * D_MODEL * 2 * D_MODEL / 4;
        pack_w4<<<(tq4 + 1023) / 1024, 256>>>(sa_W, (uint2*)wqkv, 3, 0, tq4);
        pack_w4<<<(tk4 + 1023) / 1024, 256>>>(ca_W, (uint2*)wkv, 2, 1, tk4);
        pack_b2<<<(NLAYER * 5 * D_MODEL + 255) / 256, 256>>>(sa_b, ca_b, bqkv, bkv);
    }

    // ---- fork: all 4 cross-KV projections on s2 (depend only on prep) ----
    dim3 gKV(2 * D_MODEL / 128, MS / 128);    // (8, 32)
    cudaEventRecord(evFork, 0);
    cudaStreamWaitEvent(s2, evFork, 0);
    for (int i = 0; i < NLAYER; i++) {
        gemm_bf<<<gKV, 256, GEMM_SMEM, s2>>>(srcb, wkv + (size_t)i * D_MODEL * 2 * D_MODEL,
                              bkv + (size_t)i * 2 * D_MODEL, nullptr,
                              kvL + (size_t)i * MS * 2 * D_MODEL, nullptr,
                              MS, 2 * D_MODEL, D_MODEL, 0);
        cudaEventRecord(evKv[i], s2);
    }

    pe_kernel<<<(LT * D_MODEL + 255) / 256, 256>>>();
    embed_kernel<<<(MT * D_MODEL + 255) / 256, 256>>>(ids, emb);

    dim3 gProjT(D_MODEL / 128, MT / 128);     // (4, 64)
    dim3 gQKV(3 * D_MODEL / 128, MT / 128);   // (12, 64)
    dim3 gFfn1(D_FF / 128, MT / 128);         // (16, 64)
    dim3 gFlash(LT / 128, BATCH * NHEAD);
    const int lnGrid = MT / 8;

    for (int i = 0; i < NLAYER; i++) {
        const bf16*  saW = wsa + (size_t)i * 4 * D_MODEL * D_MODEL;
        const float* sab = sa_b + (size_t)i * 4 * D_MODEL;
        const bf16*  caW = wca + (size_t)i * 4 * D_MODEL * D_MODEL;
        const float* cab = ca_b + (size_t)i * 4 * D_MODEL;
        const float* lnA = ln_a + (size_t)i * 3 * D_MODEL;
        const float* lnB = ln_b + (size_t)i * 3 * D_MODEL;
        bf16* kvi = kvL + (size_t)i * MS * 2 * D_MODEL;

        // ---- self-attention ----
        ln_kernel<<<lnGrid, 256>>>(x, hb, lnA + 0 * D_MODEL, lnB + 0 * D_MODEL);
        gemm_bf<<<gQKV, 256, GEMM_SMEM>>>(hb, wqkv + (size_t)i * D_MODEL * 3 * D_MODEL,
                               bqkv + (size_t)i * 3 * D_MODEL, nullptr, qkv, nullptr,
                               MT, 3 * D_MODEL, D_MODEL, 0);
        flash_kernel<1><<<gFlash, 256, FLASH_SMEM>>>(
            qkv, 3 * D_MODEL, qkv + D_MODEL, qkv + 2 * D_MODEL, 3 * D_MODEL,
            attm, LFULL, ab, LT, LT);
        gemm_bf<<<gProjT, 256, GEMM_SMEM>>>(ab, saW + 3 * D_MODEL * D_MODEL, sab + 3 * D_MODEL,
                                 x, nullptr, x, MT, D_MODEL, D_MODEL, 0);

        // ---- cross-attention ----
        ln_kernel<<<lnGrid, 256>>>(x, hb, lnA + 1 * D_MODEL, lnB + 1 * D_MODEL);
        gemm_bf<<<gProjT, 256, GEMM_SMEM>>>(hb, caW + 0 * D_MODEL * D_MODEL, cab + 0 * D_MODEL,
                                 nullptr, qb, nullptr, MT, D_MODEL, D_MODEL, 0);
        cudaStreamWaitEvent(0, evKv[i], 0);
        flash_kernel<0><<<gFlash, 256, FLASH_SMEM>>>(
            qb, D_MODEL, kvi, kvi + D_MODEL, 2 * D_MODEL,
            srcm, SRC_S, ab, LT, SRC_S);
        gemm_bf<<<gProjT, 256, GEMM_SMEM>>>(ab, caW + 3 * D_MODEL * D_MODEL, cab + 3 * D_MODEL,
                                 x, nullptr, x, MT, D_MODEL, D_MODEL, 0);

        // ---- FFN ----
        ln_kernel<<<lnGrid, 256>>>(x, hb, lnA + 2 * D_MODEL, lnB + 2 * D_MODEL);
        gemm_bf<<<gFfn1, 256, GEMM_SMEM>>>(hb, w1 + (size_t)i * D_MODEL * D_FF,
                                ffn_b1 + (size_t)i * D_FF, nullptr, fb, nullptr,
                                MT, D_FF, D_MODEL, 1);
        gemm_bf<<<gProjT, 256, GEMM_SMEM>>>(fb, w2 + (size_t)i * D_FF * D_MODEL,
                                ffn_b2 + (size_t)i * D_MODEL, x, nullptr, x,
                                MT, D_MODEL, D_FF, 0);
    }

    ln_kernel<<<lnGrid, 256>>>(x, hb, fin_a, fin_b);
    gemm_bf<<<dim3(VOCAB / 128, MT / 128), 256, GEMM_SMEM>>>(hb, wlm, lm_b, nullptr, nullptr, lg,
                                                  MT, VOCAB, D_MODEL, 0);
    logsoftmax_kernel<<<(MT * 32 + 255) / 256, 256>>>(lg, out);
}